// round 10
// baseline (speedup 1.0000x reference)
#include <cuda_runtime.h>
#include <cuda_bf16.h>
#include <cuda_fp16.h>
#include <math.h>

#define BSZ   4
#define SEQ   1024
#define DIM   768
#define NH    12
#define HD    64
#define ROWS  (BSZ*SEQ)      // 4096
#define NBH   (BSZ*NH)       // 48
#define NITER 2

typedef unsigned short u16;
typedef unsigned int   u32;

// weight-split offsets (elements)
#define OFF_Q   0
#define OFF_K   196608
#define OFF_V   393216
#define OFF_Q2  589824
#define OFF_K2  884736
#define OFF_V2  1179648
#define OFF_O2  1769472
#define OFF_F   2359296
#define WSP_TOT 2949120

// ---------------- static scratch (no allocations allowed) ----------------
__device__ float g_im [ROWS*DIM];
__device__ float g_sa [ROWS*DIM];
__device__ float g_t1 [ROWS*DIM];
__device__ float g_m2 [ROWS*DIM];
__device__ float g_t2 [ROWS*DIM];
__device__ float g_ff [ROWS*DIM];
// split activations (hi/lo)
__device__ u16 g_imh[ROWS*DIM], g_iml[ROWS*DIM];
__device__ u16 g_qh [ROWS*DIM], g_ql [ROWS*DIM];
__device__ u16 g_kh [ROWS*DIM], g_kl [ROWS*DIM];
__device__ u16 g_vh [ROWS*DIM], g_vl [ROWS*DIM];   // fp16 split
__device__ u16 g_t1h[ROWS*DIM], g_t1l[ROWS*DIM];
__device__ u16 g_t2h[ROWS*DIM], g_t2l[ROWS*DIM];
__device__ u16 g_q2h[ROWS*DIM], g_q2l[ROWS*DIM];
__device__ u16 g_k2h[ROWS*DIM], g_k2l[ROWS*DIM];
__device__ u16 g_v2h[ROWS*DIM], g_v2l[ROWS*DIM];   // fp16 split
__device__ u16 g_avh[ROWS*DIM], g_avl[ROWS*DIM];
__device__ u16 g_ench[ROWS*DIM], g_encl[ROWS*DIM];
__device__ u16 g_Wh[WSP_TOT], g_Wl[WSP_TOT];
__device__ double g_psum [8][DIM];
__device__ double g_psum2[8][DIM];
__device__ float  g_bnsc[DIM];
__device__ float  g_bnsh[DIM];

// ---------------- helpers ----------------
__device__ __forceinline__ void bsplit(float x, u16& h, u16& l)
{
    __nv_bfloat16 bh = __float2bfloat16(x);
    h = __bfloat16_as_ushort(bh);
    l = __bfloat16_as_ushort(__float2bfloat16(x - __bfloat162float(bh)));
}
__device__ __forceinline__ void hsplit(float x, u16& h, u16& l)
{
    __half hh = __float2half_rn(x);
    h = __half_as_ushort(hh);
    l = __half_as_ushort(__float2half_rn(x - __half2float(hh)));
}
__device__ __forceinline__ u32 pk(u16 a, u16 b) { return (u32)a | ((u32)b << 16); }

__device__ __forceinline__ void mma_bf16(float d[4], u32 a0, u32 a1, u32 a2, u32 a3,
                                         u32 b0, u32 b1)
{
    asm volatile(
        "mma.sync.aligned.m16n8k16.row.col.f32.bf16.bf16.f32 "
        "{%0,%1,%2,%3}, {%4,%5,%6,%7}, {%8,%9}, {%0,%1,%2,%3};\n"
        : "+f"(d[0]), "+f"(d[1]), "+f"(d[2]), "+f"(d[3])
        : "r"(a0), "r"(a1), "r"(a2), "r"(a3), "r"(b0), "r"(b1));
}
__device__ __forceinline__ void mma_f16(float d[4], u32 a0, u32 a1, u32 a2, u32 a3,
                                        u32 b0, u32 b1)
{
    asm volatile(
        "mma.sync.aligned.m16n8k16.row.col.f32.f16.f16.f32 "
        "{%0,%1,%2,%3}, {%4,%5,%6,%7}, {%8,%9}, {%0,%1,%2,%3};\n"
        : "+f"(d[0]), "+f"(d[1]), "+f"(d[2]), "+f"(d[3])
        : "r"(a0), "r"(a1), "r"(a2), "r"(a3), "r"(b0), "r"(b1));
}

// fast exp with folded factor c (= k*log2e); computes exp(k*x) for x <= ~0
__device__ __forceinline__ float fexp(float x, float c)
{
    float t = fmaxf(x * c, -120.0f);
    float r = t + 12582912.0f;
    float nf = r - 12582912.0f;
    float f = t - nf;
    float p = 1.3333558146e-3f;
    p = fmaf(p, f, 9.6181291077e-3f);
    p = fmaf(p, f, 5.5504108664e-2f);
    p = fmaf(p, f, 2.4022650695e-1f);
    p = fmaf(p, f, 6.9314718056e-1f);
    p = fmaf(p, f, 1.0f);
    int n = __float_as_int(r) - 0x4B400000;
    return __int_as_float(__float_as_int(p) + (n << 23));
}

// ---------------- one-time splits ----------------
__global__ void wsplit_kernel(const float* __restrict__ W, int n, int off)
{
    int i = blockIdx.x*256 + threadIdx.x;
    if (i >= n) return;
    u16 h, l;
    bsplit(W[i], h, l);
    g_Wh[off + i] = h;
    g_Wl[off + i] = l;
}
__global__ void asplit_kernel(const float* __restrict__ X, int n,
                              u16* __restrict__ H, u16* __restrict__ L)
{
    int i = blockIdx.x*256 + threadIdx.x;
    if (i >= n) return;
    u16 h, l;
    bsplit(X[i], h, l);
    H[i] = h; L[i] = l;
}

// ---------------- embedding + positional encoding (+ split) ----------------
__global__ void embed_pos_kernel(const int* __restrict__ x,
                                 const float* __restrict__ embed,
                                 float* __restrict__ out,
                                 u16* __restrict__ outh, u16* __restrict__ outl)
{
    int idx2 = blockIdx.x * 256 + threadIdx.x;       // handles 2 elems (even d)
    if (idx2 >= ROWS*DIM/2) return;
    int r = idx2 / (DIM/2), d2 = idx2 - r*(DIM/2);
    int d = d2*2;
    int s = r & (SEQ-1);
    int tok = x[r];
    float inv = exp2f((float)d2 * (-13.287712379549449f * 2.0f / (float)DIM));
    float ang = (float)s * inv;
    float e0 = 2.0f * embed[(size_t)tok*DIM + d]     + sinf(ang);
    float e1 = 2.0f * embed[(size_t)tok*DIM + d + 1] + cosf(ang);
    size_t o = (size_t)r*DIM + d;
    *reinterpret_cast<float2*>(&out[o]) = make_float2(e0, e1);
    u16 h0,l0,h1,l1;
    bsplit(e0,h0,l0); bsplit(e1,h1,l1);
    *reinterpret_cast<u32*>(&outh[o]) = pk(h0,h1);
    *reinterpret_cast<u32*>(&outl[o]) = pk(l0,l1);
}

// ---------------- GEMM body: A pre-split, W pre-split ----------------
// out modes: 0 = fp32, 1 = bf16 split, 2 = fp16 split
#define GA_RS 40
#define GB_RS 136
__device__ __forceinline__ void gemm_body_s(
    const u16* __restrict__ Ahg, const u16* __restrict__ Alg, int lda,
    const u16* __restrict__ Wh, const u16* __restrict__ Wl,
    const float* __restrict__ bias,
    float* __restrict__ Cf, u16* __restrict__ Ch, u16* __restrict__ Cl,
    int N, int K, int bm, int bn, int relu, int mode,
    u16* Ah, u16* Al, u16* Bh, u16* Bl)
{
    int tid = threadIdx.x;
    int lane = tid & 31, wid = tid >> 5;
    int wm = wid & 1, wn = wid >> 1;

    float acc[4][4][4];
#pragma unroll
    for (int i=0;i<4;i++)
#pragma unroll
        for (int j=0;j<4;j++)
#pragma unroll
            for (int q=0;q<4;q++) acc[i][j][q]=0.f;

    for (int kb = 0; kb < K; kb += 32) {
        // A tile 128x32 u16 x2: 512 uint4 per array -> 2/thread
#pragma unroll
        for (int it = 0; it < 2; it++) {
            int idx = it*256 + tid;
            int r = idx >> 2, c8 = (idx & 3) * 8;
            *reinterpret_cast<uint4*>(&Ah[r*GA_RS + c8]) =
                *reinterpret_cast<const uint4*>(Ahg + (size_t)r*lda + kb + c8);
            *reinterpret_cast<uint4*>(&Al[r*GA_RS + c8]) =
                *reinterpret_cast<const uint4*>(Alg + (size_t)r*lda + kb + c8);
        }
        // B tile 32x128
#pragma unroll
        for (int it = 0; it < 2; it++) {
            int idx = it*256 + tid;
            int kk = idx >> 4, c8 = (idx & 15) * 8;
            *reinterpret_cast<uint4*>(&Bh[kk*GB_RS + c8]) =
                *reinterpret_cast<const uint4*>(&Wh[(size_t)(kb+kk)*N + bn + c8]);
            *reinterpret_cast<uint4*>(&Bl[kk*GB_RS + c8]) =
                *reinterpret_cast<const uint4*>(&Wl[(size_t)(kb+kk)*N + bn + c8]);
        }
        __syncthreads();
#pragma unroll
        for (int ks = 0; ks < 32; ks += 16) {
            u32 bhf[4][2], blf[4][2];
#pragma unroll
            for (int nf = 0; nf < 4; nf++) {
                int n  = wn*32 + nf*8 + (lane >> 2);
                int k0 = ks + (lane & 3)*2;
                bhf[nf][0] = pk(Bh[k0*GB_RS+n],     Bh[(k0+1)*GB_RS+n]);
                bhf[nf][1] = pk(Bh[(k0+8)*GB_RS+n], Bh[(k0+9)*GB_RS+n]);
                blf[nf][0] = pk(Bl[k0*GB_RS+n],     Bl[(k0+1)*GB_RS+n]);
                blf[nf][1] = pk(Bl[(k0+8)*GB_RS+n], Bl[(k0+9)*GB_RS+n]);
            }
#pragma unroll
            for (int mf = 0; mf < 4; mf++) {
                int r = wm*64 + mf*16 + (lane >> 2);
                int c = ks + (lane & 3)*2;
                u32 ah0 = *reinterpret_cast<u32*>(&Ah[r*GA_RS + c]);
                u32 ah1 = *reinterpret_cast<u32*>(&Ah[(r+8)*GA_RS + c]);
                u32 ah2 = *reinterpret_cast<u32*>(&Ah[r*GA_RS + c + 8]);
                u32 ah3 = *reinterpret_cast<u32*>(&Ah[(r+8)*GA_RS + c + 8]);
                u32 al0 = *reinterpret_cast<u32*>(&Al[r*GA_RS + c]);
                u32 al1 = *reinterpret_cast<u32*>(&Al[(r+8)*GA_RS + c]);
                u32 al2 = *reinterpret_cast<u32*>(&Al[r*GA_RS + c + 8]);
                u32 al3 = *reinterpret_cast<u32*>(&Al[(r+8)*GA_RS + c + 8]);
#pragma unroll
                for (int nf = 0; nf < 4; nf++) {
                    mma_bf16(acc[mf][nf], ah0,ah1,ah2,ah3, bhf[nf][0], bhf[nf][1]);
                    mma_bf16(acc[mf][nf], ah0,ah1,ah2,ah3, blf[nf][0], blf[nf][1]);
                    mma_bf16(acc[mf][nf], al0,al1,al2,al3, bhf[nf][0], bhf[nf][1]);
                }
            }
        }
        __syncthreads();
    }
#pragma unroll
    for (int mf = 0; mf < 4; mf++) {
#pragma unroll
        for (int nf = 0; nf < 4; nf++) {
            int r = bm + wm*64 + mf*16 + (lane >> 2);
            int c = bn + wn*32 + nf*8 + (lane & 3)*2;
            float b0 = bias[c], b1 = bias[c+1];
            float v0 = acc[mf][nf][0] + b0, v1 = acc[mf][nf][1] + b1;
            float v2 = acc[mf][nf][2] + b0, v3 = acc[mf][nf][3] + b1;
            if (relu) { v0=fmaxf(v0,0.f); v1=fmaxf(v1,0.f); v2=fmaxf(v2,0.f); v3=fmaxf(v3,0.f); }
            if (mode == 0) {
                *reinterpret_cast<float2*>(&Cf[(size_t)r*N + c])     = make_float2(v0, v1);
                *reinterpret_cast<float2*>(&Cf[(size_t)(r+8)*N + c]) = make_float2(v2, v3);
            } else {
                u16 h0,l0,h1,l1,h2,l2,h3,l3;
                if (mode == 1) { bsplit(v0,h0,l0); bsplit(v1,h1,l1); bsplit(v2,h2,l2); bsplit(v3,h3,l3); }
                else           { hsplit(v0,h0,l0); hsplit(v1,h1,l1); hsplit(v2,h2,l2); hsplit(v3,h3,l3); }
                *reinterpret_cast<u32*>(&Ch[(size_t)r*N + c])     = pk(h0,h1);
                *reinterpret_cast<u32*>(&Cl[(size_t)r*N + c])     = pk(l0,l1);
                *reinterpret_cast<u32*>(&Ch[(size_t)(r+8)*N + c]) = pk(h2,h3);
                *reinterpret_cast<u32*>(&Cl[(size_t)(r+8)*N + c]) = pk(l2,l3);
            }
        }
    }
}

__global__ __launch_bounds__(256, 2)
void gemm_ts(const u16* __restrict__ Ahg, const u16* __restrict__ Alg,
             int lda, int aoff,
             const u16* __restrict__ Wh, const u16* __restrict__ Wl,
             const float* __restrict__ bias,
             float* __restrict__ Cf, u16* __restrict__ Ch, u16* __restrict__ Cl,
             int N, int K, int relu, int mode)
{
    __shared__ __align__(16) u16 Ah[128*GA_RS], Al[128*GA_RS];
    __shared__ __align__(16) u16 Bh[32*GB_RS],  Bl[32*GB_RS];
    int bm = blockIdx.y*128, bn = blockIdx.x*128;
    gemm_body_s(Ahg + (size_t)bm*lda + aoff, Alg + (size_t)bm*lda + aoff, lda,
                Wh, Wl, bias, Cf, Ch, Cl, N, K, bm, bn, relu, mode, Ah, Al, Bh, Bl);
}

// fused QKV: grid (18, 32); group = x/6 selects q(bf16)/k(bf16)/v(fp16)
__global__ __launch_bounds__(256, 2)
void qkv_gemm_ts(const float* __restrict__ bq, const float* __restrict__ bk,
                 const float* __restrict__ bv)
{
    __shared__ __align__(16) u16 Ah[128*GA_RS], Al[128*GA_RS];
    __shared__ __align__(16) u16 Bh[32*GB_RS],  Bl[32*GB_RS];
    int grp = blockIdx.x / 6;
    int bxl = blockIdx.x - grp*6;
    int bm = blockIdx.y*128, bn = bxl*128;
    const u16* Wh = g_Wh + grp*196608;
    const u16* Wl = g_Wl + grp*196608;
    const float* bias = (grp == 0) ? bq : (grp == 1) ? bk : bv;
    u16* Ch = (grp == 0) ? g_qh : (grp == 1) ? g_kh : g_vh;
    u16* Cl = (grp == 0) ? g_ql : (grp == 1) ? g_kl : g_vl;
    int mode = (grp == 2) ? 2 : 1;
    int aoff = grp*256;
    gemm_body_s(g_imh + (size_t)bm*DIM + aoff, g_iml + (size_t)bm*DIM + aoff, DIM,
                Wh, Wl, bias, nullptr, Ch, Cl, DIM, 256, bm, bn, 1, mode, Ah, Al, Bh, Bl);
}

// ---------------- fused flash attention on pre-split inputs ----------------
// out mode: 0 = fp32, 1 = bf16 split
#define FA_RS 72
#define FA_SMEM ((2*128*FA_RS + 4*64*FA_RS) * 2)   // 73728 bytes
__global__ __launch_bounds__(256, 2)
void fused_attn(const u16* __restrict__ Qhg, const u16* __restrict__ Qlg,
                const u16* __restrict__ Khg, const u16* __restrict__ Klg,
                const u16* __restrict__ Vhg, const u16* __restrict__ Vlg,
                float* __restrict__ Of, u16* __restrict__ Oh, u16* __restrict__ Ol,
                float scale, int mode)
{
    extern __shared__ u16 sm[];
    u16* Qh = sm;
    u16* Ql = Qh + 128*FA_RS;
    u16* Kh = Ql + 128*FA_RS;
    u16* Kl = Kh + 64*FA_RS;
    u16* Vh = Kl + 64*FA_RS;
    u16* Vl = Vh + 64*FA_RS;

    int bh = blockIdx.z;
    int b = bh / NH, h = bh - b*NH;
    int tid = threadIdx.x, lane = tid & 31, w = tid >> 5;
    size_t base = ((size_t)b*SEQ)*DIM + h*HD;
    int q0 = blockIdx.x * 128;
    const float cfac = scale * 1.4426950408889634f;

    // Q tile: 128x64 u16 x2 = 1024 uint4 per array -> 4/thread
#pragma unroll
    for (int it = 0; it < 4; it++) {
        int idx = it*256 + tid;
        int r = idx >> 3, c8 = (idx & 7) * 8;
        *reinterpret_cast<uint4*>(&Qh[r*FA_RS + c8]) =
            *reinterpret_cast<const uint4*>(Qhg + base + (size_t)(q0+r)*DIM + c8);
        *reinterpret_cast<uint4*>(&Ql[r*FA_RS + c8]) =
            *reinterpret_cast<const uint4*>(Qlg + base + (size_t)(q0+r)*DIM + c8);
    }

    float o[8][4];
#pragma unroll
    for (int i=0;i<8;i++)
#pragma unroll
        for (int j=0;j<4;j++) o[i][j]=0.f;
    float m_lo = -1e30f, m_hi = -1e30f, l_lo = 0.f, l_hi = 0.f;

    int rq = w*16 + (lane >> 2);

    for (int t0 = 0; t0 < SEQ; t0 += 64) {
        __syncthreads();
        // K/V tiles 64x64 u16 x4 arrays: 512 uint4 each -> 2/thread each
#pragma unroll
        for (int it = 0; it < 2; it++) {
            int idx = it*256 + tid;
            int r = idx >> 3, c8 = (idx & 7) * 8;
            size_t g = base + (size_t)(t0+r)*DIM + c8;
            *reinterpret_cast<uint4*>(&Kh[r*FA_RS + c8]) = *reinterpret_cast<const uint4*>(Khg + g);
            *reinterpret_cast<uint4*>(&Kl[r*FA_RS + c8]) = *reinterpret_cast<const uint4*>(Klg + g);
            *reinterpret_cast<uint4*>(&Vh[r*FA_RS + c8]) = *reinterpret_cast<const uint4*>(Vhg + g);
            *reinterpret_cast<uint4*>(&Vl[r*FA_RS + c8]) = *reinterpret_cast<const uint4*>(Vlg + g);
        }
        __syncthreads();

        float sacc[8][4];
#pragma unroll
        for (int i=0;i<8;i++)
#pragma unroll
            for (int j=0;j<4;j++) sacc[i][j]=0.f;
#pragma unroll
        for (int ks = 0; ks < 4; ks++) {
            int c = ks*16 + (lane & 3)*2;
            u32 ah0 = *reinterpret_cast<u32*>(&Qh[rq*FA_RS + c]);
            u32 ah1 = *reinterpret_cast<u32*>(&Qh[(rq+8)*FA_RS + c]);
            u32 ah2 = *reinterpret_cast<u32*>(&Qh[rq*FA_RS + c + 8]);
            u32 ah3 = *reinterpret_cast<u32*>(&Qh[(rq+8)*FA_RS + c + 8]);
            u32 al0 = *reinterpret_cast<u32*>(&Ql[rq*FA_RS + c]);
            u32 al1 = *reinterpret_cast<u32*>(&Ql[(rq+8)*FA_RS + c]);
            u32 al2 = *reinterpret_cast<u32*>(&Ql[rq*FA_RS + c + 8]);
            u32 al3 = *reinterpret_cast<u32*>(&Ql[(rq+8)*FA_RS + c + 8]);
#pragma unroll
            for (int nf = 0; nf < 8; nf++) {
                int n = nf*8 + (lane >> 2);
                u32 bh0 = *reinterpret_cast<u32*>(&Kh[n*FA_RS + c]);
                u32 bh1 = *reinterpret_cast<u32*>(&Kh[n*FA_RS + c + 8]);
                u32 bl0 = *reinterpret_cast<u32*>(&Kl[n*FA_RS + c]);
                u32 bl1 = *reinterpret_cast<u32*>(&Kl[n*FA_RS + c + 8]);
                mma_bf16(sacc[nf], ah0,ah1,ah2,ah3, bh0,bh1);
                mma_bf16(sacc[nf], ah0,ah1,ah2,ah3, bl0,bl1);
                mma_bf16(sacc[nf], al0,al1,al2,al3, bh0,bh1);
            }
        }

        // online softmax on raw scores; scale folded into exp factor
        float tm_lo = -1e30f, tm_hi = -1e30f;
#pragma unroll
        for (int nf = 0; nf < 8; nf++) {
            tm_lo = fmaxf(tm_lo, fmaxf(sacc[nf][0], sacc[nf][1]));
            tm_hi = fmaxf(tm_hi, fmaxf(sacc[nf][2], sacc[nf][3]));
        }
        tm_lo = fmaxf(tm_lo, __shfl_xor_sync(0xffffffffu, tm_lo, 1));
        tm_lo = fmaxf(tm_lo, __shfl_xor_sync(0xffffffffu, tm_lo, 2));
        tm_hi = fmaxf(tm_hi, __shfl_xor_sync(0xffffffffu, tm_hi, 1));
        tm_hi = fmaxf(tm_hi, __shfl_xor_sync(0xffffffffu, tm_hi, 2));
        float mn_lo = fmaxf(m_lo, tm_lo), mn_hi = fmaxf(m_hi, tm_hi);
        float f_lo = fexp(m_lo - mn_lo, cfac), f_hi = fexp(m_hi - mn_hi, cfac);
        m_lo = mn_lo; m_hi = mn_hi;

        float ts_lo = 0.f, ts_hi = 0.f;
        u32 plo[8], phi[8];
#pragma unroll
        for (int nf = 0; nf < 8; nf++) {
            float p0 = fexp(sacc[nf][0] - mn_lo, cfac);
            float p1 = fexp(sacc[nf][1] - mn_lo, cfac);
            float p2 = fexp(sacc[nf][2] - mn_hi, cfac);
            float p3 = fexp(sacc[nf][3] - mn_hi, cfac);
            ts_lo += p0 + p1; ts_hi += p2 + p3;
            __half2 hl = __floats2half2_rn(p0, p1);
            __half2 hh = __floats2half2_rn(p2, p3);
            plo[nf] = *reinterpret_cast<u32*>(&hl);
            phi[nf] = *reinterpret_cast<u32*>(&hh);
        }
        ts_lo += __shfl_xor_sync(0xffffffffu, ts_lo, 1);
        ts_lo += __shfl_xor_sync(0xffffffffu, ts_lo, 2);
        ts_hi += __shfl_xor_sync(0xffffffffu, ts_hi, 1);
        ts_hi += __shfl_xor_sync(0xffffffffu, ts_hi, 2);
        l_lo = l_lo * f_lo + ts_lo;
        l_hi = l_hi * f_hi + ts_hi;

#pragma unroll
        for (int ef = 0; ef < 8; ef++) {
            o[ef][0] *= f_lo; o[ef][1] *= f_lo;
            o[ef][2] *= f_hi; o[ef][3] *= f_hi;
        }

#pragma unroll
        for (int ks = 0; ks < 4; ks++) {
            int k0 = ks*16 + (lane & 3)*2;
            u32 a0 = plo[2*ks], a1 = phi[2*ks], a2 = plo[2*ks+1], a3 = phi[2*ks+1];
#pragma unroll
            for (int ef = 0; ef < 8; ef++) {
                int e = ef*8 + (lane >> 2);
                u32 b0h = pk(Vh[k0*FA_RS+e],     Vh[(k0+1)*FA_RS+e]);
                u32 b1h = pk(Vh[(k0+8)*FA_RS+e], Vh[(k0+9)*FA_RS+e]);
                u32 b0l = pk(Vl[k0*FA_RS+e],     Vl[(k0+1)*FA_RS+e]);
                u32 b1l = pk(Vl[(k0+8)*FA_RS+e], Vl[(k0+9)*FA_RS+e]);
                mma_f16(o[ef], a0,a1,a2,a3, b0h,b1h);
                mma_f16(o[ef], a0,a1,a2,a3, b0l,b1l);
            }
        }
    }

    float il_lo = 1.0f / l_lo, il_hi = 1.0f / l_hi;
    size_t row = (size_t)b*SEQ + q0 + rq;
#pragma unroll
    for (int ef = 0; ef < 8; ef++) {
        int col = h*HD + ef*8 + (lane & 3)*2;
        float v0 = o[ef][0]*il_lo, v1 = o[ef][1]*il_lo;
        float v2 = o[ef][2]*il_hi, v3 = o[ef][3]*il_hi;
        if (mode == 0) {
            *reinterpret_cast<float2*>(&Of[row*DIM + col])     = make_float2(v0, v1);
            *reinterpret_cast<float2*>(&Of[(row+8)*DIM + col]) = make_float2(v2, v3);
        } else {
            u16 h0,l0,h1,l1,h2,l2,h3,l3;
            bsplit(v0,h0,l0); bsplit(v1,h1,l1); bsplit(v2,h2,l2); bsplit(v3,h3,l3);
            *reinterpret_cast<u32*>(&Oh[row*DIM + col])     = pk(h0,h1);
            *reinterpret_cast<u32*>(&Ol[row*DIM + col])     = pk(l0,l1);
            *reinterpret_cast<u32*>(&Oh[(row+8)*DIM + col]) = pk(h2,h3);
            *reinterpret_cast<u32*>(&Ol[(row+8)*DIM + col]) = pk(l2,l3);
        }
    }
}

// ---------------- batch norm ----------------
__global__ __launch_bounds__(256)
void bn_stats(const float* __restrict__ X, const float* __restrict__ Y)
{
    int f  = blockIdx.x*32 + threadIdx.x;
    int rb = blockIdx.y*512;
    float s = 0.0f, s2 = 0.0f;
    for (int r = rb + threadIdx.y; r < rb + 512; r += 8) {
        size_t idx = (size_t)r*DIM + f;
        float v = X[idx] + Y[idx];
        s += v; s2 = fmaf(v, v, s2);
    }
    __shared__ double sh[2][8][32];
    sh[0][threadIdx.y][threadIdx.x] = (double)s;
    sh[1][threadIdx.y][threadIdx.x] = (double)s2;
    __syncthreads();
    if (threadIdx.y == 0) {
        double ts = 0.0, ts2 = 0.0;
#pragma unroll
        for (int i = 0; i < 8; i++) { ts += sh[0][i][threadIdx.x]; ts2 += sh[1][i][threadIdx.x]; }
        g_psum [blockIdx.y][f] = ts;
        g_psum2[blockIdx.y][f] = ts2;
    }
}

__global__ void bn_finalize(const float* __restrict__ g, const float* __restrict__ b)
{
    int f = blockIdx.x*256 + threadIdx.x;
    if (f >= DIM) return;
    double s = 0.0, s2 = 0.0;
#pragma unroll
    for (int i = 0; i < 8; i++) { s += g_psum[i][f]; s2 += g_psum2[i][f]; }
    double mu  = s  * (1.0 / ROWS);
    double var = s2 * (1.0 / ROWS) - mu*mu;
    float rstd = (float)(1.0 / sqrt(var + 1e-5));
    float sc = g[f] * rstd;
    g_bnsc[f] = sc;
    g_bnsh[f] = b[f] - (float)mu * sc;
}

// O = (X+Y)*sc + sh, fp32 + bf16-split outputs
__global__ __launch_bounds__(256)
void bn_apply2(const float* __restrict__ X, const float* __restrict__ Y,
               float* __restrict__ O, u16* __restrict__ Oh, u16* __restrict__ Ol)
{
    int idx4 = blockIdx.x*256 + threadIdx.x;
    if (idx4 >= ROWS*DIM/4) return;
    int f = (idx4*4) % DIM;
    float4 x = *reinterpret_cast<const float4*>(&X[(size_t)idx4*4]);
    float4 y = *reinterpret_cast<const float4*>(&Y[(size_t)idx4*4]);
    float4 o;
    o.x = fmaf(x.x + y.x, g_bnsc[f+0], g_bnsh[f+0]);
    o.y = fmaf(x.y + y.y, g_bnsc[f+1], g_bnsh[f+1]);
    o.z = fmaf(x.z + y.z, g_bnsc[f+2], g_bnsh[f+2]);
    o.w = fmaf(x.w + y.w, g_bnsc[f+3], g_bnsh[f+3]);
    *reinterpret_cast<float4*>(&O[(size_t)idx4*4]) = o;
    u16 h0,l0,h1,l1,h2,l2,h3,l3;
    bsplit(o.x,h0,l0); bsplit(o.y,h1,l1); bsplit(o.z,h2,l2); bsplit(o.w,h3,l3);
    uint2 hp = make_uint2(pk(h0,h1), pk(h2,h3));
    uint2 lp = make_uint2(pk(l0,l1), pk(l2,l3));
    *reinterpret_cast<uint2*>(&Oh[(size_t)idx4*4]) = hp;
    *reinterpret_cast<uint2*>(&Ol[(size_t)idx4*4]) = lp;
}

// ---------------- launch ----------------
static float* sym(const void* s)
{
    void* p = nullptr;
    cudaGetSymbolAddress(&p, s);
    return (float*)p;
}

extern "C" void kernel_launch(void* const* d_in, const int* in_sizes, int n_in,
                              void* d_out, int out_size)
{
    const int*   x     = (const int*)  d_in[0];
    const float* encod = (const float*)d_in[1];
    const float* embed = (const float*)d_in[2];
    const float* Wq  = (const float*)d_in[3];  const float* bq  = (const float*)d_in[4];
    const float* Wk  = (const float*)d_in[5];  const float* bk  = (const float*)d_in[6];
    const float* Wv  = (const float*)d_in[7];  const float* bv  = (const float*)d_in[8];
    const float* g1  = (const float*)d_in[9];  const float* b1  = (const float*)d_in[10];
    const float* Wq2 = (const float*)d_in[11]; const float* bq2 = (const float*)d_in[12];
    const float* Wk2 = (const float*)d_in[13]; const float* bk2 = (const float*)d_in[14];
    const float* Wv2 = (const float*)d_in[15]; const float* bv2 = (const float*)d_in[16];
    const float* Wo2 = (const float*)d_in[17]; const float* bo2 = (const float*)d_in[18];
    const float* g2  = (const float*)d_in[19]; const float* b2  = (const float*)d_in[20];
    const float* Wf  = (const float*)d_in[21]; const float* bf  = (const float*)d_in[22];
    float* out = (float*)d_out;

    float *im = sym(g_im), *sa = sym(g_sa), *t1 = sym(g_t1);
    float *m2 = sym(g_m2), *t2 = sym(g_t2), *ff = sym(g_ff);
    u16 *imh = (u16*)sym(g_imh), *iml = (u16*)sym(g_iml);
    u16 *qh = (u16*)sym(g_qh), *ql = (u16*)sym(g_ql);
    u16 *kh = (u16*)sym(g_kh), *kl = (u16*)sym(g_kl);
    u16 *vh = (u16*)sym(g_vh), *vl = (u16*)sym(g_vl);
    u16 *t1h = (u16*)sym(g_t1h), *t1l = (u16*)sym(g_t1l);
    u16 *t2h = (u16*)sym(g_t2h), *t2l = (u16*)sym(g_t2l);
    u16 *q2h = (u16*)sym(g_q2h), *q2l = (u16*)sym(g_q2l);
    u16 *k2h = (u16*)sym(g_k2h), *k2l = (u16*)sym(g_k2l);
    u16 *v2h = (u16*)sym(g_v2h), *v2l = (u16*)sym(g_v2l);
    u16 *avh = (u16*)sym(g_avh), *avl = (u16*)sym(g_avl);
    u16 *ench = (u16*)sym(g_ench), *encl = (u16*)sym(g_encl);
    u16 *wh = (u16*)sym(g_Wh), *wl = (u16*)sym(g_Wl);

    cudaFuncSetAttribute(fused_attn, cudaFuncAttributeMaxDynamicSharedMemorySize, FA_SMEM);

    const float scale1 = 1.0f / sqrtf((float)DIM);
    const float scale2 = 1.0f / sqrtf((float)HD);

    dim3 gemmGrid(DIM/128, ROWS/128);      // (6, 32)
    dim3 qkvGrid(3*DIM/128, ROWS/128);     // (18, 32)
    dim3 faGrid(SEQ/128, 1, NBH);          // (8, 1, 48)
    dim3 bnGrid(DIM/32, 8);
    dim3 bnBlk(32, 8);
    int ew2Blocks = (ROWS*DIM/2 + 255)/256;
    int ew4Blocks = (ROWS*DIM/4 + 255)/256;

    // one-time splits
    wsplit_kernel<<<(196608+255)/256, 256>>>(Wq,  196608, OFF_Q);
    wsplit_kernel<<<(196608+255)/256, 256>>>(Wk,  196608, OFF_K);
    wsplit_kernel<<<(196608+255)/256, 256>>>(Wv,  196608, OFF_V);
    wsplit_kernel<<<(294912+255)/256, 256>>>(Wq2, 294912, OFF_Q2);
    wsplit_kernel<<<(294912+255)/256, 256>>>(Wk2, 294912, OFF_K2);
    wsplit_kernel<<<(589824+255)/256, 256>>>(Wv2, 589824, OFF_V2);
    wsplit_kernel<<<(589824+255)/256, 256>>>(Wo2, 589824, OFF_O2);
    wsplit_kernel<<<(589824+255)/256, 256>>>(Wf,  589824, OFF_F);
    asplit_kernel<<<(ROWS*DIM+255)/256, 256>>>(encod, ROWS*DIM, ench, encl);

    embed_pos_kernel<<<ew2Blocks, 256>>>(x, embed, im, imh, iml);

    // loop-invariant cross-attention projections (split bf16 outputs)
    gemm_ts<<<gemmGrid, 256>>>(ench, encl, DIM, 0,   wh+OFF_Q2, wl+OFF_Q2, bq2,
                               nullptr, q2h, q2l, DIM, DIM/2, 0, 1);
    gemm_ts<<<gemmGrid, 256>>>(ench, encl, DIM, 384, wh+OFF_K2, wl+OFF_K2, bk2,
                               nullptr, k2h, k2l, DIM, DIM/2, 0, 1);

    for (int li = 0; li < NITER; li++) {
        // self attention
        qkv_gemm_ts<<<qkvGrid, 256>>>(bq, bk, bv);
        fused_attn<<<faGrid, 256, FA_SMEM>>>(qh, ql, kh, kl, vh, vl,
                                             sa, nullptr, nullptr, scale1, 0);

        bn_stats<<<bnGrid, bnBlk>>>(im, sa);
        bn_finalize<<<3, 256>>>(g1, b1);
        bn_apply2<<<ew4Blocks, 256>>>(im, sa, t1, t1h, t1l);

        // cross attention
        gemm_ts<<<gemmGrid, 256>>>(t1h, t1l, DIM, 0, wh+OFF_V2, wl+OFF_V2, bv2,
                                   nullptr, v2h, v2l, DIM, DIM, 0, 2);
        fused_attn<<<faGrid, 256, FA_SMEM>>>(q2h, q2l, k2h, k2l, v2h, v2l,
                                             nullptr, avh, avl, scale2, 1);
        gemm_ts<<<gemmGrid, 256>>>(avh, avl, DIM, 0, wh+OFF_O2, wl+OFF_O2, bo2,
                                   m2, nullptr, nullptr, DIM, DIM, 0, 0);

        bn_stats<<<bnGrid, bnBlk>>>(m2, t1);
        bn_finalize<<<3, 256>>>(g2, b2);
        bn_apply2<<<ew4Blocks, 256>>>(m2, t1, t2, t2h, t2l);

        // FFN + bn3
        gemm_ts<<<gemmGrid, 256>>>(t2h, t2l, DIM, 0, wh+OFF_F, wl+OFF_F, bf,
                                   ff, nullptr, nullptr, DIM, DIM, 0, 0);
        bn_stats<<<bnGrid, bnBlk>>>(t2, ff);
        bn_finalize<<<3, 256>>>(g2, b2);
        bn_apply2<<<ew4Blocks, 256>>>(t2, ff, im, imh, iml);
    }

    cudaMemcpyAsync(out, im, (size_t)ROWS*DIM*sizeof(float),
                    cudaMemcpyDeviceToDevice);
}

// round 11
// speedup vs baseline: 1.0056x; 1.0056x over previous
#include <cuda_runtime.h>
#include <cuda_bf16.h>
#include <cuda_fp16.h>
#include <math.h>

#define BSZ   4
#define SEQ   1024
#define DIM   768
#define NH    12
#define HD    64
#define ROWS  (BSZ*SEQ)      // 4096
#define NBH   (BSZ*NH)       // 48
#define NITER 2

typedef unsigned short u16;
typedef unsigned int   u32;

// weight-split offsets (elements); encod appended after weights
#define OFF_Q   0
#define OFF_K   196608
#define OFF_V   393216
#define OFF_Q2  589824
#define OFF_K2  884736
#define OFF_V2  1179648
#define OFF_O2  1769472
#define OFF_F   2359296
#define WSP_TOT 2949120
#define SPLIT_TOT (WSP_TOT + ROWS*DIM)   // + encod

// ---------------- static scratch (no allocations allowed) ----------------
__device__ float g_im [ROWS*DIM];
__device__ float g_sa [ROWS*DIM];
__device__ float g_t1 [ROWS*DIM];
__device__ float g_m2 [ROWS*DIM];
__device__ float g_t2 [ROWS*DIM];
__device__ float g_ff [ROWS*DIM];
__device__ float g_pe [SEQ*DIM];                  // positional encoding table
// split activations (hi/lo)
__device__ u16 g_imh[ROWS*DIM], g_iml[ROWS*DIM];
__device__ u16 g_qh [ROWS*DIM], g_ql [ROWS*DIM];
__device__ u16 g_kh [ROWS*DIM], g_kl [ROWS*DIM];
__device__ u16 g_vh [ROWS*DIM], g_vl [ROWS*DIM];   // fp16 split
__device__ u16 g_t1h[ROWS*DIM], g_t1l[ROWS*DIM];
__device__ u16 g_t2h[ROWS*DIM], g_t2l[ROWS*DIM];
__device__ u16 g_q2h[ROWS*DIM], g_q2l[ROWS*DIM];
__device__ u16 g_k2h[ROWS*DIM], g_k2l[ROWS*DIM];
__device__ u16 g_v2h[ROWS*DIM], g_v2l[ROWS*DIM];   // fp16 split
__device__ u16 g_avh[ROWS*DIM], g_avl[ROWS*DIM];
__device__ u16 g_ench[ROWS*DIM], g_encl[ROWS*DIM];
__device__ u16 g_Wh[WSP_TOT], g_Wl[WSP_TOT];
__device__ double g_psum [8][DIM];
__device__ double g_psum2[8][DIM];
__device__ float  g_bnsc[DIM];
__device__ float  g_bnsh[DIM];

// ---------------- helpers ----------------
__device__ __forceinline__ void bsplit(float x, u16& h, u16& l)
{
    __nv_bfloat16 bh = __float2bfloat16(x);
    h = __bfloat16_as_ushort(bh);
    l = __bfloat16_as_ushort(__float2bfloat16(x - __bfloat162float(bh)));
}
__device__ __forceinline__ void hsplit(float x, u16& h, u16& l)
{
    __half hh = __float2half_rn(x);
    h = __half_as_ushort(hh);
    l = __half_as_ushort(__float2half_rn(x - __half2float(hh)));
}
__device__ __forceinline__ u32 pk(u16 a, u16 b) { return (u32)a | ((u32)b << 16); }

__device__ __forceinline__ void mma_bf16(float d[4], u32 a0, u32 a1, u32 a2, u32 a3,
                                         u32 b0, u32 b1)
{
    asm volatile(
        "mma.sync.aligned.m16n8k16.row.col.f32.bf16.bf16.f32 "
        "{%0,%1,%2,%3}, {%4,%5,%6,%7}, {%8,%9}, {%0,%1,%2,%3};\n"
        : "+f"(d[0]), "+f"(d[1]), "+f"(d[2]), "+f"(d[3])
        : "r"(a0), "r"(a1), "r"(a2), "r"(a3), "r"(b0), "r"(b1));
}
__device__ __forceinline__ void mma_f16(float d[4], u32 a0, u32 a1, u32 a2, u32 a3,
                                        u32 b0, u32 b1)
{
    asm volatile(
        "mma.sync.aligned.m16n8k16.row.col.f32.f16.f16.f32 "
        "{%0,%1,%2,%3}, {%4,%5,%6,%7}, {%8,%9}, {%0,%1,%2,%3};\n"
        : "+f"(d[0]), "+f"(d[1]), "+f"(d[2]), "+f"(d[3])
        : "r"(a0), "r"(a1), "r"(a2), "r"(a3), "r"(b0), "r"(b1));
}

// fast exp with folded factor c (= k*log2e); computes exp(k*x) for x <= ~0
__device__ __forceinline__ float fexp(float x, float c)
{
    float t = fmaxf(x * c, -120.0f);
    float r = t + 12582912.0f;
    float nf = r - 12582912.0f;
    float f = t - nf;
    float p = 1.3333558146e-3f;
    p = fmaf(p, f, 9.6181291077e-3f);
    p = fmaf(p, f, 5.5504108664e-2f);
    p = fmaf(p, f, 2.4022650695e-1f);
    p = fmaf(p, f, 6.9314718056e-1f);
    p = fmaf(p, f, 1.0f);
    int n = __float_as_int(r) - 0x4B400000;
    return __int_as_float(__float_as_int(p) + (n << 23));
}

// ---------------- one-time: PE table (786K precise trig, not 12.6M) ----------------
__global__ void pe_table_kernel()
{
    int idx2 = blockIdx.x*256 + threadIdx.x;
    if (idx2 >= SEQ*DIM/2) return;
    int s = idx2 / (DIM/2), d2 = idx2 - s*(DIM/2);
    float inv = exp2f((float)d2 * (-13.287712379549449f * 2.0f / (float)DIM));
    float ang = (float)s * inv;
    g_pe[(size_t)s*DIM + 2*d2]     = sinf(ang);
    g_pe[(size_t)s*DIM + 2*d2 + 1] = cosf(ang);
}

// ---------------- one-time: ALL splits (8 weights + encod) in one launch ----------------
__global__ void allsplit_kernel(const float* __restrict__ p0, const float* __restrict__ p1,
                                const float* __restrict__ p2, const float* __restrict__ p3,
                                const float* __restrict__ p4, const float* __restrict__ p5,
                                const float* __restrict__ p6, const float* __restrict__ p7,
                                const float* __restrict__ p8)
{
    int i = blockIdx.x*256 + threadIdx.x;
    if (i >= SPLIT_TOT) return;
    const int off1 = OFF_K, off2 = OFF_V, off3 = OFF_Q2, off4 = OFF_K2,
              off5 = OFF_V2, off6 = OFF_O2, off7 = OFF_F, off8 = WSP_TOT;
    const float* p; int j;
    if      (i < off1) { p = p0; j = i; }
    else if (i < off2) { p = p1; j = i - off1; }
    else if (i < off3) { p = p2; j = i - off2; }
    else if (i < off4) { p = p3; j = i - off3; }
    else if (i < off5) { p = p4; j = i - off4; }
    else if (i < off6) { p = p5; j = i - off5; }
    else if (i < off7) { p = p6; j = i - off6; }
    else if (i < off8) { p = p7; j = i - off7; }
    else               { p = p8; j = i - off8; }
    u16 h, l;
    bsplit(p[j], h, l);
    if (i < off8) { g_Wh[i] = h;   g_Wl[i] = l; }
    else          { g_ench[j] = h; g_encl[j] = l; }
}

// ---------------- embedding + PE (memory-bound gather, no trig) ----------------
__global__ void embed_pos_kernel(const int* __restrict__ x,
                                 const float* __restrict__ embed,
                                 float* __restrict__ out,
                                 u16* __restrict__ outh, u16* __restrict__ outl)
{
    int idx4 = blockIdx.x * 256 + threadIdx.x;
    if (idx4 >= ROWS*DIM/4) return;
    int r = idx4 / (DIM/4), d = (idx4 - r*(DIM/4))*4;
    int s = r & (SEQ-1);
    int tok = x[r];
    float4 e = *reinterpret_cast<const float4*>(&embed[(size_t)tok*DIM + d]);
    float4 p = *reinterpret_cast<const float4*>(&g_pe[(size_t)s*DIM + d]);
    float4 o;
    o.x = fmaf(2.0f, e.x, p.x); o.y = fmaf(2.0f, e.y, p.y);
    o.z = fmaf(2.0f, e.z, p.z); o.w = fmaf(2.0f, e.w, p.w);
    size_t q = (size_t)idx4*4;
    *reinterpret_cast<float4*>(&out[q]) = o;
    u16 h0,l0,h1,l1,h2,l2,h3,l3;
    bsplit(o.x,h0,l0); bsplit(o.y,h1,l1); bsplit(o.z,h2,l2); bsplit(o.w,h3,l3);
    *reinterpret_cast<uint2*>(&outh[q]) = make_uint2(pk(h0,h1), pk(h2,h3));
    *reinterpret_cast<uint2*>(&outl[q]) = make_uint2(pk(l0,l1), pk(l2,l3));
}

// ---------------- GEMM body: A pre-split, W pre-split ----------------
// out modes: 0 = fp32, 1 = bf16 split, 2 = fp16 split
#define GA_RS 40
#define GB_RS 136
__device__ __forceinline__ void gemm_body_s(
    const u16* __restrict__ Ahg, const u16* __restrict__ Alg, int lda,
    const u16* __restrict__ Wh, const u16* __restrict__ Wl,
    const float* __restrict__ bias,
    float* __restrict__ Cf, u16* __restrict__ Ch, u16* __restrict__ Cl,
    int N, int K, int bm, int bn, int relu, int mode,
    u16* Ah, u16* Al, u16* Bh, u16* Bl)
{
    int tid = threadIdx.x;
    int lane = tid & 31, wid = tid >> 5;
    int wm = wid & 1, wn = wid >> 1;

    float acc[4][4][4];
#pragma unroll
    for (int i=0;i<4;i++)
#pragma unroll
        for (int j=0;j<4;j++)
#pragma unroll
            for (int q=0;q<4;q++) acc[i][j][q]=0.f;

    for (int kb = 0; kb < K; kb += 32) {
#pragma unroll
        for (int it = 0; it < 2; it++) {
            int idx = it*256 + tid;
            int r = idx >> 2, c8 = (idx & 3) * 8;
            *reinterpret_cast<uint4*>(&Ah[r*GA_RS + c8]) =
                *reinterpret_cast<const uint4*>(Ahg + (size_t)r*lda + kb + c8);
            *reinterpret_cast<uint4*>(&Al[r*GA_RS + c8]) =
                *reinterpret_cast<const uint4*>(Alg + (size_t)r*lda + kb + c8);
        }
#pragma unroll
        for (int it = 0; it < 2; it++) {
            int idx = it*256 + tid;
            int kk = idx >> 4, c8 = (idx & 15) * 8;
            *reinterpret_cast<uint4*>(&Bh[kk*GB_RS + c8]) =
                *reinterpret_cast<const uint4*>(&Wh[(size_t)(kb+kk)*N + bn + c8]);
            *reinterpret_cast<uint4*>(&Bl[kk*GB_RS + c8]) =
                *reinterpret_cast<const uint4*>(&Wl[(size_t)(kb+kk)*N + bn + c8]);
        }
        __syncthreads();
#pragma unroll
        for (int ks = 0; ks < 32; ks += 16) {
            u32 bhf[4][2], blf[4][2];
#pragma unroll
            for (int nf = 0; nf < 4; nf++) {
                int n  = wn*32 + nf*8 + (lane >> 2);
                int k0 = ks + (lane & 3)*2;
                bhf[nf][0] = pk(Bh[k0*GB_RS+n],     Bh[(k0+1)*GB_RS+n]);
                bhf[nf][1] = pk(Bh[(k0+8)*GB_RS+n], Bh[(k0+9)*GB_RS+n]);
                blf[nf][0] = pk(Bl[k0*GB_RS+n],     Bl[(k0+1)*GB_RS+n]);
                blf[nf][1] = pk(Bl[(k0+8)*GB_RS+n], Bl[(k0+9)*GB_RS+n]);
            }
#pragma unroll
            for (int mf = 0; mf < 4; mf++) {
                int r = wm*64 + mf*16 + (lane >> 2);
                int c = ks + (lane & 3)*2;
                u32 ah0 = *reinterpret_cast<u32*>(&Ah[r*GA_RS + c]);
                u32 ah1 = *reinterpret_cast<u32*>(&Ah[(r+8)*GA_RS + c]);
                u32 ah2 = *reinterpret_cast<u32*>(&Ah[r*GA_RS + c + 8]);
                u32 ah3 = *reinterpret_cast<u32*>(&Ah[(r+8)*GA_RS + c + 8]);
                u32 al0 = *reinterpret_cast<u32*>(&Al[r*GA_RS + c]);
                u32 al1 = *reinterpret_cast<u32*>(&Al[(r+8)*GA_RS + c]);
                u32 al2 = *reinterpret_cast<u32*>(&Al[r*GA_RS + c + 8]);
                u32 al3 = *reinterpret_cast<u32*>(&Al[(r+8)*GA_RS + c + 8]);
#pragma unroll
                for (int nf = 0; nf < 4; nf++) {
                    mma_bf16(acc[mf][nf], ah0,ah1,ah2,ah3, bhf[nf][0], bhf[nf][1]);
                    mma_bf16(acc[mf][nf], ah0,ah1,ah2,ah3, blf[nf][0], blf[nf][1]);
                    mma_bf16(acc[mf][nf], al0,al1,al2,al3, bhf[nf][0], bhf[nf][1]);
                }
            }
        }
        __syncthreads();
    }
#pragma unroll
    for (int mf = 0; mf < 4; mf++) {
#pragma unroll
        for (int nf = 0; nf < 4; nf++) {
            int r = bm + wm*64 + mf*16 + (lane >> 2);
            int c = bn + wn*32 + nf*8 + (lane & 3)*2;
            float b0 = bias[c], b1 = bias[c+1];
            float v0 = acc[mf][nf][0] + b0, v1 = acc[mf][nf][1] + b1;
            float v2 = acc[mf][nf][2] + b0, v3 = acc[mf][nf][3] + b1;
            if (relu) { v0=fmaxf(v0,0.f); v1=fmaxf(v1,0.f); v2=fmaxf(v2,0.f); v3=fmaxf(v3,0.f); }
            if (mode == 0) {
                *reinterpret_cast<float2*>(&Cf[(size_t)r*N + c])     = make_float2(v0, v1);
                *reinterpret_cast<float2*>(&Cf[(size_t)(r+8)*N + c]) = make_float2(v2, v3);
            } else {
                u16 h0,l0,h1,l1,h2,l2,h3,l3;
                if (mode == 1) { bsplit(v0,h0,l0); bsplit(v1,h1,l1); bsplit(v2,h2,l2); bsplit(v3,h3,l3); }
                else           { hsplit(v0,h0,l0); hsplit(v1,h1,l1); hsplit(v2,h2,l2); hsplit(v3,h3,l3); }
                *reinterpret_cast<u32*>(&Ch[(size_t)r*N + c])     = pk(h0,h1);
                *reinterpret_cast<u32*>(&Cl[(size_t)r*N + c])     = pk(l0,l1);
                *reinterpret_cast<u32*>(&Ch[(size_t)(r+8)*N + c]) = pk(h2,h3);
                *reinterpret_cast<u32*>(&Cl[(size_t)(r+8)*N + c]) = pk(l2,l3);
            }
        }
    }
}

__global__ __launch_bounds__(256, 2)
void gemm_ts(const u16* __restrict__ Ahg, const u16* __restrict__ Alg,
             int lda, int aoff,
             const u16* __restrict__ Wh, const u16* __restrict__ Wl,
             const float* __restrict__ bias,
             float* __restrict__ Cf, u16* __restrict__ Ch, u16* __restrict__ Cl,
             int N, int K, int relu, int mode)
{
    __shared__ __align__(16) u16 Ah[128*GA_RS], Al[128*GA_RS];
    __shared__ __align__(16) u16 Bh[32*GB_RS],  Bl[32*GB_RS];
    int bm = blockIdx.y*128, bn = blockIdx.x*128;
    gemm_body_s(Ahg + (size_t)bm*lda + aoff, Alg + (size_t)bm*lda + aoff, lda,
                Wh, Wl, bias, Cf, Ch, Cl, N, K, bm, bn, relu, mode, Ah, Al, Bh, Bl);
}

// fused QKV: grid (18, 32); group = x/6 selects q(bf16)/k(bf16)/v(fp16)
__global__ __launch_bounds__(256, 2)
void qkv_gemm_ts(const float* __restrict__ bq, const float* __restrict__ bk,
                 const float* __restrict__ bv)
{
    __shared__ __align__(16) u16 Ah[128*GA_RS], Al[128*GA_RS];
    __shared__ __align__(16) u16 Bh[32*GB_RS],  Bl[32*GB_RS];
    int grp = blockIdx.x / 6;
    int bxl = blockIdx.x - grp*6;
    int bm = blockIdx.y*128, bn = bxl*128;
    const u16* Wh = g_Wh + grp*196608;
    const u16* Wl = g_Wl + grp*196608;
    const float* bias = (grp == 0) ? bq : (grp == 1) ? bk : bv;
    u16* Ch = (grp == 0) ? g_qh : (grp == 1) ? g_kh : g_vh;
    u16* Cl = (grp == 0) ? g_ql : (grp == 1) ? g_kl : g_vl;
    int mode = (grp == 2) ? 2 : 1;
    int aoff = grp*256;
    gemm_body_s(g_imh + (size_t)bm*DIM + aoff, g_iml + (size_t)bm*DIM + aoff, DIM,
                Wh, Wl, bias, nullptr, Ch, Cl, DIM, 256, bm, bn, 1, mode, Ah, Al, Bh, Bl);
}

// ---------------- fused flash attention on pre-split inputs ----------------
// out mode: 0 = fp32, 1 = bf16 split
#define FA_RS 72
#define FA_SMEM ((2*128*FA_RS + 4*64*FA_RS) * 2)   // 73728 bytes
__global__ __launch_bounds__(256, 2)
void fused_attn(const u16* __restrict__ Qhg, const u16* __restrict__ Qlg,
                const u16* __restrict__ Khg, const u16* __restrict__ Klg,
                const u16* __restrict__ Vhg, const u16* __restrict__ Vlg,
                float* __restrict__ Of, u16* __restrict__ Oh, u16* __restrict__ Ol,
                float scale, int mode)
{
    extern __shared__ u16 sm[];
    u16* Qh = sm;
    u16* Ql = Qh + 128*FA_RS;
    u16* Kh = Ql + 128*FA_RS;
    u16* Kl = Kh + 64*FA_RS;
    u16* Vh = Kl + 64*FA_RS;
    u16* Vl = Vh + 64*FA_RS;

    int bh = blockIdx.z;
    int b = bh / NH, h = bh - b*NH;
    int tid = threadIdx.x, lane = tid & 31, w = tid >> 5;
    size_t base = ((size_t)b*SEQ)*DIM + h*HD;
    int q0 = blockIdx.x * 128;
    const float cfac = scale * 1.4426950408889634f;

#pragma unroll
    for (int it = 0; it < 4; it++) {
        int idx = it*256 + tid;
        int r = idx >> 3, c8 = (idx & 7) * 8;
        *reinterpret_cast<uint4*>(&Qh[r*FA_RS + c8]) =
            *reinterpret_cast<const uint4*>(Qhg + base + (size_t)(q0+r)*DIM + c8);
        *reinterpret_cast<uint4*>(&Ql[r*FA_RS + c8]) =
            *reinterpret_cast<const uint4*>(Qlg + base + (size_t)(q0+r)*DIM + c8);
    }

    float o[8][4];
#pragma unroll
    for (int i=0;i<8;i++)
#pragma unroll
        for (int j=0;j<4;j++) o[i][j]=0.f;
    float m_lo = -1e30f, m_hi = -1e30f, l_lo = 0.f, l_hi = 0.f;

    int rq = w*16 + (lane >> 2);

    for (int t0 = 0; t0 < SEQ; t0 += 64) {
        __syncthreads();
#pragma unroll
        for (int it = 0; it < 2; it++) {
            int idx = it*256 + tid;
            int r = idx >> 3, c8 = (idx & 7) * 8;
            size_t g = base + (size_t)(t0+r)*DIM + c8;
            *reinterpret_cast<uint4*>(&Kh[r*FA_RS + c8]) = *reinterpret_cast<const uint4*>(Khg + g);
            *reinterpret_cast<uint4*>(&Kl[r*FA_RS + c8]) = *reinterpret_cast<const uint4*>(Klg + g);
            *reinterpret_cast<uint4*>(&Vh[r*FA_RS + c8]) = *reinterpret_cast<const uint4*>(Vhg + g);
            *reinterpret_cast<uint4*>(&Vl[r*FA_RS + c8]) = *reinterpret_cast<const uint4*>(Vlg + g);
        }
        __syncthreads();

        float sacc[8][4];
#pragma unroll
        for (int i=0;i<8;i++)
#pragma unroll
            for (int j=0;j<4;j++) sacc[i][j]=0.f;
#pragma unroll
        for (int ks = 0; ks < 4; ks++) {
            int c = ks*16 + (lane & 3)*2;
            u32 ah0 = *reinterpret_cast<u32*>(&Qh[rq*FA_RS + c]);
            u32 ah1 = *reinterpret_cast<u32*>(&Qh[(rq+8)*FA_RS + c]);
            u32 ah2 = *reinterpret_cast<u32*>(&Qh[rq*FA_RS + c + 8]);
            u32 ah3 = *reinterpret_cast<u32*>(&Qh[(rq+8)*FA_RS + c + 8]);
            u32 al0 = *reinterpret_cast<u32*>(&Ql[rq*FA_RS + c]);
            u32 al1 = *reinterpret_cast<u32*>(&Ql[(rq+8)*FA_RS + c]);
            u32 al2 = *reinterpret_cast<u32*>(&Ql[rq*FA_RS + c + 8]);
            u32 al3 = *reinterpret_cast<u32*>(&Ql[(rq+8)*FA_RS + c + 8]);
#pragma unroll
            for (int nf = 0; nf < 8; nf++) {
                int n = nf*8 + (lane >> 2);
                u32 bh0 = *reinterpret_cast<u32*>(&Kh[n*FA_RS + c]);
                u32 bh1 = *reinterpret_cast<u32*>(&Kh[n*FA_RS + c + 8]);
                u32 bl0 = *reinterpret_cast<u32*>(&Kl[n*FA_RS + c]);
                u32 bl1 = *reinterpret_cast<u32*>(&Kl[n*FA_RS + c + 8]);
                mma_bf16(sacc[nf], ah0,ah1,ah2,ah3, bh0,bh1);
                mma_bf16(sacc[nf], ah0,ah1,ah2,ah3, bl0,bl1);
                mma_bf16(sacc[nf], al0,al1,al2,al3, bh0,bh1);
            }
        }

        float tm_lo = -1e30f, tm_hi = -1e30f;
#pragma unroll
        for (int nf = 0; nf < 8; nf++) {
            tm_lo = fmaxf(tm_lo, fmaxf(sacc[nf][0], sacc[nf][1]));
            tm_hi = fmaxf(tm_hi, fmaxf(sacc[nf][2], sacc[nf][3]));
        }
        tm_lo = fmaxf(tm_lo, __shfl_xor_sync(0xffffffffu, tm_lo, 1));
        tm_lo = fmaxf(tm_lo, __shfl_xor_sync(0xffffffffu, tm_lo, 2));
        tm_hi = fmaxf(tm_hi, __shfl_xor_sync(0xffffffffu, tm_hi, 1));
        tm_hi = fmaxf(tm_hi, __shfl_xor_sync(0xffffffffu, tm_hi, 2));
        float mn_lo = fmaxf(m_lo, tm_lo), mn_hi = fmaxf(m_hi, tm_hi);
        float f_lo = fexp(m_lo - mn_lo, cfac), f_hi = fexp(m_hi - mn_hi, cfac);
        m_lo = mn_lo; m_hi = mn_hi;

        float ts_lo = 0.f, ts_hi = 0.f;
        u32 plo[8], phi[8];
#pragma unroll
        for (int nf = 0; nf < 8; nf++) {
            float p0 = fexp(sacc[nf][0] - mn_lo, cfac);
            float p1 = fexp(sacc[nf][1] - mn_lo, cfac);
            float p2 = fexp(sacc[nf][2] - mn_hi, cfac);
            float p3 = fexp(sacc[nf][3] - mn_hi, cfac);
            ts_lo += p0 + p1; ts_hi += p2 + p3;
            __half2 hl = __floats2half2_rn(p0, p1);
            __half2 hh = __floats2half2_rn(p2, p3);
            plo[nf] = *reinterpret_cast<u32*>(&hl);
            phi[nf] = *reinterpret_cast<u32*>(&hh);
        }
        ts_lo += __shfl_xor_sync(0xffffffffu, ts_lo, 1);
        ts_lo += __shfl_xor_sync(0xffffffffu, ts_lo, 2);
        ts_hi += __shfl_xor_sync(0xffffffffu, ts_hi, 1);
        ts_hi += __shfl_xor_sync(0xffffffffu, ts_hi, 2);
        l_lo = l_lo * f_lo + ts_lo;
        l_hi = l_hi * f_hi + ts_hi;

#pragma unroll
        for (int ef = 0; ef < 8; ef++) {
            o[ef][0] *= f_lo; o[ef][1] *= f_lo;
            o[ef][2] *= f_hi; o[ef][3] *= f_hi;
        }

#pragma unroll
        for (int ks = 0; ks < 4; ks++) {
            int k0 = ks*16 + (lane & 3)*2;
            u32 a0 = plo[2*ks], a1 = phi[2*ks], a2 = plo[2*ks+1], a3 = phi[2*ks+1];
#pragma unroll
            for (int ef = 0; ef < 8; ef++) {
                int e = ef*8 + (lane >> 2);
                u32 b0h = pk(Vh[k0*FA_RS+e],     Vh[(k0+1)*FA_RS+e]);
                u32 b1h = pk(Vh[(k0+8)*FA_RS+e], Vh[(k0+9)*FA_RS+e]);
                u32 b0l = pk(Vl[k0*FA_RS+e],     Vl[(k0+1)*FA_RS+e]);
                u32 b1l = pk(Vl[(k0+8)*FA_RS+e], Vl[(k0+9)*FA_RS+e]);
                mma_f16(o[ef], a0,a1,a2,a3, b0h,b1h);
                mma_f16(o[ef], a0,a1,a2,a3, b0l,b1l);
            }
        }
    }

    float il_lo = 1.0f / l_lo, il_hi = 1.0f / l_hi;
    size_t row = (size_t)b*SEQ + q0 + rq;
#pragma unroll
    for (int ef = 0; ef < 8; ef++) {
        int col = h*HD + ef*8 + (lane & 3)*2;
        float v0 = o[ef][0]*il_lo, v1 = o[ef][1]*il_lo;
        float v2 = o[ef][2]*il_hi, v3 = o[ef][3]*il_hi;
        if (mode == 0) {
            *reinterpret_cast<float2*>(&Of[row*DIM + col])     = make_float2(v0, v1);
            *reinterpret_cast<float2*>(&Of[(row+8)*DIM + col]) = make_float2(v2, v3);
        } else {
            u16 h0,l0,h1,l1,h2,l2,h3,l3;
            bsplit(v0,h0,l0); bsplit(v1,h1,l1); bsplit(v2,h2,l2); bsplit(v3,h3,l3);
            *reinterpret_cast<u32*>(&Oh[row*DIM + col])     = pk(h0,h1);
            *reinterpret_cast<u32*>(&Ol[row*DIM + col])     = pk(l0,l1);
            *reinterpret_cast<u32*>(&Oh[(row+8)*DIM + col]) = pk(h2,h3);
            *reinterpret_cast<u32*>(&Ol[(row+8)*DIM + col]) = pk(l2,l3);
        }
    }
}

// ---------------- batch norm ----------------
__global__ __launch_bounds__(256)
void bn_stats(const float* __restrict__ X, const float* __restrict__ Y)
{
    int f  = blockIdx.x*32 + threadIdx.x;
    int rb = blockIdx.y*512;
    float s = 0.0f, s2 = 0.0f;
    for (int r = rb + threadIdx.y; r < rb + 512; r += 8) {
        size_t idx = (size_t)r*DIM + f;
        float v = X[idx] + Y[idx];
        s += v; s2 = fmaf(v, v, s2);
    }
    __shared__ double sh[2][8][32];
    sh[0][threadIdx.y][threadIdx.x] = (double)s;
    sh[1][threadIdx.y][threadIdx.x] = (double)s2;
    __syncthreads();
    if (threadIdx.y == 0) {
        double ts = 0.0, ts2 = 0.0;
#pragma unroll
        for (int i = 0; i < 8; i++) { ts += sh[0][i][threadIdx.x]; ts2 += sh[1][i][threadIdx.x]; }
        g_psum [blockIdx.y][f] = ts;
        g_psum2[blockIdx.y][f] = ts2;
    }
}

__global__ void bn_finalize(const float* __restrict__ g, const float* __restrict__ b)
{
    int f = blockIdx.x*256 + threadIdx.x;
    if (f >= DIM) return;
    double s = 0.0, s2 = 0.0;
#pragma unroll
    for (int i = 0; i < 8; i++) { s += g_psum[i][f]; s2 += g_psum2[i][f]; }
    double mu  = s  * (1.0 / ROWS);
    double var = s2 * (1.0 / ROWS) - mu*mu;
    float rstd = (float)(1.0 / sqrt(var + 1e-5));
    float sc = g[f] * rstd;
    g_bnsc[f] = sc;
    g_bnsh[f] = b[f] - (float)mu * sc;
}

// O = (X+Y)*sc + sh, fp32 + bf16-split outputs
__global__ __launch_bounds__(256)
void bn_apply2(const float* __restrict__ X, const float* __restrict__ Y,
               float* __restrict__ O, u16* __restrict__ Oh, u16* __restrict__ Ol)
{
    int idx4 = blockIdx.x*256 + threadIdx.x;
    if (idx4 >= ROWS*DIM/4) return;
    int f = (idx4*4) % DIM;
    float4 x = *reinterpret_cast<const float4*>(&X[(size_t)idx4*4]);
    float4 y = *reinterpret_cast<const float4*>(&Y[(size_t)idx4*4]);
    float4 o;
    o.x = fmaf(x.x + y.x, g_bnsc[f+0], g_bnsh[f+0]);
    o.y = fmaf(x.y + y.y, g_bnsc[f+1], g_bnsh[f+1]);
    o.z = fmaf(x.z + y.z, g_bnsc[f+2], g_bnsh[f+2]);
    o.w = fmaf(x.w + y.w, g_bnsc[f+3], g_bnsh[f+3]);
    *reinterpret_cast<float4*>(&O[(size_t)idx4*4]) = o;
    u16 h0,l0,h1,l1,h2,l2,h3,l3;
    bsplit(o.x,h0,l0); bsplit(o.y,h1,l1); bsplit(o.z,h2,l2); bsplit(o.w,h3,l3);
    *reinterpret_cast<uint2*>(&Oh[(size_t)idx4*4]) = make_uint2(pk(h0,h1), pk(h2,h3));
    *reinterpret_cast<uint2*>(&Ol[(size_t)idx4*4]) = make_uint2(pk(l0,l1), pk(l2,l3));
}

// ---------------- launch ----------------
static float* sym(const void* s)
{
    void* p = nullptr;
    cudaGetSymbolAddress(&p, s);
    return (float*)p;
}

extern "C" void kernel_launch(void* const* d_in, const int* in_sizes, int n_in,
                              void* d_out, int out_size)
{
    const int*   x     = (const int*)  d_in[0];
    const float* encod = (const float*)d_in[1];
    const float* embed = (const float*)d_in[2];
    const float* Wq  = (const float*)d_in[3];  const float* bq  = (const float*)d_in[4];
    const float* Wk  = (const float*)d_in[5];  const float* bk  = (const float*)d_in[6];
    const float* Wv  = (const float*)d_in[7];  const float* bv  = (const float*)d_in[8];
    const float* g1  = (const float*)d_in[9];  const float* b1  = (const float*)d_in[10];
    const float* Wq2 = (const float*)d_in[11]; const float* bq2 = (const float*)d_in[12];
    const float* Wk2 = (const float*)d_in[13]; const float* bk2 = (const float*)d_in[14];
    const float* Wv2 = (const float*)d_in[15]; const float* bv2 = (const float*)d_in[16];
    const float* Wo2 = (const float*)d_in[17]; const float* bo2 = (const float*)d_in[18];
    const float* g2  = (const float*)d_in[19]; const float* b2  = (const float*)d_in[20];
    const float* Wf  = (const float*)d_in[21]; const float* bf  = (const float*)d_in[22];
    float* out = (float*)d_out;

    float *im = sym(g_im), *sa = sym(g_sa), *t1 = sym(g_t1);
    float *m2 = sym(g_m2), *t2 = sym(g_t2), *ff = sym(g_ff);
    u16 *imh = (u16*)sym(g_imh), *iml = (u16*)sym(g_iml);
    u16 *qh = (u16*)sym(g_qh), *ql = (u16*)sym(g_ql);
    u16 *kh = (u16*)sym(g_kh), *kl = (u16*)sym(g_kl);
    u16 *vh = (u16*)sym(g_vh), *vl = (u16*)sym(g_vl);
    u16 *t1h = (u16*)sym(g_t1h), *t1l = (u16*)sym(g_t1l);
    u16 *t2h = (u16*)sym(g_t2h), *t2l = (u16*)sym(g_t2l);
    u16 *q2h = (u16*)sym(g_q2h), *q2l = (u16*)sym(g_q2l);
    u16 *k2h = (u16*)sym(g_k2h), *k2l = (u16*)sym(g_k2l);
    u16 *v2h = (u16*)sym(g_v2h), *v2l = (u16*)sym(g_v2l);
    u16 *avh = (u16*)sym(g_avh), *avl = (u16*)sym(g_avl);
    u16 *ench = (u16*)sym(g_ench), *encl = (u16*)sym(g_encl);
    u16 *wh = (u16*)sym(g_Wh), *wl = (u16*)sym(g_Wl);

    cudaFuncSetAttribute(fused_attn, cudaFuncAttributeMaxDynamicSharedMemorySize, FA_SMEM);

    const float scale1 = 1.0f / sqrtf((float)DIM);
    const float scale2 = 1.0f / sqrtf((float)HD);

    dim3 gemmGrid(DIM/128, ROWS/128);      // (6, 32)
    dim3 qkvGrid(3*DIM/128, ROWS/128);     // (18, 32)
    dim3 faGrid(SEQ/128, 1, NBH);          // (8, 1, 48)
    dim3 bnGrid(DIM/32, 8);
    dim3 bnBlk(32, 8);
    int ew4Blocks = (ROWS*DIM/4 + 255)/256;

    // one-time: PE table + merged splits (single launches)
    pe_table_kernel<<<(SEQ*DIM/2 + 255)/256, 256>>>();
    allsplit_kernel<<<(SPLIT_TOT + 255)/256, 256>>>(Wq, Wk, Wv, Wq2, Wk2, Wv2, Wo2, Wf, encod);

    embed_pos_kernel<<<ew4Blocks, 256>>>(x, embed, im, imh, iml);

    // loop-invariant cross-attention projections (split bf16 outputs)
    gemm_ts<<<gemmGrid, 256>>>(ench, encl, DIM, 0,   wh+OFF_Q2, wl+OFF_Q2, bq2,
                               nullptr, q2h, q2l, DIM, DIM/2, 0, 1);
    gemm_ts<<<gemmGrid, 256>>>(ench, encl, DIM, 384, wh+OFF_K2, wl+OFF_K2, bk2,
                               nullptr, k2h, k2l, DIM, DIM/2, 0, 1);

    for (int li = 0; li < NITER; li++) {
        // self attention
        qkv_gemm_ts<<<qkvGrid, 256>>>(bq, bk, bv);
        fused_attn<<<faGrid, 256, FA_SMEM>>>(qh, ql, kh, kl, vh, vl,
                                             sa, nullptr, nullptr, scale1, 0);

        bn_stats<<<bnGrid, bnBlk>>>(im, sa);
        bn_finalize<<<3, 256>>>(g1, b1);
        bn_apply2<<<ew4Blocks, 256>>>(im, sa, t1, t1h, t1l);

        // cross attention
        gemm_ts<<<gemmGrid, 256>>>(t1h, t1l, DIM, 0, wh+OFF_V2, wl+OFF_V2, bv2,
                                   nullptr, v2h, v2l, DIM, DIM, 0, 2);
        fused_attn<<<faGrid, 256, FA_SMEM>>>(q2h, q2l, k2h, k2l, v2h, v2l,
                                             nullptr, avh, avl, scale2, 1);
        gemm_ts<<<gemmGrid, 256>>>(avh, avl, DIM, 0, wh+OFF_O2, wl+OFF_O2, bo2,
                                   m2, nullptr, nullptr, DIM, DIM, 0, 0);

        bn_stats<<<bnGrid, bnBlk>>>(m2, t1);
        bn_finalize<<<3, 256>>>(g2, b2);
        bn_apply2<<<ew4Blocks, 256>>>(m2, t1, t2, t2h, t2l);

        // FFN + bn3
        gemm_ts<<<gemmGrid, 256>>>(t2h, t2l, DIM, 0, wh+OFF_F, wl+OFF_F, bf,
                                   ff, nullptr, nullptr, DIM, DIM, 0, 0);
        bn_stats<<<bnGrid, bnBlk>>>(t2, ff);
        bn_finalize<<<3, 256>>>(g2, b2);
        bn_apply2<<<ew4Blocks, 256>>>(t2, ff, im, imh, iml);
    }

    cudaMemcpyAsync(out, im, (size_t)ROWS*DIM*sizeof(float),
                    cudaMemcpyDeviceToDevice);
}

// round 12
// speedup vs baseline: 1.0337x; 1.0279x over previous
#include <cuda_runtime.h>
#include <cuda_bf16.h>
#include <cuda_fp16.h>
#include <math.h>

#define BSZ   4
#define SEQ   1024
#define DIM   768
#define NH    12
#define HD    64
#define ROWS  (BSZ*SEQ)      // 4096
#define NBH   (BSZ*NH)       // 48
#define NITER 2

typedef unsigned short u16;
typedef unsigned int   u32;

// weight-split offsets (elements)
#define OFF_Q   0
#define OFF_K   196608
#define OFF_V   393216
#define OFF_Q2  589824
#define OFF_K2  884736
#define OFF_V2  1179648
#define OFF_O2  1769472
#define OFF_F   2359296
#define WSP_TOT 2949120

// ---------------- static scratch (no allocations allowed) ----------------
__device__ float g_im [ROWS*DIM];
__device__ float g_sa [ROWS*DIM];
__device__ float g_t1 [ROWS*DIM];
__device__ float g_av [ROWS*DIM];
__device__ float g_m2 [ROWS*DIM];
__device__ float g_t2 [ROWS*DIM];
__device__ float g_ff [ROWS*DIM];
__device__ float g_pe [SEQ*DIM];                  // positional encoding table
// split activations (hi/lo) — only the ones re-read many times (attention operands)
__device__ u16 g_qh [ROWS*DIM], g_ql [ROWS*DIM];
__device__ u16 g_kh [ROWS*DIM], g_kl [ROWS*DIM];
__device__ u16 g_vh [ROWS*DIM], g_vl [ROWS*DIM];   // fp16 split
__device__ u16 g_q2h[ROWS*DIM], g_q2l[ROWS*DIM];
__device__ u16 g_k2h[ROWS*DIM], g_k2l[ROWS*DIM];
__device__ u16 g_v2h[ROWS*DIM], g_v2l[ROWS*DIM];   // fp16 split
__device__ u16 g_Wh[WSP_TOT], g_Wl[WSP_TOT];
__device__ double g_psum [8][DIM];
__device__ double g_psum2[8][DIM];
__device__ float  g_bnsc[DIM];
__device__ float  g_bnsh[DIM];

// ---------------- helpers ----------------
__device__ __forceinline__ void bsplit(float x, u16& h, u16& l)
{
    __nv_bfloat16 bh = __float2bfloat16(x);
    h = __bfloat16_as_ushort(bh);
    l = __bfloat16_as_ushort(__float2bfloat16(x - __bfloat162float(bh)));
}
__device__ __forceinline__ void hsplit(float x, u16& h, u16& l)
{
    __half hh = __float2half_rn(x);
    h = __half_as_ushort(hh);
    l = __half_as_ushort(__float2half_rn(x - __half2float(hh)));
}
__device__ __forceinline__ u32 pk(u16 a, u16 b) { return (u32)a | ((u32)b << 16); }

__device__ __forceinline__ void mma_bf16(float d[4], u32 a0, u32 a1, u32 a2, u32 a3,
                                         u32 b0, u32 b1)
{
    asm volatile(
        "mma.sync.aligned.m16n8k16.row.col.f32.bf16.bf16.f32 "
        "{%0,%1,%2,%3}, {%4,%5,%6,%7}, {%8,%9}, {%0,%1,%2,%3};\n"
        : "+f"(d[0]), "+f"(d[1]), "+f"(d[2]), "+f"(d[3])
        : "r"(a0), "r"(a1), "r"(a2), "r"(a3), "r"(b0), "r"(b1));
}
__device__ __forceinline__ void mma_f16(float d[4], u32 a0, u32 a1, u32 a2, u32 a3,
                                        u32 b0, u32 b1)
{
    asm volatile(
        "mma.sync.aligned.m16n8k16.row.col.f32.f16.f16.f32 "
        "{%0,%1,%2,%3}, {%4,%5,%6,%7}, {%8,%9}, {%0,%1,%2,%3};\n"
        : "+f"(d[0]), "+f"(d[1]), "+f"(d[2]), "+f"(d[3])
        : "r"(a0), "r"(a1), "r"(a2), "r"(a3), "r"(b0), "r"(b1));
}

// fast exp with folded factor c (= k*log2e); computes exp(k*x) for x <= ~0
__device__ __forceinline__ float fexp(float x, float c)
{
    float t = fmaxf(x * c, -120.0f);
    float r = t + 12582912.0f;
    float nf = r - 12582912.0f;
    float f = t - nf;
    float p = 1.3333558146e-3f;
    p = fmaf(p, f, 9.6181291077e-3f);
    p = fmaf(p, f, 5.5504108664e-2f);
    p = fmaf(p, f, 2.4022650695e-1f);
    p = fmaf(p, f, 6.9314718056e-1f);
    p = fmaf(p, f, 1.0f);
    int n = __float_as_int(r) - 0x4B400000;
    return __int_as_float(__float_as_int(p) + (n << 23));
}

// ---------------- one-time: PE table ----------------
__global__ void pe_table_kernel()
{
    int idx2 = blockIdx.x*256 + threadIdx.x;
    if (idx2 >= SEQ*DIM/2) return;
    int s = idx2 / (DIM/2), d2 = idx2 - s*(DIM/2);
    float inv = exp2f((float)d2 * (-13.287712379549449f * 2.0f / (float)DIM));
    float ang = (float)s * inv;
    g_pe[(size_t)s*DIM + 2*d2]     = sinf(ang);
    g_pe[(size_t)s*DIM + 2*d2 + 1] = cosf(ang);
}

// ---------------- one-time: weight splits in one launch ----------------
__global__ void allsplit_kernel(const float* __restrict__ p0, const float* __restrict__ p1,
                                const float* __restrict__ p2, const float* __restrict__ p3,
                                const float* __restrict__ p4, const float* __restrict__ p5,
                                const float* __restrict__ p6, const float* __restrict__ p7)
{
    int i = blockIdx.x*256 + threadIdx.x;
    if (i >= WSP_TOT) return;
    const float* p; int j;
    if      (i < OFF_K)  { p = p0; j = i; }
    else if (i < OFF_V)  { p = p1; j = i - OFF_K; }
    else if (i < OFF_Q2) { p = p2; j = i - OFF_V; }
    else if (i < OFF_K2) { p = p3; j = i - OFF_Q2; }
    else if (i < OFF_V2) { p = p4; j = i - OFF_K2; }
    else if (i < OFF_O2) { p = p5; j = i - OFF_V2; }
    else if (i < OFF_F)  { p = p6; j = i - OFF_O2; }
    else                 { p = p7; j = i - OFF_F; }
    u16 h, l;
    bsplit(p[j], h, l);
    g_Wh[i] = h;
    g_Wl[i] = l;
}

// ---------------- embedding + PE (memory-bound gather) ----------------
__global__ void embed_pos_kernel(const int* __restrict__ x,
                                 const float* __restrict__ embed,
                                 float* __restrict__ out)
{
    int idx4 = blockIdx.x * 256 + threadIdx.x;
    if (idx4 >= ROWS*DIM/4) return;
    int r = idx4 / (DIM/4), d = (idx4 - r*(DIM/4))*4;
    int s = r & (SEQ-1);
    int tok = x[r];
    float4 e = *reinterpret_cast<const float4*>(&embed[(size_t)tok*DIM + d]);
    float4 p = *reinterpret_cast<const float4*>(&g_pe[(size_t)s*DIM + d]);
    float4 o;
    o.x = fmaf(2.0f, e.x, p.x); o.y = fmaf(2.0f, e.y, p.y);
    o.z = fmaf(2.0f, e.z, p.z); o.w = fmaf(2.0f, e.w, p.w);
    *reinterpret_cast<float4*>(&out[(size_t)idx4*4]) = o;
}

// ---------------- GEMM body: A fp32 (inline split), W pre-split ----------------
// out modes: 0 = fp32, 1 = bf16 split, 2 = fp16 split
#define GA_RS 40
#define GB_RS 136
__device__ __forceinline__ void gemm_body(
    const float* __restrict__ Ab, int lda,
    const u16* __restrict__ Wh, const u16* __restrict__ Wl,
    const float* __restrict__ bias,
    float* __restrict__ Cf, u16* __restrict__ Ch, u16* __restrict__ Cl,
    int N, int K, int bm, int bn, int relu, int mode,
    u16* Ah, u16* Al, u16* Bh, u16* Bl)
{
    int tid = threadIdx.x;
    int lane = tid & 31, wid = tid >> 5;
    int wm = wid & 1, wn = wid >> 1;

    float acc[4][4][4];
#pragma unroll
    for (int i=0;i<4;i++)
#pragma unroll
        for (int j=0;j<4;j++)
#pragma unroll
            for (int q=0;q<4;q++) acc[i][j][q]=0.f;

    for (int kb = 0; kb < K; kb += 32) {
        // A tile 128x32 fp32 -> inline split (one fp32 stream, conversion under mma shadow)
#pragma unroll
        for (int it = 0; it < 4; it++) {
            int idx = it*256 + tid;
            int r = idx >> 3, c4 = (idx & 7) * 4;
            float4 v = *reinterpret_cast<const float4*>(Ab + (size_t)r*lda + kb + c4);
            u16 h0,l0,h1,l1,h2,l2,h3,l3;
            bsplit(v.x,h0,l0); bsplit(v.y,h1,l1); bsplit(v.z,h2,l2); bsplit(v.w,h3,l3);
            *reinterpret_cast<u32*>(&Ah[r*GA_RS + c4])     = pk(h0,h1);
            *reinterpret_cast<u32*>(&Ah[r*GA_RS + c4 + 2]) = pk(h2,h3);
            *reinterpret_cast<u32*>(&Al[r*GA_RS + c4])     = pk(l0,l1);
            *reinterpret_cast<u32*>(&Al[r*GA_RS + c4 + 2]) = pk(l2,l3);
        }
        // B tile 32x128 pre-split: pure uint4 copies (weights read 32x, split once)
#pragma unroll
        for (int it = 0; it < 2; it++) {
            int idx = it*256 + tid;
            int kk = idx >> 4, c8 = (idx & 15) * 8;
            *reinterpret_cast<uint4*>(&Bh[kk*GB_RS + c8]) =
                *reinterpret_cast<const uint4*>(&Wh[(size_t)(kb+kk)*N + bn + c8]);
            *reinterpret_cast<uint4*>(&Bl[kk*GB_RS + c8]) =
                *reinterpret_cast<const uint4*>(&Wl[(size_t)(kb+kk)*N + bn + c8]);
        }
        __syncthreads();
#pragma unroll
        for (int ks = 0; ks < 32; ks += 16) {
            u32 bhf[4][2], blf[4][2];
#pragma unroll
            for (int nf = 0; nf < 4; nf++) {
                int n  = wn*32 + nf*8 + (lane >> 2);
                int k0 = ks + (lane & 3)*2;
                bhf[nf][0] = pk(Bh[k0*GB_RS+n],     Bh[(k0+1)*GB_RS+n]);
                bhf[nf][1] = pk(Bh[(k0+8)*GB_RS+n], Bh[(k0+9)*GB_RS+n]);
                blf[nf][0] = pk(Bl[k0*GB_RS+n],     Bl[(k0+1)*GB_RS+n]);
                blf[nf][1] = pk(Bl[(k0+8)*GB_RS+n], Bl[(k0+9)*GB_RS+n]);
            }
#pragma unroll
            for (int mf = 0; mf < 4; mf++) {
                int r = wm*64 + mf*16 + (lane >> 2);
                int c = ks + (lane & 3)*2;
                u32 ah0 = *reinterpret_cast<u32*>(&Ah[r*GA_RS + c]);
                u32 ah1 = *reinterpret_cast<u32*>(&Ah[(r+8)*GA_RS + c]);
                u32 ah2 = *reinterpret_cast<u32*>(&Ah[r*GA_RS + c + 8]);
                u32 ah3 = *reinterpret_cast<u32*>(&Ah[(r+8)*GA_RS + c + 8]);
                u32 al0 = *reinterpret_cast<u32*>(&Al[r*GA_RS + c]);
                u32 al1 = *reinterpret_cast<u32*>(&Al[(r+8)*GA_RS + c]);
                u32 al2 = *reinterpret_cast<u32*>(&Al[r*GA_RS + c + 8]);
                u32 al3 = *reinterpret_cast<u32*>(&Al[(r+8)*GA_RS + c + 8]);
#pragma unroll
                for (int nf = 0; nf < 4; nf++) {
                    mma_bf16(acc[mf][nf], ah0,ah1,ah2,ah3, bhf[nf][0], bhf[nf][1]);
                    mma_bf16(acc[mf][nf], ah0,ah1,ah2,ah3, blf[nf][0], blf[nf][1]);
                    mma_bf16(acc[mf][nf], al0,al1,al2,al3, bhf[nf][0], bhf[nf][1]);
                }
            }
        }
        __syncthreads();
    }
#pragma unroll
    for (int mf = 0; mf < 4; mf++) {
#pragma unroll
        for (int nf = 0; nf < 4; nf++) {
            int r = bm + wm*64 + mf*16 + (lane >> 2);
            int c = bn + wn*32 + nf*8 + (lane & 3)*2;
            float b0 = bias[c], b1 = bias[c+1];
            float v0 = acc[mf][nf][0] + b0, v1 = acc[mf][nf][1] + b1;
            float v2 = acc[mf][nf][2] + b0, v3 = acc[mf][nf][3] + b1;
            if (relu) { v0=fmaxf(v0,0.f); v1=fmaxf(v1,0.f); v2=fmaxf(v2,0.f); v3=fmaxf(v3,0.f); }
            if (mode == 0) {
                *reinterpret_cast<float2*>(&Cf[(size_t)r*N + c])     = make_float2(v0, v1);
                *reinterpret_cast<float2*>(&Cf[(size_t)(r+8)*N + c]) = make_float2(v2, v3);
            } else {
                u16 h0,l0,h1,l1,h2,l2,h3,l3;
                if (mode == 1) { bsplit(v0,h0,l0); bsplit(v1,h1,l1); bsplit(v2,h2,l2); bsplit(v3,h3,l3); }
                else           { hsplit(v0,h0,l0); hsplit(v1,h1,l1); hsplit(v2,h2,l2); hsplit(v3,h3,l3); }
                *reinterpret_cast<u32*>(&Ch[(size_t)r*N + c])     = pk(h0,h1);
                *reinterpret_cast<u32*>(&Cl[(size_t)r*N + c])     = pk(l0,l1);
                *reinterpret_cast<u32*>(&Ch[(size_t)(r+8)*N + c]) = pk(h2,h3);
                *reinterpret_cast<u32*>(&Cl[(size_t)(r+8)*N + c]) = pk(l2,l3);
            }
        }
    }
}

__global__ __launch_bounds__(256, 2)
void gemm_ts(const float* __restrict__ A, int lda, int aoff,
             const u16* __restrict__ Wh, const u16* __restrict__ Wl,
             const float* __restrict__ bias,
             float* __restrict__ Cf, u16* __restrict__ Ch, u16* __restrict__ Cl,
             int N, int K, int relu, int mode)
{
    __shared__ __align__(16) u16 Ah[128*GA_RS], Al[128*GA_RS];
    __shared__ __align__(16) u16 Bh[32*GB_RS],  Bl[32*GB_RS];
    int bm = blockIdx.y*128, bn = blockIdx.x*128;
    gemm_body(A + (size_t)bm*lda + aoff, lda, Wh, Wl, bias,
              Cf, Ch, Cl, N, K, bm, bn, relu, mode, Ah, Al, Bh, Bl);
}

// fused QKV: grid (18, 32); group = x/6 selects q(bf16)/k(bf16)/v(fp16)
__global__ __launch_bounds__(256, 2)
void qkv_gemm_ts(const float* __restrict__ A,
                 const float* __restrict__ bq, const float* __restrict__ bk,
                 const float* __restrict__ bv)
{
    __shared__ __align__(16) u16 Ah[128*GA_RS], Al[128*GA_RS];
    __shared__ __align__(16) u16 Bh[32*GB_RS],  Bl[32*GB_RS];
    int grp = blockIdx.x / 6;
    int bxl = blockIdx.x - grp*6;
    int bm = blockIdx.y*128, bn = bxl*128;
    const u16* Wh = g_Wh + grp*196608;
    const u16* Wl = g_Wl + grp*196608;
    const float* bias = (grp == 0) ? bq : (grp == 1) ? bk : bv;
    u16* Ch = (grp == 0) ? g_qh : (grp == 1) ? g_kh : g_vh;
    u16* Cl = (grp == 0) ? g_ql : (grp == 1) ? g_kl : g_vl;
    int mode = (grp == 2) ? 2 : 1;
    int aoff = grp*256;
    gemm_body(A + (size_t)bm*DIM + aoff, DIM, Wh, Wl, bias,
              nullptr, Ch, Cl, DIM, 256, bm, bn, 1, mode, Ah, Al, Bh, Bl);
}

// ---------------- fused flash attention on pre-split inputs, fp32 output ----------------
#define FA_RS 72
#define FA_SMEM ((2*128*FA_RS + 4*64*FA_RS) * 2)   // 73728 bytes
__global__ __launch_bounds__(256, 2)
void fused_attn(const u16* __restrict__ Qhg, const u16* __restrict__ Qlg,
                const u16* __restrict__ Khg, const u16* __restrict__ Klg,
                const u16* __restrict__ Vhg, const u16* __restrict__ Vlg,
                float* __restrict__ Of, float scale)
{
    extern __shared__ u16 sm[];
    u16* Qh = sm;
    u16* Ql = Qh + 128*FA_RS;
    u16* Kh = Ql + 128*FA_RS;
    u16* Kl = Kh + 64*FA_RS;
    u16* Vh = Kl + 64*FA_RS;
    u16* Vl = Vh + 64*FA_RS;

    int bh = blockIdx.z;
    int b = bh / NH, h = bh - b*NH;
    int tid = threadIdx.x, lane = tid & 31, w = tid >> 5;
    size_t base = ((size_t)b*SEQ)*DIM + h*HD;
    int q0 = blockIdx.x * 128;
    const float cfac = scale * 1.4426950408889634f;

#pragma unroll
    for (int it = 0; it < 4; it++) {
        int idx = it*256 + tid;
        int r = idx >> 3, c8 = (idx & 7) * 8;
        *reinterpret_cast<uint4*>(&Qh[r*FA_RS + c8]) =
            *reinterpret_cast<const uint4*>(Qhg + base + (size_t)(q0+r)*DIM + c8);
        *reinterpret_cast<uint4*>(&Ql[r*FA_RS + c8]) =
            *reinterpret_cast<const uint4*>(Qlg + base + (size_t)(q0+r)*DIM + c8);
    }

    float o[8][4];
#pragma unroll
    for (int i=0;i<8;i++)
#pragma unroll
        for (int j=0;j<4;j++) o[i][j]=0.f;
    float m_lo = -1e30f, m_hi = -1e30f, l_lo = 0.f, l_hi = 0.f;

    int rq = w*16 + (lane >> 2);

    for (int t0 = 0; t0 < SEQ; t0 += 64) {
        __syncthreads();
#pragma unroll
        for (int it = 0; it < 2; it++) {
            int idx = it*256 + tid;
            int r = idx >> 3, c8 = (idx & 7) * 8;
            size_t g = base + (size_t)(t0+r)*DIM + c8;
            *reinterpret_cast<uint4*>(&Kh[r*FA_RS + c8]) = *reinterpret_cast<const uint4*>(Khg + g);
            *reinterpret_cast<uint4*>(&Kl[r*FA_RS + c8]) = *reinterpret_cast<const uint4*>(Klg + g);
            *reinterpret_cast<uint4*>(&Vh[r*FA_RS + c8]) = *reinterpret_cast<const uint4*>(Vhg + g);
            *reinterpret_cast<uint4*>(&Vl[r*FA_RS + c8]) = *reinterpret_cast<const uint4*>(Vlg + g);
        }
        __syncthreads();

        float sacc[8][4];
#pragma unroll
        for (int i=0;i<8;i++)
#pragma unroll
            for (int j=0;j<4;j++) sacc[i][j]=0.f;
#pragma unroll
        for (int ks = 0; ks < 4; ks++) {
            int c = ks*16 + (lane & 3)*2;
            u32 ah0 = *reinterpret_cast<u32*>(&Qh[rq*FA_RS + c]);
            u32 ah1 = *reinterpret_cast<u32*>(&Qh[(rq+8)*FA_RS + c]);
            u32 ah2 = *reinterpret_cast<u32*>(&Qh[rq*FA_RS + c + 8]);
            u32 ah3 = *reinterpret_cast<u32*>(&Qh[(rq+8)*FA_RS + c + 8]);
            u32 al0 = *reinterpret_cast<u32*>(&Ql[rq*FA_RS + c]);
            u32 al1 = *reinterpret_cast<u32*>(&Ql[(rq+8)*FA_RS + c]);
            u32 al2 = *reinterpret_cast<u32*>(&Ql[rq*FA_RS + c + 8]);
            u32 al3 = *reinterpret_cast<u32*>(&Ql[(rq+8)*FA_RS + c + 8]);
#pragma unroll
            for (int nf = 0; nf < 8; nf++) {
                int n = nf*8 + (lane >> 2);
                u32 bh0 = *reinterpret_cast<u32*>(&Kh[n*FA_RS + c]);
                u32 bh1 = *reinterpret_cast<u32*>(&Kh[n*FA_RS + c + 8]);
                u32 bl0 = *reinterpret_cast<u32*>(&Kl[n*FA_RS + c]);
                u32 bl1 = *reinterpret_cast<u32*>(&Kl[n*FA_RS + c + 8]);
                mma_bf16(sacc[nf], ah0,ah1,ah2,ah3, bh0,bh1);
                mma_bf16(sacc[nf], ah0,ah1,ah2,ah3, bl0,bl1);
                mma_bf16(sacc[nf], al0,al1,al2,al3, bh0,bh1);
            }
        }

        float tm_lo = -1e30f, tm_hi = -1e30f;
#pragma unroll
        for (int nf = 0; nf < 8; nf++) {
            tm_lo = fmaxf(tm_lo, fmaxf(sacc[nf][0], sacc[nf][1]));
            tm_hi = fmaxf(tm_hi, fmaxf(sacc[nf][2], sacc[nf][3]));
        }
        tm_lo = fmaxf(tm_lo, __shfl_xor_sync(0xffffffffu, tm_lo, 1));
        tm_lo = fmaxf(tm_lo, __shfl_xor_sync(0xffffffffu, tm_lo, 2));
        tm_hi = fmaxf(tm_hi, __shfl_xor_sync(0xffffffffu, tm_hi, 1));
        tm_hi = fmaxf(tm_hi, __shfl_xor_sync(0xffffffffu, tm_hi, 2));
        float mn_lo = fmaxf(m_lo, tm_lo), mn_hi = fmaxf(m_hi, tm_hi);
        float f_lo = fexp(m_lo - mn_lo, cfac), f_hi = fexp(m_hi - mn_hi, cfac);
        m_lo = mn_lo; m_hi = mn_hi;

        float ts_lo = 0.f, ts_hi = 0.f;
        u32 plo[8], phi[8];
#pragma unroll
        for (int nf = 0; nf < 8; nf++) {
            float p0 = fexp(sacc[nf][0] - mn_lo, cfac);
            float p1 = fexp(sacc[nf][1] - mn_lo, cfac);
            float p2 = fexp(sacc[nf][2] - mn_hi, cfac);
            float p3 = fexp(sacc[nf][3] - mn_hi, cfac);
            ts_lo += p0 + p1; ts_hi += p2 + p3;
            __half2 hl = __floats2half2_rn(p0, p1);
            __half2 hh = __floats2half2_rn(p2, p3);
            plo[nf] = *reinterpret_cast<u32*>(&hl);
            phi[nf] = *reinterpret_cast<u32*>(&hh);
        }
        ts_lo += __shfl_xor_sync(0xffffffffu, ts_lo, 1);
        ts_lo += __shfl_xor_sync(0xffffffffu, ts_lo, 2);
        ts_hi += __shfl_xor_sync(0xffffffffu, ts_hi, 1);
        ts_hi += __shfl_xor_sync(0xffffffffu, ts_hi, 2);
        l_lo = l_lo * f_lo + ts_lo;
        l_hi = l_hi * f_hi + ts_hi;

#pragma unroll
        for (int ef = 0; ef < 8; ef++) {
            o[ef][0] *= f_lo; o[ef][1] *= f_lo;
            o[ef][2] *= f_hi; o[ef][3] *= f_hi;
        }

#pragma unroll
        for (int ks = 0; ks < 4; ks++) {
            int k0 = ks*16 + (lane & 3)*2;
            u32 a0 = plo[2*ks], a1 = phi[2*ks], a2 = plo[2*ks+1], a3 = phi[2*ks+1];
#pragma unroll
            for (int ef = 0; ef < 8; ef++) {
                int e = ef*8 + (lane >> 2);
                u32 b0h = pk(Vh[k0*FA_RS+e],     Vh[(k0+1)*FA_RS+e]);
                u32 b1h = pk(Vh[(k0+8)*FA_RS+e], Vh[(k0+9)*FA_RS+e]);
                u32 b0l = pk(Vl[k0*FA_RS+e],     Vl[(k0+1)*FA_RS+e]);
                u32 b1l = pk(Vl[(k0+8)*FA_RS+e], Vl[(k0+9)*FA_RS+e]);
                mma_f16(o[ef], a0,a1,a2,a3, b0h,b1h);
                mma_f16(o[ef], a0,a1,a2,a3, b0l,b1l);
            }
        }
    }

    float il_lo = 1.0f / l_lo, il_hi = 1.0f / l_hi;
    size_t row = (size_t)b*SEQ + q0 + rq;
#pragma unroll
    for (int ef = 0; ef < 8; ef++) {
        int col = h*HD + ef*8 + (lane & 3)*2;
        *reinterpret_cast<float2*>(&Of[row*DIM + col]) =
            make_float2(o[ef][0]*il_lo, o[ef][1]*il_lo);
        *reinterpret_cast<float2*>(&Of[(row+8)*DIM + col]) =
            make_float2(o[ef][2]*il_hi, o[ef][3]*il_hi);
    }
}

// ---------------- batch norm ----------------
__global__ __launch_bounds__(256)
void bn_stats(const float* __restrict__ X, const float* __restrict__ Y)
{
    int f  = blockIdx.x*32 + threadIdx.x;
    int rb = blockIdx.y*512;
    float s = 0.0f, s2 = 0.0f;
    for (int r = rb + threadIdx.y; r < rb + 512; r += 8) {
        size_t idx = (size_t)r*DIM + f;
        float v = X[idx] + Y[idx];
        s += v; s2 = fmaf(v, v, s2);
    }
    __shared__ double sh[2][8][32];
    sh[0][threadIdx.y][threadIdx.x] = (double)s;
    sh[1][threadIdx.y][threadIdx.x] = (double)s2;
    __syncthreads();
    if (threadIdx.y == 0) {
        double ts = 0.0, ts2 = 0.0;
#pragma unroll
        for (int i = 0; i < 8; i++) { ts += sh[0][i][threadIdx.x]; ts2 += sh[1][i][threadIdx.x]; }
        g_psum [blockIdx.y][f] = ts;
        g_psum2[blockIdx.y][f] = ts2;
    }
}

__global__ void bn_finalize(const float* __restrict__ g, const float* __restrict__ b)
{
    int f = blockIdx.x*256 + threadIdx.x;
    if (f >= DIM) return;
    double s = 0.0, s2 = 0.0;
#pragma unroll
    for (int i = 0; i < 8; i++) { s += g_psum[i][f]; s2 += g_psum2[i][f]; }
    double mu  = s  * (1.0 / ROWS);
    double var = s2 * (1.0 / ROWS) - mu*mu;
    float rstd = (float)(1.0 / sqrt(var + 1e-5));
    float sc = g[f] * rstd;
    g_bnsc[f] = sc;
    g_bnsh[f] = b[f] - (float)mu * sc;
}

// O = (X+Y)*sc + sh, fp32 only
__global__ __launch_bounds__(256)
void bn_apply2(const float* __restrict__ X, const float* __restrict__ Y,
               float* __restrict__ O)
{
    int idx4 = blockIdx.x*256 + threadIdx.x;
    if (idx4 >= ROWS*DIM/4) return;
    int f = (idx4*4) % DIM;
    float4 x = *reinterpret_cast<const float4*>(&X[(size_t)idx4*4]);
    float4 y = *reinterpret_cast<const float4*>(&Y[(size_t)idx4*4]);
    float4 o;
    o.x = fmaf(x.x + y.x, g_bnsc[f+0], g_bnsh[f+0]);
    o.y = fmaf(x.y + y.y, g_bnsc[f+1], g_bnsh[f+1]);
    o.z = fmaf(x.z + y.z, g_bnsc[f+2], g_bnsh[f+2]);
    o.w = fmaf(x.w + y.w, g_bnsc[f+3], g_bnsh[f+3]);
    *reinterpret_cast<float4*>(&O[(size_t)idx4*4]) = o;
}

// ---------------- launch ----------------
static float* sym(const void* s)
{
    void* p = nullptr;
    cudaGetSymbolAddress(&p, s);
    return (float*)p;
}

extern "C" void kernel_launch(void* const* d_in, const int* in_sizes, int n_in,
                              void* d_out, int out_size)
{
    const int*   x     = (const int*)  d_in[0];
    const float* encod = (const float*)d_in[1];
    const float* embed = (const float*)d_in[2];
    const float* Wq  = (const float*)d_in[3];  const float* bq  = (const float*)d_in[4];
    const float* Wk  = (const float*)d_in[5];  const float* bk  = (const float*)d_in[6];
    const float* Wv  = (const float*)d_in[7];  const float* bv  = (const float*)d_in[8];
    const float* g1  = (const float*)d_in[9];  const float* b1  = (const float*)d_in[10];
    const float* Wq2 = (const float*)d_in[11]; const float* bq2 = (const float*)d_in[12];
    const float* Wk2 = (const float*)d_in[13]; const float* bk2 = (const float*)d_in[14];
    const float* Wv2 = (const float*)d_in[15]; const float* bv2 = (const float*)d_in[16];
    const float* Wo2 = (const float*)d_in[17]; const float* bo2 = (const float*)d_in[18];
    const float* g2  = (const float*)d_in[19]; const float* b2  = (const float*)d_in[20];
    const float* Wf  = (const float*)d_in[21]; const float* bf  = (const float*)d_in[22];
    float* out = (float*)d_out;

    float *im = sym(g_im), *sa = sym(g_sa), *t1 = sym(g_t1), *av = sym(g_av);
    float *m2 = sym(g_m2), *t2 = sym(g_t2), *ff = sym(g_ff);
    u16 *qh = (u16*)sym(g_qh), *ql = (u16*)sym(g_ql);
    u16 *kh = (u16*)sym(g_kh), *kl = (u16*)sym(g_kl);
    u16 *vh = (u16*)sym(g_vh), *vl = (u16*)sym(g_vl);
    u16 *q2h = (u16*)sym(g_q2h), *q2l = (u16*)sym(g_q2l);
    u16 *k2h = (u16*)sym(g_k2h), *k2l = (u16*)sym(g_k2l);
    u16 *v2h = (u16*)sym(g_v2h), *v2l = (u16*)sym(g_v2l);
    u16 *wh = (u16*)sym(g_Wh), *wl = (u16*)sym(g_Wl);

    cudaFuncSetAttribute(fused_attn, cudaFuncAttributeMaxDynamicSharedMemorySize, FA_SMEM);

    const float scale1 = 1.0f / sqrtf((float)DIM);
    const float scale2 = 1.0f / sqrtf((float)HD);

    dim3 gemmGrid(DIM/128, ROWS/128);      // (6, 32)
    dim3 qkvGrid(3*DIM/128, ROWS/128);     // (18, 32)
    dim3 faGrid(SEQ/128, 1, NBH);          // (8, 1, 48)
    dim3 bnGrid(DIM/32, 8);
    dim3 bnBlk(32, 8);
    int ew4Blocks = (ROWS*DIM/4 + 255)/256;

    // one-time: PE table + weight splits
    pe_table_kernel<<<(SEQ*DIM/2 + 255)/256, 256>>>();
    allsplit_kernel<<<(WSP_TOT + 255)/256, 256>>>(Wq, Wk, Wv, Wq2, Wk2, Wv2, Wo2, Wf);

    embed_pos_kernel<<<ew4Blocks, 256>>>(x, embed, im);

    // loop-invariant cross-attention projections (split bf16 outputs for attn)
    gemm_ts<<<gemmGrid, 256>>>(encod, DIM, 0,   wh+OFF_Q2, wl+OFF_Q2, bq2,
                               nullptr, q2h, q2l, DIM, DIM/2, 0, 1);
    gemm_ts<<<gemmGrid, 256>>>(encod, DIM, 384, wh+OFF_K2, wl+OFF_K2, bk2,
                               nullptr, k2h, k2l, DIM, DIM/2, 0, 1);

    for (int li = 0; li < NITER; li++) {
        // self attention
        qkv_gemm_ts<<<qkvGrid, 256>>>(im, bq, bk, bv);
        fused_attn<<<faGrid, 256, FA_SMEM>>>(qh, ql, kh, kl, vh, vl, sa, scale1);

        bn_stats<<<bnGrid, bnBlk>>>(im, sa);
        bn_finalize<<<3, 256>>>(g1, b1);
        bn_apply2<<<ew4Blocks, 256>>>(im, sa, t1);

        // cross attention
        gemm_ts<<<gemmGrid, 256>>>(t1, DIM, 0, wh+OFF_V2, wl+OFF_V2, bv2,
                                   nullptr, v2h, v2l, DIM, DIM, 0, 2);
        fused_attn<<<faGrid, 256, FA_SMEM>>>(q2h, q2l, k2h, k2l, v2h, v2l, av, scale2);
        gemm_ts<<<gemmGrid, 256>>>(av, DIM, 0, wh+OFF_O2, wl+OFF_O2, bo2,
                                   m2, nullptr, nullptr, DIM, DIM, 0, 0);

        bn_stats<<<bnGrid, bnBlk>>>(m2, t1);
        bn_finalize<<<3, 256>>>(g2, b2);
        bn_apply2<<<ew4Blocks, 256>>>(m2, t1, t2);

        // FFN + bn3
        gemm_ts<<<gemmGrid, 256>>>(t2, DIM, 0, wh+OFF_F, wl+OFF_F, bf,
                                   ff, nullptr, nullptr, DIM, DIM, 0, 0);
        bn_stats<<<bnGrid, bnBlk>>>(t2, ff);
        bn_finalize<<<3, 256>>>(g2, b2);
        bn_apply2<<<ew4Blocks, 256>>>(t2, ff, im);
    }

    cudaMemcpyAsync(out, im, (size_t)ROWS*DIM*sizeof(float),
                    cudaMemcpyDeviceToDevice);
}

// round 13
// speedup vs baseline: 1.0412x; 1.0072x over previous
#include <cuda_runtime.h>
#include <cuda_bf16.h>
#include <cuda_fp16.h>
#include <math.h>

#define BSZ   4
#define SEQ   1024
#define DIM   768
#define NH    12
#define HD    64
#define ROWS  (BSZ*SEQ)      // 4096
#define NBH   (BSZ*NH)       // 48
#define NITER 2

typedef unsigned short u16;
typedef unsigned int   u32;

// weight-split offsets (elements)
#define OFF_Q   0
#define OFF_K   196608
#define OFF_V   393216
#define OFF_Q2  589824
#define OFF_K2  884736
#define OFF_V2  1179648
#define OFF_O2  1769472
#define OFF_F   2359296
#define WSP_TOT 2949120

// ---------------- static scratch (no allocations allowed) ----------------
__device__ float g_im [ROWS*DIM];
__device__ float g_sa [ROWS*DIM];
__device__ float g_t1 [ROWS*DIM];
__device__ float g_av [ROWS*DIM];
__device__ float g_m2 [ROWS*DIM];
__device__ float g_t2 [ROWS*DIM];
__device__ float g_ff [ROWS*DIM];
__device__ float g_pe [SEQ*DIM];
__device__ u16 g_qh [ROWS*DIM], g_ql [ROWS*DIM];
__device__ u16 g_kh [ROWS*DIM], g_kl [ROWS*DIM];
__device__ u16 g_vh [ROWS*DIM], g_vl [ROWS*DIM];   // fp16 split
__device__ u16 g_q2h[ROWS*DIM], g_q2l[ROWS*DIM];
__device__ u16 g_k2h[ROWS*DIM], g_k2l[ROWS*DIM];
__device__ u16 g_v2h[ROWS*DIM], g_v2l[ROWS*DIM];   // fp16 split
__device__ u16 g_Wh[WSP_TOT], g_Wl[WSP_TOT];
__device__ double g_psum [8][DIM];
__device__ double g_psum2[8][DIM];
__device__ float  g_bnsc[DIM];
__device__ float  g_bnsh[DIM];

// ---------------- helpers ----------------
__device__ __forceinline__ void bsplit(float x, u16& h, u16& l)
{
    __nv_bfloat16 bh = __float2bfloat16(x);
    h = __bfloat16_as_ushort(bh);
    l = __bfloat16_as_ushort(__float2bfloat16(x - __bfloat162float(bh)));
}
__device__ __forceinline__ void hsplit(float x, u16& h, u16& l)
{
    __half hh = __float2half_rn(x);
    h = __half_as_ushort(hh);
    l = __half_as_ushort(__float2half_rn(x - __half2float(hh)));
}
__device__ __forceinline__ u32 pk(u16 a, u16 b) { return (u32)a | ((u32)b << 16); }

__device__ __forceinline__ void cpa16(void* dst_smem, const void* src)
{
    u32 d = (u32)__cvta_generic_to_shared(dst_smem);
    asm volatile("cp.async.cg.shared.global [%0], [%1], 16;" :: "r"(d), "l"(src));
}
#define CP_COMMIT() asm volatile("cp.async.commit_group;" ::: "memory")
#define CP_WAIT0()  asm volatile("cp.async.wait_group 0;" ::: "memory")

__device__ __forceinline__ void mma_bf16(float d[4], u32 a0, u32 a1, u32 a2, u32 a3,
                                         u32 b0, u32 b1)
{
    asm volatile(
        "mma.sync.aligned.m16n8k16.row.col.f32.bf16.bf16.f32 "
        "{%0,%1,%2,%3}, {%4,%5,%6,%7}, {%8,%9}, {%0,%1,%2,%3};\n"
        : "+f"(d[0]), "+f"(d[1]), "+f"(d[2]), "+f"(d[3])
        : "r"(a0), "r"(a1), "r"(a2), "r"(a3), "r"(b0), "r"(b1));
}
__device__ __forceinline__ void mma_f16(float d[4], u32 a0, u32 a1, u32 a2, u32 a3,
                                        u32 b0, u32 b1)
{
    asm volatile(
        "mma.sync.aligned.m16n8k16.row.col.f32.f16.f16.f32 "
        "{%0,%1,%2,%3}, {%4,%5,%6,%7}, {%8,%9}, {%0,%1,%2,%3};\n"
        : "+f"(d[0]), "+f"(d[1]), "+f"(d[2]), "+f"(d[3])
        : "r"(a0), "r"(a1), "r"(a2), "r"(a3), "r"(b0), "r"(b1));
}

// fast exp with folded factor c (= k*log2e)
__device__ __forceinline__ float fexp(float x, float c)
{
    float t = fmaxf(x * c, -120.0f);
    float r = t + 12582912.0f;
    float nf = r - 12582912.0f;
    float f = t - nf;
    float p = 1.3333558146e-3f;
    p = fmaf(p, f, 9.6181291077e-3f);
    p = fmaf(p, f, 5.5504108664e-2f);
    p = fmaf(p, f, 2.4022650695e-1f);
    p = fmaf(p, f, 6.9314718056e-1f);
    p = fmaf(p, f, 1.0f);
    int n = __float_as_int(r) - 0x4B400000;
    return __int_as_float(__float_as_int(p) + (n << 23));
}

// ---------------- one-time: PE table ----------------
__global__ void pe_table_kernel()
{
    int idx2 = blockIdx.x*256 + threadIdx.x;
    if (idx2 >= SEQ*DIM/2) return;
    int s = idx2 / (DIM/2), d2 = idx2 - s*(DIM/2);
    float inv = exp2f((float)d2 * (-13.287712379549449f * 2.0f / (float)DIM));
    float ang = (float)s * inv;
    g_pe[(size_t)s*DIM + 2*d2]     = sinf(ang);
    g_pe[(size_t)s*DIM + 2*d2 + 1] = cosf(ang);
}

// ---------------- one-time: weight splits ----------------
__global__ void allsplit_kernel(const float* __restrict__ p0, const float* __restrict__ p1,
                                const float* __restrict__ p2, const float* __restrict__ p3,
                                const float* __restrict__ p4, const float* __restrict__ p5,
                                const float* __restrict__ p6, const float* __restrict__ p7)
{
    int i = blockIdx.x*256 + threadIdx.x;
    if (i >= WSP_TOT) return;
    const float* p; int j;
    if      (i < OFF_K)  { p = p0; j = i; }
    else if (i < OFF_V)  { p = p1; j = i - OFF_K; }
    else if (i < OFF_Q2) { p = p2; j = i - OFF_V; }
    else if (i < OFF_K2) { p = p3; j = i - OFF_Q2; }
    else if (i < OFF_V2) { p = p4; j = i - OFF_K2; }
    else if (i < OFF_O2) { p = p5; j = i - OFF_V2; }
    else if (i < OFF_F)  { p = p6; j = i - OFF_O2; }
    else                 { p = p7; j = i - OFF_F; }
    u16 h, l;
    bsplit(p[j], h, l);
    g_Wh[i] = h;
    g_Wl[i] = l;
}

// ---------------- embedding + PE ----------------
__global__ void embed_pos_kernel(const int* __restrict__ x,
                                 const float* __restrict__ embed,
                                 float* __restrict__ out)
{
    int idx4 = blockIdx.x * 256 + threadIdx.x;
    if (idx4 >= ROWS*DIM/4) return;
    int r = idx4 / (DIM/4), d = (idx4 - r*(DIM/4))*4;
    int s = r & (SEQ-1);
    int tok = x[r];
    float4 e = *reinterpret_cast<const float4*>(&embed[(size_t)tok*DIM + d]);
    float4 p = *reinterpret_cast<const float4*>(&g_pe[(size_t)s*DIM + d]);
    float4 o;
    o.x = fmaf(2.0f, e.x, p.x); o.y = fmaf(2.0f, e.y, p.y);
    o.z = fmaf(2.0f, e.z, p.z); o.w = fmaf(2.0f, e.w, p.w);
    *reinterpret_cast<float4*>(&out[(size_t)idx4*4]) = o;
}

// ---------------- GEMM: double-buffered, cp.async B, reg-prefetch A ----------------
// out modes: 0 = fp32, 1 = bf16 split, 2 = fp16 split
#define GA_RS 40
#define GB_RS 136
#define GEMM_SMEM ((4*128*GA_RS + 4*32*GB_RS) * 2)   // 75776 bytes
__device__ __forceinline__ void gemm_body(
    const float* __restrict__ Ab, int lda,
    const u16* __restrict__ Wh, const u16* __restrict__ Wl,
    const float* __restrict__ bias,
    float* __restrict__ Cf, u16* __restrict__ Ch, u16* __restrict__ Cl,
    int N, int K, int bm, int bn, int relu, int mode, u16* sm)
{
    int tid = threadIdx.x;
    int lane = tid & 31, wid = tid >> 5;
    int wm = wid & 1, wn = wid >> 1;

    // smem layout: [A: 2 bufs x (Ah,Al) 128*GA_RS] [B: 2 bufs x (Bh,Bl) 32*GB_RS]
    u16* Bbase = sm + 4*128*GA_RS;
#define AH(b) (sm + (b)*(2*128*GA_RS))
#define AL(b) (sm + (b)*(2*128*GA_RS) + 128*GA_RS)
#define BH(b) (Bbase + (b)*(2*32*GB_RS))
#define BL(b) (Bbase + (b)*(2*32*GB_RS) + 32*GB_RS)

    // loader coords
    int ar[4], ac[4];
#pragma unroll
    for (int it = 0; it < 4; it++) {
        int idx = it*256 + tid;
        ar[it] = idx >> 3; ac[it] = (idx & 7) * 4;
    }
    int bk_[2], bc_[2];
#pragma unroll
    for (int it = 0; it < 2; it++) {
        int idx = it*256 + tid;
        bk_[it] = idx >> 4; bc_[it] = (idx & 15) * 8;
    }

    float acc[4][4][4];
#pragma unroll
    for (int i=0;i<4;i++)
#pragma unroll
        for (int j=0;j<4;j++)
#pragma unroll
            for (int q=0;q<4;q++) acc[i][j][q]=0.f;

    // prologue: stage tile 0
    {
        float4 pa[4];
#pragma unroll
        for (int it = 0; it < 4; it++)
            pa[it] = *reinterpret_cast<const float4*>(Ab + (size_t)ar[it]*lda + ac[it]);
#pragma unroll
        for (int it = 0; it < 4; it++) {
            u16 h0,l0,h1,l1,h2,l2,h3,l3;
            bsplit(pa[it].x,h0,l0); bsplit(pa[it].y,h1,l1);
            bsplit(pa[it].z,h2,l2); bsplit(pa[it].w,h3,l3);
            *reinterpret_cast<u32*>(&AH(0)[ar[it]*GA_RS + ac[it]])     = pk(h0,h1);
            *reinterpret_cast<u32*>(&AH(0)[ar[it]*GA_RS + ac[it] + 2]) = pk(h2,h3);
            *reinterpret_cast<u32*>(&AL(0)[ar[it]*GA_RS + ac[it]])     = pk(l0,l1);
            *reinterpret_cast<u32*>(&AL(0)[ar[it]*GA_RS + ac[it] + 2]) = pk(l2,l3);
        }
#pragma unroll
        for (int it = 0; it < 2; it++) {
            cpa16(&BH(0)[bk_[it]*GB_RS + bc_[it]], &Wh[(size_t)bk_[it]*N + bn + bc_[it]]);
            cpa16(&BL(0)[bk_[it]*GB_RS + bc_[it]], &Wl[(size_t)bk_[it]*N + bn + bc_[it]]);
        }
        CP_COMMIT();
        CP_WAIT0();
        __syncthreads();
    }

    int buf = 0;
    for (int kb = 0; kb < K; kb += 32) {
        bool more = (kb + 32) < K;
        int nb = buf ^ 1;
        float4 pa[4];
        if (more) {
#pragma unroll
            for (int it = 0; it < 4; it++)
                pa[it] = *reinterpret_cast<const float4*>(Ab + (size_t)ar[it]*lda + kb+32 + ac[it]);
#pragma unroll
            for (int it = 0; it < 2; it++) {
                cpa16(&BH(nb)[bk_[it]*GB_RS + bc_[it]], &Wh[(size_t)(kb+32+bk_[it])*N + bn + bc_[it]]);
                cpa16(&BL(nb)[bk_[it]*GB_RS + bc_[it]], &Wl[(size_t)(kb+32+bk_[it])*N + bn + bc_[it]]);
            }
            CP_COMMIT();
        }
        u16* cAh = AH(buf); u16* cAl = AL(buf);
        u16* cBh = BH(buf); u16* cBl = BL(buf);
#pragma unroll
        for (int ks = 0; ks < 32; ks += 16) {
            u32 bhf[4][2], blf[4][2];
#pragma unroll
            for (int nf = 0; nf < 4; nf++) {
                int n  = wn*32 + nf*8 + (lane >> 2);
                int k0 = ks + (lane & 3)*2;
                bhf[nf][0] = pk(cBh[k0*GB_RS+n],     cBh[(k0+1)*GB_RS+n]);
                bhf[nf][1] = pk(cBh[(k0+8)*GB_RS+n], cBh[(k0+9)*GB_RS+n]);
                blf[nf][0] = pk(cBl[k0*GB_RS+n],     cBl[(k0+1)*GB_RS+n]);
                blf[nf][1] = pk(cBl[(k0+8)*GB_RS+n], cBl[(k0+9)*GB_RS+n]);
            }
#pragma unroll
            for (int mf = 0; mf < 4; mf++) {
                int r = wm*64 + mf*16 + (lane >> 2);
                int c = ks + (lane & 3)*2;
                u32 ah0 = *reinterpret_cast<u32*>(&cAh[r*GA_RS + c]);
                u32 ah1 = *reinterpret_cast<u32*>(&cAh[(r+8)*GA_RS + c]);
                u32 ah2 = *reinterpret_cast<u32*>(&cAh[r*GA_RS + c + 8]);
                u32 ah3 = *reinterpret_cast<u32*>(&cAh[(r+8)*GA_RS + c + 8]);
                u32 al0 = *reinterpret_cast<u32*>(&cAl[r*GA_RS + c]);
                u32 al1 = *reinterpret_cast<u32*>(&cAl[(r+8)*GA_RS + c]);
                u32 al2 = *reinterpret_cast<u32*>(&cAl[r*GA_RS + c + 8]);
                u32 al3 = *reinterpret_cast<u32*>(&cAl[(r+8)*GA_RS + c + 8]);
#pragma unroll
                for (int nf = 0; nf < 4; nf++) {
                    mma_bf16(acc[mf][nf], ah0,ah1,ah2,ah3, bhf[nf][0], bhf[nf][1]);
                    mma_bf16(acc[mf][nf], ah0,ah1,ah2,ah3, blf[nf][0], blf[nf][1]);
                    mma_bf16(acc[mf][nf], al0,al1,al2,al3, bhf[nf][0], bhf[nf][1]);
                }
            }
        }
        if (more) {
            u16* nAh = AH(nb); u16* nAl = AL(nb);
#pragma unroll
            for (int it = 0; it < 4; it++) {
                u16 h0,l0,h1,l1,h2,l2,h3,l3;
                bsplit(pa[it].x,h0,l0); bsplit(pa[it].y,h1,l1);
                bsplit(pa[it].z,h2,l2); bsplit(pa[it].w,h3,l3);
                *reinterpret_cast<u32*>(&nAh[ar[it]*GA_RS + ac[it]])     = pk(h0,h1);
                *reinterpret_cast<u32*>(&nAh[ar[it]*GA_RS + ac[it] + 2]) = pk(h2,h3);
                *reinterpret_cast<u32*>(&nAl[ar[it]*GA_RS + ac[it]])     = pk(l0,l1);
                *reinterpret_cast<u32*>(&nAl[ar[it]*GA_RS + ac[it] + 2]) = pk(l2,l3);
            }
            CP_WAIT0();
        }
        __syncthreads();
        buf = nb;
    }
#undef AH
#undef AL
#undef BH
#undef BL

#pragma unroll
    for (int mf = 0; mf < 4; mf++) {
#pragma unroll
        for (int nf = 0; nf < 4; nf++) {
            int r = bm + wm*64 + mf*16 + (lane >> 2);
            int c = bn + wn*32 + nf*8 + (lane & 3)*2;
            float b0 = bias[c], b1 = bias[c+1];
            float v0 = acc[mf][nf][0] + b0, v1 = acc[mf][nf][1] + b1;
            float v2 = acc[mf][nf][2] + b0, v3 = acc[mf][nf][3] + b1;
            if (relu) { v0=fmaxf(v0,0.f); v1=fmaxf(v1,0.f); v2=fmaxf(v2,0.f); v3=fmaxf(v3,0.f); }
            if (mode == 0) {
                *reinterpret_cast<float2*>(&Cf[(size_t)r*N + c])     = make_float2(v0, v1);
                *reinterpret_cast<float2*>(&Cf[(size_t)(r+8)*N + c]) = make_float2(v2, v3);
            } else {
                u16 h0,l0,h1,l1,h2,l2,h3,l3;
                if (mode == 1) { bsplit(v0,h0,l0); bsplit(v1,h1,l1); bsplit(v2,h2,l2); bsplit(v3,h3,l3); }
                else           { hsplit(v0,h0,l0); hsplit(v1,h1,l1); hsplit(v2,h2,l2); hsplit(v3,h3,l3); }
                *reinterpret_cast<u32*>(&Ch[(size_t)r*N + c])     = pk(h0,h1);
                *reinterpret_cast<u32*>(&Cl[(size_t)r*N + c])     = pk(l0,l1);
                *reinterpret_cast<u32*>(&Ch[(size_t)(r+8)*N + c]) = pk(h2,h3);
                *reinterpret_cast<u32*>(&Cl[(size_t)(r+8)*N + c]) = pk(l2,l3);
            }
        }
    }
}

__global__ __launch_bounds__(256, 2)
void gemm_ts(const float* __restrict__ A, int lda, int aoff,
             const u16* __restrict__ Wh, const u16* __restrict__ Wl,
             const float* __restrict__ bias,
             float* __restrict__ Cf, u16* __restrict__ Ch, u16* __restrict__ Cl,
             int N, int K, int relu, int mode)
{
    extern __shared__ u16 smg[];
    int bm = blockIdx.y*128, bn = blockIdx.x*128;
    gemm_body(A + (size_t)bm*lda + aoff, lda, Wh, Wl, bias,
              Cf, Ch, Cl, N, K, bm, bn, relu, mode, smg);
}

__global__ __launch_bounds__(256, 2)
void qkv_gemm_ts(const float* __restrict__ A,
                 const float* __restrict__ bq, const float* __restrict__ bk,
                 const float* __restrict__ bv)
{
    extern __shared__ u16 smg[];
    int grp = blockIdx.x / 6;
    int bxl = blockIdx.x - grp*6;
    int bm = blockIdx.y*128, bn = bxl*128;
    const u16* Wh = g_Wh + grp*196608;
    const u16* Wl = g_Wl + grp*196608;
    const float* bias = (grp == 0) ? bq : (grp == 1) ? bk : bv;
    u16* Ch = (grp == 0) ? g_qh : (grp == 1) ? g_kh : g_vh;
    u16* Cl = (grp == 0) ? g_ql : (grp == 1) ? g_kl : g_vl;
    int mode = (grp == 2) ? 2 : 1;
    int aoff = grp*256;
    gemm_body(A + (size_t)bm*DIM + aoff, DIM, Wh, Wl, bias,
              nullptr, Ch, Cl, DIM, 256, bm, bn, 1, mode, smg);
}

// ---------------- fused flash attention: K/V double-buffered, cp.async prefetch ----------------
#define FA_RS 72
#define FA_SMEM ((2*128*FA_RS + 2*4*64*FA_RS) * 2)   // 110592 bytes
__global__ __launch_bounds__(256, 2)
void fused_attn(const u16* __restrict__ Qhg, const u16* __restrict__ Qlg,
                const u16* __restrict__ Khg, const u16* __restrict__ Klg,
                const u16* __restrict__ Vhg, const u16* __restrict__ Vlg,
                float* __restrict__ Of, float scale)
{
    extern __shared__ u16 sm[];
    u16* Qh = sm;
    u16* Ql = Qh + 128*FA_RS;
    u16* KVb = sm + 2*128*FA_RS;          // 2 bufs x [Kh,Kl,Vh,Vl] each 64*FA_RS
#define KH(b) (KVb + (b)*(4*64*FA_RS))
#define KL(b) (KVb + (b)*(4*64*FA_RS) + 64*FA_RS)
#define VH(b) (KVb + (b)*(4*64*FA_RS) + 2*64*FA_RS)
#define VL(b) (KVb + (b)*(4*64*FA_RS) + 3*64*FA_RS)

    int bh = blockIdx.z;
    int b = bh / NH, h = bh - b*NH;
    int tid = threadIdx.x, lane = tid & 31, w = tid >> 5;
    size_t base = ((size_t)b*SEQ)*DIM + h*HD;
    int q0 = blockIdx.x * 128;
    const float cfac = scale * 1.4426950408889634f;

    int kr[2], kc[2];
#pragma unroll
    for (int it = 0; it < 2; it++) {
        int idx = it*256 + tid;
        kr[it] = idx >> 3; kc[it] = (idx & 7) * 8;
    }

    // prologue: cp.async K/V tile 0 into buf 0, overlap with Q load
#pragma unroll
    for (int it = 0; it < 2; it++) {
        size_t g = base + (size_t)kr[it]*DIM + kc[it];
        cpa16(&KH(0)[kr[it]*FA_RS + kc[it]], Khg + g);
        cpa16(&KL(0)[kr[it]*FA_RS + kc[it]], Klg + g);
        cpa16(&VH(0)[kr[it]*FA_RS + kc[it]], Vhg + g);
        cpa16(&VL(0)[kr[it]*FA_RS + kc[it]], Vlg + g);
    }
    CP_COMMIT();
#pragma unroll
    for (int it = 0; it < 4; it++) {
        int idx = it*256 + tid;
        int r = idx >> 3, c8 = (idx & 7) * 8;
        *reinterpret_cast<uint4*>(&Qh[r*FA_RS + c8]) =
            *reinterpret_cast<const uint4*>(Qhg + base + (size_t)(q0+r)*DIM + c8);
        *reinterpret_cast<uint4*>(&Ql[r*FA_RS + c8]) =
            *reinterpret_cast<const uint4*>(Qlg + base + (size_t)(q0+r)*DIM + c8);
    }
    CP_WAIT0();
    __syncthreads();

    float o[8][4];
#pragma unroll
    for (int i=0;i<8;i++)
#pragma unroll
        for (int j=0;j<4;j++) o[i][j]=0.f;
    float m_lo = -1e30f, m_hi = -1e30f, l_lo = 0.f, l_hi = 0.f;

    int rq = w*16 + (lane >> 2);
    int buf = 0;

    for (int t0 = 0; t0 < SEQ; t0 += 64) {
        bool more = (t0 + 64) < SEQ;
        int nb = buf ^ 1;
        if (more) {
#pragma unroll
            for (int it = 0; it < 2; it++) {
                size_t g = base + (size_t)(t0+64+kr[it])*DIM + kc[it];
                cpa16(&KH(nb)[kr[it]*FA_RS + kc[it]], Khg + g);
                cpa16(&KL(nb)[kr[it]*FA_RS + kc[it]], Klg + g);
                cpa16(&VH(nb)[kr[it]*FA_RS + kc[it]], Vhg + g);
                cpa16(&VL(nb)[kr[it]*FA_RS + kc[it]], Vlg + g);
            }
            CP_COMMIT();
        }
        u16* cKh = KH(buf); u16* cKl = KL(buf);
        u16* cVh = VH(buf); u16* cVl = VL(buf);

        float sacc[8][4];
#pragma unroll
        for (int i=0;i<8;i++)
#pragma unroll
            for (int j=0;j<4;j++) sacc[i][j]=0.f;
#pragma unroll
        for (int ks = 0; ks < 4; ks++) {
            int c = ks*16 + (lane & 3)*2;
            u32 ah0 = *reinterpret_cast<u32*>(&Qh[rq*FA_RS + c]);
            u32 ah1 = *reinterpret_cast<u32*>(&Qh[(rq+8)*FA_RS + c]);
            u32 ah2 = *reinterpret_cast<u32*>(&Qh[rq*FA_RS + c + 8]);
            u32 ah3 = *reinterpret_cast<u32*>(&Qh[(rq+8)*FA_RS + c + 8]);
            u32 al0 = *reinterpret_cast<u32*>(&Ql[rq*FA_RS + c]);
            u32 al1 = *reinterpret_cast<u32*>(&Ql[(rq+8)*FA_RS + c]);
            u32 al2 = *reinterpret_cast<u32*>(&Ql[rq*FA_RS + c + 8]);
            u32 al3 = *reinterpret_cast<u32*>(&Ql[(rq+8)*FA_RS + c + 8]);
#pragma unroll
            for (int nf = 0; nf < 8; nf++) {
                int n = nf*8 + (lane >> 2);
                u32 bh0 = *reinterpret_cast<u32*>(&cKh[n*FA_RS + c]);
                u32 bh1 = *reinterpret_cast<u32*>(&cKh[n*FA_RS + c + 8]);
                u32 bl0 = *reinterpret_cast<u32*>(&cKl[n*FA_RS + c]);
                u32 bl1 = *reinterpret_cast<u32*>(&cKl[n*FA_RS + c + 8]);
                mma_bf16(sacc[nf], ah0,ah1,ah2,ah3, bh0,bh1);
                mma_bf16(sacc[nf], ah0,ah1,ah2,ah3, bl0,bl1);
                mma_bf16(sacc[nf], al0,al1,al2,al3, bh0,bh1);
            }
        }

        float tm_lo = -1e30f, tm_hi = -1e30f;
#pragma unroll
        for (int nf = 0; nf < 8; nf++) {
            tm_lo = fmaxf(tm_lo, fmaxf(sacc[nf][0], sacc[nf][1]));
            tm_hi = fmaxf(tm_hi, fmaxf(sacc[nf][2], sacc[nf][3]));
        }
        tm_lo = fmaxf(tm_lo, __shfl_xor_sync(0xffffffffu, tm_lo, 1));
        tm_lo = fmaxf(tm_lo, __shfl_xor_sync(0xffffffffu, tm_lo, 2));
        tm_hi = fmaxf(tm_hi, __shfl_xor_sync(0xffffffffu, tm_hi, 1));
        tm_hi = fmaxf(tm_hi, __shfl_xor_sync(0xffffffffu, tm_hi, 2));
        float mn_lo = fmaxf(m_lo, tm_lo), mn_hi = fmaxf(m_hi, tm_hi);
        float f_lo = fexp(m_lo - mn_lo, cfac), f_hi = fexp(m_hi - mn_hi, cfac);
        m_lo = mn_lo; m_hi = mn_hi;

        float ts_lo = 0.f, ts_hi = 0.f;
        u32 plo[8], phi[8];
#pragma unroll
        for (int nf = 0; nf < 8; nf++) {
            float p0 = fexp(sacc[nf][0] - mn_lo, cfac);
            float p1 = fexp(sacc[nf][1] - mn_lo, cfac);
            float p2 = fexp(sacc[nf][2] - mn_hi, cfac);
            float p3 = fexp(sacc[nf][3] - mn_hi, cfac);
            ts_lo += p0 + p1; ts_hi += p2 + p3;
            __half2 hl = __floats2half2_rn(p0, p1);
            __half2 hh = __floats2half2_rn(p2, p3);
            plo[nf] = *reinterpret_cast<u32*>(&hl);
            phi[nf] = *reinterpret_cast<u32*>(&hh);
        }
        ts_lo += __shfl_xor_sync(0xffffffffu, ts_lo, 1);
        ts_lo += __shfl_xor_sync(0xffffffffu, ts_lo, 2);
        ts_hi += __shfl_xor_sync(0xffffffffu, ts_hi, 1);
        ts_hi += __shfl_xor_sync(0xffffffffu, ts_hi, 2);
        l_lo = l_lo * f_lo + ts_lo;
        l_hi = l_hi * f_hi + ts_hi;

#pragma unroll
        for (int ef = 0; ef < 8; ef++) {
            o[ef][0] *= f_lo; o[ef][1] *= f_lo;
            o[ef][2] *= f_hi; o[ef][3] *= f_hi;
        }

#pragma unroll
        for (int ks = 0; ks < 4; ks++) {
            int k0 = ks*16 + (lane & 3)*2;
            u32 a0 = plo[2*ks], a1 = phi[2*ks], a2 = plo[2*ks+1], a3 = phi[2*ks+1];
#pragma unroll
            for (int ef = 0; ef < 8; ef++) {
                int e = ef*8 + (lane >> 2);
                u32 b0h = pk(cVh[k0*FA_RS+e],     cVh[(k0+1)*FA_RS+e]);
                u32 b1h = pk(cVh[(k0+8)*FA_RS+e], cVh[(k0+9)*FA_RS+e]);
                u32 b0l = pk(cVl[k0*FA_RS+e],     cVl[(k0+1)*FA_RS+e]);
                u32 b1l = pk(cVl[(k0+8)*FA_RS+e], cVl[(k0+9)*FA_RS+e]);
                mma_f16(o[ef], a0,a1,a2,a3, b0h,b1h);
                mma_f16(o[ef], a0,a1,a2,a3, b0l,b1l);
            }
        }
        if (more) CP_WAIT0();
        __syncthreads();
        buf = nb;
    }
#undef KH
#undef KL
#undef VH
#undef VL

    float il_lo = 1.0f / l_lo, il_hi = 1.0f / l_hi;
    size_t row = (size_t)b*SEQ + q0 + rq;
#pragma unroll
    for (int ef = 0; ef < 8; ef++) {
        int col = h*HD + ef*8 + (lane & 3)*2;
        *reinterpret_cast<float2*>(&Of[row*DIM + col]) =
            make_float2(o[ef][0]*il_lo, o[ef][1]*il_lo);
        *reinterpret_cast<float2*>(&Of[(row+8)*DIM + col]) =
            make_float2(o[ef][2]*il_hi, o[ef][3]*il_hi);
    }
}

// ---------------- batch norm ----------------
__global__ __launch_bounds__(256)
void bn_stats(const float* __restrict__ X, const float* __restrict__ Y)
{
    int f  = blockIdx.x*32 + threadIdx.x;
    int rb = blockIdx.y*512;
    float s = 0.0f, s2 = 0.0f;
    for (int r = rb + threadIdx.y; r < rb + 512; r += 8) {
        size_t idx = (size_t)r*DIM + f;
        float v = X[idx] + Y[idx];
        s += v; s2 = fmaf(v, v, s2);
    }
    __shared__ double sh[2][8][32];
    sh[0][threadIdx.y][threadIdx.x] = (double)s;
    sh[1][threadIdx.y][threadIdx.x] = (double)s2;
    __syncthreads();
    if (threadIdx.y == 0) {
        double ts = 0.0, ts2 = 0.0;
#pragma unroll
        for (int i = 0; i < 8; i++) { ts += sh[0][i][threadIdx.x]; ts2 += sh[1][i][threadIdx.x]; }
        g_psum [blockIdx.y][f] = ts;
        g_psum2[blockIdx.y][f] = ts2;
    }
}

__global__ void bn_finalize(const float* __restrict__ g, const float* __restrict__ b)
{
    int f = blockIdx.x*256 + threadIdx.x;
    if (f >= DIM) return;
    double s = 0.0, s2 = 0.0;
#pragma unroll
    for (int i = 0; i < 8; i++) { s += g_psum[i][f]; s2 += g_psum2[i][f]; }
    double mu  = s  * (1.0 / ROWS);
    double var = s2 * (1.0 / ROWS) - mu*mu;
    float rstd = (float)(1.0 / sqrt(var + 1e-5));
    float sc = g[f] * rstd;
    g_bnsc[f] = sc;
    g_bnsh[f] = b[f] - (float)mu * sc;
}

__global__ __launch_bounds__(256)
void bn_apply2(const float* __restrict__ X, const float* __restrict__ Y,
               float* __restrict__ O)
{
    int idx4 = blockIdx.x*256 + threadIdx.x;
    if (idx4 >= ROWS*DIM/4) return;
    int f = (idx4*4) % DIM;
    float4 x = *reinterpret_cast<const float4*>(&X[(size_t)idx4*4]);
    float4 y = *reinterpret_cast<const float4*>(&Y[(size_t)idx4*4]);
    float4 o;
    o.x = fmaf(x.x + y.x, g_bnsc[f+0], g_bnsh[f+0]);
    o.y = fmaf(x.y + y.y, g_bnsc[f+1], g_bnsh[f+1]);
    o.z = fmaf(x.z + y.z, g_bnsc[f+2], g_bnsh[f+2]);
    o.w = fmaf(x.w + y.w, g_bnsc[f+3], g_bnsh[f+3]);
    *reinterpret_cast<float4*>(&O[(size_t)idx4*4]) = o;
}

// ---------------- launch ----------------
static float* sym(const void* s)
{
    void* p = nullptr;
    cudaGetSymbolAddress(&p, s);
    return (float*)p;
}

extern "C" void kernel_launch(void* const* d_in, const int* in_sizes, int n_in,
                              void* d_out, int out_size)
{
    const int*   x     = (const int*)  d_in[0];
    const float* encod = (const float*)d_in[1];
    const float* embed = (const float*)d_in[2];
    const float* Wq  = (const float*)d_in[3];  const float* bq  = (const float*)d_in[4];
    const float* Wk  = (const float*)d_in[5];  const float* bk  = (const float*)d_in[6];
    const float* Wv  = (const float*)d_in[7];  const float* bv  = (const float*)d_in[8];
    const float* g1  = (const float*)d_in[9];  const float* b1  = (const float*)d_in[10];
    const float* Wq2 = (const float*)d_in[11]; const float* bq2 = (const float*)d_in[12];
    const float* Wk2 = (const float*)d_in[13]; const float* bk2 = (const float*)d_in[14];
    const float* Wv2 = (const float*)d_in[15]; const float* bv2 = (const float*)d_in[16];
    const float* Wo2 = (const float*)d_in[17]; const float* bo2 = (const float*)d_in[18];
    const float* g2  = (const float*)d_in[19]; const float* b2  = (const float*)d_in[20];
    const float* Wf  = (const float*)d_in[21]; const float* bf  = (const float*)d_in[22];
    float* out = (float*)d_out;

    float *im = sym(g_im), *sa = sym(g_sa), *t1 = sym(g_t1), *av = sym(g_av);
    float *m2 = sym(g_m2), *t2 = sym(g_t2), *ff = sym(g_ff);
    u16 *qh = (u16*)sym(g_qh), *ql = (u16*)sym(g_ql);
    u16 *kh = (u16*)sym(g_kh), *kl = (u16*)sym(g_kl);
    u16 *vh = (u16*)sym(g_vh), *vl = (u16*)sym(g_vl);
    u16 *q2h = (u16*)sym(g_q2h), *q2l = (u16*)sym(g_q2l);
    u16 *k2h = (u16*)sym(g_k2h), *k2l = (u16*)sym(g_k2l);
    u16 *v2h = (u16*)sym(g_v2h), *v2l = (u16*)sym(g_v2l);
    u16 *wh = (u16*)sym(g_Wh), *wl = (u16*)sym(g_Wl);

    cudaFuncSetAttribute(fused_attn,  cudaFuncAttributeMaxDynamicSharedMemorySize, FA_SMEM);
    cudaFuncSetAttribute(gemm_ts,     cudaFuncAttributeMaxDynamicSharedMemorySize, GEMM_SMEM);
    cudaFuncSetAttribute(qkv_gemm_ts, cudaFuncAttributeMaxDynamicSharedMemorySize, GEMM_SMEM);

    const float scale1 = 1.0f / sqrtf((float)DIM);
    const float scale2 = 1.0f / sqrtf((float)HD);

    dim3 gemmGrid(DIM/128, ROWS/128);      // (6, 32)
    dim3 qkvGrid(3*DIM/128, ROWS/128);     // (18, 32)
    dim3 faGrid(SEQ/128, 1, NBH);          // (8, 1, 48)
    dim3 bnGrid(DIM/32, 8);
    dim3 bnBlk(32, 8);
    int ew4Blocks = (ROWS*DIM/4 + 255)/256;

    pe_table_kernel<<<(SEQ*DIM/2 + 255)/256, 256>>>();
    allsplit_kernel<<<(WSP_TOT + 255)/256, 256>>>(Wq, Wk, Wv, Wq2, Wk2, Wv2, Wo2, Wf);

    embed_pos_kernel<<<ew4Blocks, 256>>>(x, embed, im);

    gemm_ts<<<gemmGrid, 256, GEMM_SMEM>>>(encod, DIM, 0,   wh+OFF_Q2, wl+OFF_Q2, bq2,
                                          nullptr, q2h, q2l, DIM, DIM/2, 0, 1);
    gemm_ts<<<gemmGrid, 256, GEMM_SMEM>>>(encod, DIM, 384, wh+OFF_K2, wl+OFF_K2, bk2,
                                          nullptr, k2h, k2l, DIM, DIM/2, 0, 1);

    for (int li = 0; li < NITER; li++) {
        qkv_gemm_ts<<<qkvGrid, 256, GEMM_SMEM>>>(im, bq, bk, bv);
        fused_attn<<<faGrid, 256, FA_SMEM>>>(qh, ql, kh, kl, vh, vl, sa, scale1);

        bn_stats<<<bnGrid, bnBlk>>>(im, sa);
        bn_finalize<<<3, 256>>>(g1, b1);
        bn_apply2<<<ew4Blocks, 256>>>(im, sa, t1);

        gemm_ts<<<gemmGrid, 256, GEMM_SMEM>>>(t1, DIM, 0, wh+OFF_V2, wl+OFF_V2, bv2,
                                              nullptr, v2h, v2l, DIM, DIM, 0, 2);
        fused_attn<<<faGrid, 256, FA_SMEM>>>(q2h, q2l, k2h, k2l, v2h, v2l, av, scale2);
        gemm_ts<<<gemmGrid, 256, GEMM_SMEM>>>(av, DIM, 0, wh+OFF_O2, wl+OFF_O2, bo2,
                                              m2, nullptr, nullptr, DIM, DIM, 0, 0);

        bn_stats<<<bnGrid, bnBlk>>>(m2, t1);
        bn_finalize<<<3, 256>>>(g2, b2);
        bn_apply2<<<ew4Blocks, 256>>>(m2, t1, t2);

        gemm_ts<<<gemmGrid, 256, GEMM_SMEM>>>(t2, DIM, 0, wh+OFF_F, wl+OFF_F, bf,
                                              ff, nullptr, nullptr, DIM, DIM, 0, 0);
        bn_stats<<<bnGrid, bnBlk>>>(t2, ff);
        bn_finalize<<<3, 256>>>(g2, b2);
        bn_apply2<<<ew4Blocks, 256>>>(t2, ff, im);
    }

    cudaMemcpyAsync(out, im, (size_t)ROWS*DIM*sizeof(float),
                    cudaMemcpyDeviceToDevice);
}

// round 14
// speedup vs baseline: 1.0682x; 1.0259x over previous
#include <cuda_runtime.h>
#include <cuda_bf16.h>
#include <cuda_fp16.h>
#include <math.h>

#define BSZ   4
#define SEQ   1024
#define DIM   768
#define NH    12
#define HD    64
#define ROWS  (BSZ*SEQ)      // 4096
#define NBH   (BSZ*NH)       // 48
#define NITER 2

typedef unsigned short u16;
typedef unsigned int   u32;

// weight-split offsets (elements)
#define OFF_Q   0
#define OFF_K   196608
#define OFF_V   393216
#define OFF_Q2  589824
#define OFF_K2  884736
#define OFF_V2  1179648
#define OFF_O2  1769472
#define OFF_F   2359296
#define WSP_TOT 2949120

// ---------------- static scratch (no allocations allowed) ----------------
__device__ float g_im [ROWS*DIM];
__device__ float g_sa [ROWS*DIM];
__device__ float g_t1 [ROWS*DIM];
__device__ float g_av [ROWS*DIM];
__device__ float g_m2 [ROWS*DIM];
__device__ float g_t2 [ROWS*DIM];
__device__ float g_ff [ROWS*DIM];
__device__ float g_pe [SEQ*DIM];
__device__ u16 g_qh [ROWS*DIM], g_ql [ROWS*DIM];
__device__ u16 g_kh [ROWS*DIM], g_kl [ROWS*DIM];
__device__ u16 g_vh [ROWS*DIM], g_vl [ROWS*DIM];   // fp16 split
__device__ u16 g_q2h[ROWS*DIM], g_q2l[ROWS*DIM];
__device__ u16 g_k2h[ROWS*DIM], g_k2l[ROWS*DIM];
__device__ u16 g_v2h[ROWS*DIM], g_v2l[ROWS*DIM];   // fp16 split
__device__ u16 g_Wh[WSP_TOT], g_Wl[WSP_TOT];
__device__ double g_psum [8][DIM];
__device__ double g_psum2[8][DIM];
__device__ float  g_bnsc[DIM];
__device__ float  g_bnsh[DIM];

// ---------------- helpers ----------------
__device__ __forceinline__ void bsplit(float x, u16& h, u16& l)
{
    __nv_bfloat16 bh = __float2bfloat16(x);
    h = __bfloat16_as_ushort(bh);
    l = __bfloat16_as_ushort(__float2bfloat16(x - __bfloat162float(bh)));
}
__device__ __forceinline__ void hsplit(float x, u16& h, u16& l)
{
    __half hh = __float2half_rn(x);
    h = __half_as_ushort(hh);
    l = __half_as_ushort(__float2half_rn(x - __half2float(hh)));
}
__device__ __forceinline__ u32 pk(u16 a, u16 b) { return (u32)a | ((u32)b << 16); }

__device__ __forceinline__ void cpa16(void* dst_smem, const void* src)
{
    u32 d = (u32)__cvta_generic_to_shared(dst_smem);
    asm volatile("cp.async.cg.shared.global [%0], [%1], 16;" :: "r"(d), "l"(src));
}
#define CP_COMMIT() asm volatile("cp.async.commit_group;" ::: "memory")
#define CP_WAIT0()  asm volatile("cp.async.wait_group 0;" ::: "memory")

__device__ __forceinline__ void mma_bf16(float d[4], u32 a0, u32 a1, u32 a2, u32 a3,
                                         u32 b0, u32 b1)
{
    asm volatile(
        "mma.sync.aligned.m16n8k16.row.col.f32.bf16.bf16.f32 "
        "{%0,%1,%2,%3}, {%4,%5,%6,%7}, {%8,%9}, {%0,%1,%2,%3};\n"
        : "+f"(d[0]), "+f"(d[1]), "+f"(d[2]), "+f"(d[3])
        : "r"(a0), "r"(a1), "r"(a2), "r"(a3), "r"(b0), "r"(b1));
}
__device__ __forceinline__ void mma_f16(float d[4], u32 a0, u32 a1, u32 a2, u32 a3,
                                        u32 b0, u32 b1)
{
    asm volatile(
        "mma.sync.aligned.m16n8k16.row.col.f32.f16.f16.f32 "
        "{%0,%1,%2,%3}, {%4,%5,%6,%7}, {%8,%9}, {%0,%1,%2,%3};\n"
        : "+f"(d[0]), "+f"(d[1]), "+f"(d[2]), "+f"(d[3])
        : "r"(a0), "r"(a1), "r"(a2), "r"(a3), "r"(b0), "r"(b1));
}

// fast exp with folded factor c (= k*log2e)
__device__ __forceinline__ float fexp(float x, float c)
{
    float t = fmaxf(x * c, -120.0f);
    float r = t + 12582912.0f;
    float nf = r - 12582912.0f;
    float f = t - nf;
    float p = 1.3333558146e-3f;
    p = fmaf(p, f, 9.6181291077e-3f);
    p = fmaf(p, f, 5.5504108664e-2f);
    p = fmaf(p, f, 2.4022650695e-1f);
    p = fmaf(p, f, 6.9314718056e-1f);
    p = fmaf(p, f, 1.0f);
    int n = __float_as_int(r) - 0x4B400000;
    return __int_as_float(__float_as_int(p) + (n << 23));
}

// ---------------- one-time: PE table ----------------
__global__ void pe_table_kernel()
{
    int idx2 = blockIdx.x*256 + threadIdx.x;
    if (idx2 >= SEQ*DIM/2) return;
    int s = idx2 / (DIM/2), d2 = idx2 - s*(DIM/2);
    float inv = exp2f((float)d2 * (-13.287712379549449f * 2.0f / (float)DIM));
    float ang = (float)s * inv;
    g_pe[(size_t)s*DIM + 2*d2]     = sinf(ang);
    g_pe[(size_t)s*DIM + 2*d2 + 1] = cosf(ang);
}

// ---------------- one-time: weight splits ----------------
__global__ void allsplit_kernel(const float* __restrict__ p0, const float* __restrict__ p1,
                                const float* __restrict__ p2, const float* __restrict__ p3,
                                const float* __restrict__ p4, const float* __restrict__ p5,
                                const float* __restrict__ p6, const float* __restrict__ p7)
{
    int i = blockIdx.x*256 + threadIdx.x;
    if (i >= WSP_TOT) return;
    const float* p; int j;
    if      (i < OFF_K)  { p = p0; j = i; }
    else if (i < OFF_V)  { p = p1; j = i - OFF_K; }
    else if (i < OFF_Q2) { p = p2; j = i - OFF_V; }
    else if (i < OFF_K2) { p = p3; j = i - OFF_Q2; }
    else if (i < OFF_V2) { p = p4; j = i - OFF_K2; }
    else if (i < OFF_O2) { p = p5; j = i - OFF_V2; }
    else if (i < OFF_F)  { p = p6; j = i - OFF_O2; }
    else                 { p = p7; j = i - OFF_F; }
    u16 h, l;
    bsplit(p[j], h, l);
    g_Wh[i] = h;
    g_Wl[i] = l;
}

// ---------------- embedding + PE ----------------
__global__ void embed_pos_kernel(const int* __restrict__ x,
                                 const float* __restrict__ embed,
                                 float* __restrict__ out)
{
    int idx4 = blockIdx.x * 256 + threadIdx.x;
    if (idx4 >= ROWS*DIM/4) return;
    int r = idx4 / (DIM/4), d = (idx4 - r*(DIM/4))*4;
    int s = r & (SEQ-1);
    int tok = x[r];
    float4 e = *reinterpret_cast<const float4*>(&embed[(size_t)tok*DIM + d]);
    float4 p = *reinterpret_cast<const float4*>(&g_pe[(size_t)s*DIM + d]);
    float4 o;
    o.x = fmaf(2.0f, e.x, p.x); o.y = fmaf(2.0f, e.y, p.y);
    o.z = fmaf(2.0f, e.z, p.z); o.w = fmaf(2.0f, e.w, p.w);
    *reinterpret_cast<float4*>(&out[(size_t)idx4*4]) = o;
}

// ---------------- GEMM: 64x128 tile, 3 CTAs/SM, term-major mma order ----------------
// out modes: 0 = fp32, 1 = bf16 split, 2 = fp16 split
#define GA_RS 40
#define GB_RS 136
#define GEMM_SMEM ((4*64*GA_RS + 4*32*GB_RS) * 2)   // 55296 bytes
__device__ __forceinline__ void gemm_body(
    const float* __restrict__ Ab, int lda,
    const u16* __restrict__ Wh, const u16* __restrict__ Wl,
    const float* __restrict__ bias,
    float* __restrict__ Cf, u16* __restrict__ Ch, u16* __restrict__ Cl,
    int N, int K, int bm, int bn, int relu, int mode, u16* sm)
{
    int tid = threadIdx.x;
    int lane = tid & 31, wid = tid >> 5;
    int wm = wid & 1, wn = wid >> 1;      // 2 m-warps x 4 n-warps, warp tile 32x32

    u16* Bbase = sm + 4*64*GA_RS;
#define AH(b) (sm + (b)*(2*64*GA_RS))
#define AL(b) (sm + (b)*(2*64*GA_RS) + 64*GA_RS)
#define BH(b) (Bbase + (b)*(2*32*GB_RS))
#define BL(b) (Bbase + (b)*(2*32*GB_RS) + 32*GB_RS)

    // loader coords: A 64x32 = 512 float4 -> 2/thread; B 32x128 u16 = 512 uint4/array -> 2/thread
    int ar[2], ac[2], bk_[2], bc_[2];
#pragma unroll
    for (int it = 0; it < 2; it++) {
        int idx = it*256 + tid;
        ar[it] = idx >> 3;  ac[it] = (idx & 7) * 4;
        bk_[it] = idx >> 4; bc_[it] = (idx & 15) * 8;
    }

    float acc[2][4][4];
#pragma unroll
    for (int i=0;i<2;i++)
#pragma unroll
        for (int j=0;j<4;j++)
#pragma unroll
            for (int q=0;q<4;q++) acc[i][j][q]=0.f;

    // prologue
    {
        float4 pa[2];
#pragma unroll
        for (int it = 0; it < 2; it++)
            pa[it] = *reinterpret_cast<const float4*>(Ab + (size_t)ar[it]*lda + ac[it]);
#pragma unroll
        for (int it = 0; it < 2; it++) {
            u16 h0,l0,h1,l1,h2,l2,h3,l3;
            bsplit(pa[it].x,h0,l0); bsplit(pa[it].y,h1,l1);
            bsplit(pa[it].z,h2,l2); bsplit(pa[it].w,h3,l3);
            *reinterpret_cast<u32*>(&AH(0)[ar[it]*GA_RS + ac[it]])     = pk(h0,h1);
            *reinterpret_cast<u32*>(&AH(0)[ar[it]*GA_RS + ac[it] + 2]) = pk(h2,h3);
            *reinterpret_cast<u32*>(&AL(0)[ar[it]*GA_RS + ac[it]])     = pk(l0,l1);
            *reinterpret_cast<u32*>(&AL(0)[ar[it]*GA_RS + ac[it] + 2]) = pk(l2,l3);
        }
#pragma unroll
        for (int it = 0; it < 2; it++) {
            cpa16(&BH(0)[bk_[it]*GB_RS + bc_[it]], &Wh[(size_t)bk_[it]*N + bn + bc_[it]]);
            cpa16(&BL(0)[bk_[it]*GB_RS + bc_[it]], &Wl[(size_t)bk_[it]*N + bn + bc_[it]]);
        }
        CP_COMMIT();
        CP_WAIT0();
        __syncthreads();
    }

    int buf = 0;
    for (int kb = 0; kb < K; kb += 32) {
        bool more = (kb + 32) < K;
        int nb = buf ^ 1;
        float4 pa[2];
        if (more) {
#pragma unroll
            for (int it = 0; it < 2; it++)
                pa[it] = *reinterpret_cast<const float4*>(Ab + (size_t)ar[it]*lda + kb+32 + ac[it]);
#pragma unroll
            for (int it = 0; it < 2; it++) {
                cpa16(&BH(nb)[bk_[it]*GB_RS + bc_[it]], &Wh[(size_t)(kb+32+bk_[it])*N + bn + bc_[it]]);
                cpa16(&BL(nb)[bk_[it]*GB_RS + bc_[it]], &Wl[(size_t)(kb+32+bk_[it])*N + bn + bc_[it]]);
            }
            CP_COMMIT();
        }
        u16* cAh = AH(buf); u16* cAl = AL(buf);
        u16* cBh = BH(buf); u16* cBl = BL(buf);
#pragma unroll
        for (int ks = 0; ks < 32; ks += 16) {
            int c = ks + (lane & 3)*2;
            u32 bhf[4][2], blf[4][2];
#pragma unroll
            for (int nf = 0; nf < 4; nf++) {
                int n  = wn*32 + nf*8 + (lane >> 2);
                bhf[nf][0] = pk(cBh[c*GB_RS+n],     cBh[(c+1)*GB_RS+n]);
                bhf[nf][1] = pk(cBh[(c+8)*GB_RS+n], cBh[(c+9)*GB_RS+n]);
                blf[nf][0] = pk(cBl[c*GB_RS+n],     cBl[(c+1)*GB_RS+n]);
                blf[nf][1] = pk(cBl[(c+8)*GB_RS+n], cBl[(c+9)*GB_RS+n]);
            }
            u32 ah[2][4], al[2][4];
#pragma unroll
            for (int mf = 0; mf < 2; mf++) {
                int r = wm*32 + mf*16 + (lane >> 2);
                ah[mf][0] = *reinterpret_cast<u32*>(&cAh[r*GA_RS + c]);
                ah[mf][1] = *reinterpret_cast<u32*>(&cAh[(r+8)*GA_RS + c]);
                ah[mf][2] = *reinterpret_cast<u32*>(&cAh[r*GA_RS + c + 8]);
                ah[mf][3] = *reinterpret_cast<u32*>(&cAh[(r+8)*GA_RS + c + 8]);
                al[mf][0] = *reinterpret_cast<u32*>(&cAl[r*GA_RS + c]);
                al[mf][1] = *reinterpret_cast<u32*>(&cAl[(r+8)*GA_RS + c]);
                al[mf][2] = *reinterpret_cast<u32*>(&cAl[r*GA_RS + c + 8]);
                al[mf][3] = *reinterpret_cast<u32*>(&cAl[(r+8)*GA_RS + c + 8]);
            }
            // term-major: 8 independent mmas between accumulator reuse
#pragma unroll
            for (int mf = 0; mf < 2; mf++)
#pragma unroll
                for (int nf = 0; nf < 4; nf++)
                    mma_bf16(acc[mf][nf], ah[mf][0],ah[mf][1],ah[mf][2],ah[mf][3],
                             bhf[nf][0], bhf[nf][1]);
#pragma unroll
            for (int mf = 0; mf < 2; mf++)
#pragma unroll
                for (int nf = 0; nf < 4; nf++)
                    mma_bf16(acc[mf][nf], ah[mf][0],ah[mf][1],ah[mf][2],ah[mf][3],
                             blf[nf][0], blf[nf][1]);
#pragma unroll
            for (int mf = 0; mf < 2; mf++)
#pragma unroll
                for (int nf = 0; nf < 4; nf++)
                    mma_bf16(acc[mf][nf], al[mf][0],al[mf][1],al[mf][2],al[mf][3],
                             bhf[nf][0], bhf[nf][1]);
        }
        if (more) {
            u16* nAh = AH(nb); u16* nAl = AL(nb);
#pragma unroll
            for (int it = 0; it < 2; it++) {
                u16 h0,l0,h1,l1,h2,l2,h3,l3;
                bsplit(pa[it].x,h0,l0); bsplit(pa[it].y,h1,l1);
                bsplit(pa[it].z,h2,l2); bsplit(pa[it].w,h3,l3);
                *reinterpret_cast<u32*>(&nAh[ar[it]*GA_RS + ac[it]])     = pk(h0,h1);
                *reinterpret_cast<u32*>(&nAh[ar[it]*GA_RS + ac[it] + 2]) = pk(h2,h3);
                *reinterpret_cast<u32*>(&nAl[ar[it]*GA_RS + ac[it]])     = pk(l0,l1);
                *reinterpret_cast<u32*>(&nAl[ar[it]*GA_RS + ac[it] + 2]) = pk(l2,l3);
            }
            CP_WAIT0();
        }
        __syncthreads();
        buf = nb;
    }
#undef AH
#undef AL
#undef BH
#undef BL

#pragma unroll
    for (int mf = 0; mf < 2; mf++) {
#pragma unroll
        for (int nf = 0; nf < 4; nf++) {
            int r = bm + wm*32 + mf*16 + (lane >> 2);
            int c = bn + wn*32 + nf*8 + (lane & 3)*2;
            float b0 = bias[c], b1 = bias[c+1];
            float v0 = acc[mf][nf][0] + b0, v1 = acc[mf][nf][1] + b1;
            float v2 = acc[mf][nf][2] + b0, v3 = acc[mf][nf][3] + b1;
            if (relu) { v0=fmaxf(v0,0.f); v1=fmaxf(v1,0.f); v2=fmaxf(v2,0.f); v3=fmaxf(v3,0.f); }
            if (mode == 0) {
                *reinterpret_cast<float2*>(&Cf[(size_t)r*N + c])     = make_float2(v0, v1);
                *reinterpret_cast<float2*>(&Cf[(size_t)(r+8)*N + c]) = make_float2(v2, v3);
            } else {
                u16 h0,l0,h1,l1,h2,l2,h3,l3;
                if (mode == 1) { bsplit(v0,h0,l0); bsplit(v1,h1,l1); bsplit(v2,h2,l2); bsplit(v3,h3,l3); }
                else           { hsplit(v0,h0,l0); hsplit(v1,h1,l1); hsplit(v2,h2,l2); hsplit(v3,h3,l3); }
                *reinterpret_cast<u32*>(&Ch[(size_t)r*N + c])     = pk(h0,h1);
                *reinterpret_cast<u32*>(&Cl[(size_t)r*N + c])     = pk(l0,l1);
                *reinterpret_cast<u32*>(&Ch[(size_t)(r+8)*N + c]) = pk(h2,h3);
                *reinterpret_cast<u32*>(&Cl[(size_t)(r+8)*N + c]) = pk(l2,l3);
            }
        }
    }
}

__global__ __launch_bounds__(256, 3)
void gemm_ts(const float* __restrict__ A, int lda, int aoff,
             const u16* __restrict__ Wh, const u16* __restrict__ Wl,
             const float* __restrict__ bias,
             float* __restrict__ Cf, u16* __restrict__ Ch, u16* __restrict__ Cl,
             int N, int K, int relu, int mode)
{
    extern __shared__ u16 smg[];
    int bm = blockIdx.y*64, bn = blockIdx.x*128;
    gemm_body(A + (size_t)bm*lda + aoff, lda, Wh, Wl, bias,
              Cf, Ch, Cl, N, K, bm, bn, relu, mode, smg);
}

__global__ __launch_bounds__(256, 3)
void qkv_gemm_ts(const float* __restrict__ A,
                 const float* __restrict__ bq, const float* __restrict__ bk,
                 const float* __restrict__ bv)
{
    extern __shared__ u16 smg[];
    int grp = blockIdx.x / 6;
    int bxl = blockIdx.x - grp*6;
    int bm = blockIdx.y*64, bn = bxl*128;
    const u16* Wh = g_Wh + grp*196608;
    const u16* Wl = g_Wl + grp*196608;
    const float* bias = (grp == 0) ? bq : (grp == 1) ? bk : bv;
    u16* Ch = (grp == 0) ? g_qh : (grp == 1) ? g_kh : g_vh;
    u16* Cl = (grp == 0) ? g_ql : (grp == 1) ? g_kl : g_vl;
    int mode = (grp == 2) ? 2 : 1;
    int aoff = grp*256;
    gemm_body(A + (size_t)bm*DIM + aoff, DIM, Wh, Wl, bias,
              nullptr, Ch, Cl, DIM, 256, bm, bn, 1, mode, smg);
}

// ---------------- fused flash attention: K/V double-buffered, cp.async prefetch ----------------
#define FA_RS 72
#define FA_SMEM ((2*128*FA_RS + 2*4*64*FA_RS) * 2)   // 110592 bytes
__global__ __launch_bounds__(256, 2)
void fused_attn(const u16* __restrict__ Qhg, const u16* __restrict__ Qlg,
                const u16* __restrict__ Khg, const u16* __restrict__ Klg,
                const u16* __restrict__ Vhg, const u16* __restrict__ Vlg,
                float* __restrict__ Of, float scale)
{
    extern __shared__ u16 sm[];
    u16* Qh = sm;
    u16* Ql = Qh + 128*FA_RS;
    u16* KVb = sm + 2*128*FA_RS;
#define KH(b) (KVb + (b)*(4*64*FA_RS))
#define KL(b) (KVb + (b)*(4*64*FA_RS) + 64*FA_RS)
#define VH(b) (KVb + (b)*(4*64*FA_RS) + 2*64*FA_RS)
#define VL(b) (KVb + (b)*(4*64*FA_RS) + 3*64*FA_RS)

    int bh = blockIdx.z;
    int b = bh / NH, h = bh - b*NH;
    int tid = threadIdx.x, lane = tid & 31, w = tid >> 5;
    size_t base = ((size_t)b*SEQ)*DIM + h*HD;
    int q0 = blockIdx.x * 128;
    const float cfac = scale * 1.4426950408889634f;

    int kr[2], kc[2];
#pragma unroll
    for (int it = 0; it < 2; it++) {
        int idx = it*256 + tid;
        kr[it] = idx >> 3; kc[it] = (idx & 7) * 8;
    }

#pragma unroll
    for (int it = 0; it < 2; it++) {
        size_t g = base + (size_t)kr[it]*DIM + kc[it];
        cpa16(&KH(0)[kr[it]*FA_RS + kc[it]], Khg + g);
        cpa16(&KL(0)[kr[it]*FA_RS + kc[it]], Klg + g);
        cpa16(&VH(0)[kr[it]*FA_RS + kc[it]], Vhg + g);
        cpa16(&VL(0)[kr[it]*FA_RS + kc[it]], Vlg + g);
    }
    CP_COMMIT();
#pragma unroll
    for (int it = 0; it < 4; it++) {
        int idx = it*256 + tid;
        int r = idx >> 3, c8 = (idx & 7) * 8;
        *reinterpret_cast<uint4*>(&Qh[r*FA_RS + c8]) =
            *reinterpret_cast<const uint4*>(Qhg + base + (size_t)(q0+r)*DIM + c8);
        *reinterpret_cast<uint4*>(&Ql[r*FA_RS + c8]) =
            *reinterpret_cast<const uint4*>(Qlg + base + (size_t)(q0+r)*DIM + c8);
    }
    CP_WAIT0();
    __syncthreads();

    float o[8][4];
#pragma unroll
    for (int i=0;i<8;i++)
#pragma unroll
        for (int j=0;j<4;j++) o[i][j]=0.f;
    float m_lo = -1e30f, m_hi = -1e30f, l_lo = 0.f, l_hi = 0.f;

    int rq = w*16 + (lane >> 2);
    int buf = 0;

    for (int t0 = 0; t0 < SEQ; t0 += 64) {
        bool more = (t0 + 64) < SEQ;
        int nb = buf ^ 1;
        if (more) {
#pragma unroll
            for (int it = 0; it < 2; it++) {
                size_t g = base + (size_t)(t0+64+kr[it])*DIM + kc[it];
                cpa16(&KH(nb)[kr[it]*FA_RS + kc[it]], Khg + g);
                cpa16(&KL(nb)[kr[it]*FA_RS + kc[it]], Klg + g);
                cpa16(&VH(nb)[kr[it]*FA_RS + kc[it]], Vhg + g);
                cpa16(&VL(nb)[kr[it]*FA_RS + kc[it]], Vlg + g);
            }
            CP_COMMIT();
        }
        u16* cKh = KH(buf); u16* cKl = KL(buf);
        u16* cVh = VH(buf); u16* cVl = VL(buf);

        float sacc[8][4];
#pragma unroll
        for (int i=0;i<8;i++)
#pragma unroll
            for (int j=0;j<4;j++) sacc[i][j]=0.f;
#pragma unroll
        for (int ks = 0; ks < 4; ks++) {
            int c = ks*16 + (lane & 3)*2;
            u32 ah0 = *reinterpret_cast<u32*>(&Qh[rq*FA_RS + c]);
            u32 ah1 = *reinterpret_cast<u32*>(&Qh[(rq+8)*FA_RS + c]);
            u32 ah2 = *reinterpret_cast<u32*>(&Qh[rq*FA_RS + c + 8]);
            u32 ah3 = *reinterpret_cast<u32*>(&Qh[(rq+8)*FA_RS + c + 8]);
            u32 al0 = *reinterpret_cast<u32*>(&Ql[rq*FA_RS + c]);
            u32 al1 = *reinterpret_cast<u32*>(&Ql[(rq+8)*FA_RS + c]);
            u32 al2 = *reinterpret_cast<u32*>(&Ql[rq*FA_RS + c + 8]);
            u32 al3 = *reinterpret_cast<u32*>(&Ql[(rq+8)*FA_RS + c + 8]);
#pragma unroll
            for (int nf = 0; nf < 8; nf++) {
                int n = nf*8 + (lane >> 2);
                u32 bh0 = *reinterpret_cast<u32*>(&cKh[n*FA_RS + c]);
                u32 bh1 = *reinterpret_cast<u32*>(&cKh[n*FA_RS + c + 8]);
                u32 bl0 = *reinterpret_cast<u32*>(&cKl[n*FA_RS + c]);
                u32 bl1 = *reinterpret_cast<u32*>(&cKl[n*FA_RS + c + 8]);
                mma_bf16(sacc[nf], ah0,ah1,ah2,ah3, bh0,bh1);
                mma_bf16(sacc[nf], ah0,ah1,ah2,ah3, bl0,bl1);
                mma_bf16(sacc[nf], al0,al1,al2,al3, bh0,bh1);
            }
        }

        float tm_lo = -1e30f, tm_hi = -1e30f;
#pragma unroll
        for (int nf = 0; nf < 8; nf++) {
            tm_lo = fmaxf(tm_lo, fmaxf(sacc[nf][0], sacc[nf][1]));
            tm_hi = fmaxf(tm_hi, fmaxf(sacc[nf][2], sacc[nf][3]));
        }
        tm_lo = fmaxf(tm_lo, __shfl_xor_sync(0xffffffffu, tm_lo, 1));
        tm_lo = fmaxf(tm_lo, __shfl_xor_sync(0xffffffffu, tm_lo, 2));
        tm_hi = fmaxf(tm_hi, __shfl_xor_sync(0xffffffffu, tm_hi, 1));
        tm_hi = fmaxf(tm_hi, __shfl_xor_sync(0xffffffffu, tm_hi, 2));
        float mn_lo = fmaxf(m_lo, tm_lo), mn_hi = fmaxf(m_hi, tm_hi);
        float f_lo = fexp(m_lo - mn_lo, cfac), f_hi = fexp(m_hi - mn_hi, cfac);
        m_lo = mn_lo; m_hi = mn_hi;

        float ts_lo = 0.f, ts_hi = 0.f;
        u32 plo[8], phi[8];
#pragma unroll
        for (int nf = 0; nf < 8; nf++) {
            float p0 = fexp(sacc[nf][0] - mn_lo, cfac);
            float p1 = fexp(sacc[nf][1] - mn_lo, cfac);
            float p2 = fexp(sacc[nf][2] - mn_hi, cfac);
            float p3 = fexp(sacc[nf][3] - mn_hi, cfac);
            ts_lo += p0 + p1; ts_hi += p2 + p3;
            __half2 hl = __floats2half2_rn(p0, p1);
            __half2 hh = __floats2half2_rn(p2, p3);
            plo[nf] = *reinterpret_cast<u32*>(&hl);
            phi[nf] = *reinterpret_cast<u32*>(&hh);
        }
        ts_lo += __shfl_xor_sync(0xffffffffu, ts_lo, 1);
        ts_lo += __shfl_xor_sync(0xffffffffu, ts_lo, 2);
        ts_hi += __shfl_xor_sync(0xffffffffu, ts_hi, 1);
        ts_hi += __shfl_xor_sync(0xffffffffu, ts_hi, 2);
        l_lo = l_lo * f_lo + ts_lo;
        l_hi = l_hi * f_hi + ts_hi;

#pragma unroll
        for (int ef = 0; ef < 8; ef++) {
            o[ef][0] *= f_lo; o[ef][1] *= f_lo;
            o[ef][2] *= f_hi; o[ef][3] *= f_hi;
        }

#pragma unroll
        for (int ks = 0; ks < 4; ks++) {
            int k0 = ks*16 + (lane & 3)*2;
            u32 a0 = plo[2*ks], a1 = phi[2*ks], a2 = plo[2*ks+1], a3 = phi[2*ks+1];
#pragma unroll
            for (int ef = 0; ef < 8; ef++) {
                int e = ef*8 + (lane >> 2);
                u32 b0h = pk(cVh[k0*FA_RS+e],     cVh[(k0+1)*FA_RS+e]);
                u32 b1h = pk(cVh[(k0+8)*FA_RS+e], cVh[(k0+9)*FA_RS+e]);
                u32 b0l = pk(cVl[k0*FA_RS+e],     cVl[(k0+1)*FA_RS+e]);
                u32 b1l = pk(cVl[(k0+8)*FA_RS+e], cVl[(k0+9)*FA_RS+e]);
                mma_f16(o[ef], a0,a1,a2,a3, b0h,b1h);
                mma_f16(o[ef], a0,a1,a2,a3, b0l,b1l);
            }
        }
        if (more) CP_WAIT0();
        __syncthreads();
        buf = nb;
    }
#undef KH
#undef KL
#undef VH
#undef VL

    float il_lo = 1.0f / l_lo, il_hi = 1.0f / l_hi;
    size_t row = (size_t)b*SEQ + q0 + rq;
#pragma unroll
    for (int ef = 0; ef < 8; ef++) {
        int col = h*HD + ef*8 + (lane & 3)*2;
        *reinterpret_cast<float2*>(&Of[row*DIM + col]) =
            make_float2(o[ef][0]*il_lo, o[ef][1]*il_lo);
        *reinterpret_cast<float2*>(&Of[(row+8)*DIM + col]) =
            make_float2(o[ef][2]*il_hi, o[ef][3]*il_hi);
    }
}

// ---------------- batch norm ----------------
__global__ __launch_bounds__(256)
void bn_stats(const float* __restrict__ X, const float* __restrict__ Y)
{
    int f  = blockIdx.x*32 + threadIdx.x;
    int rb = blockIdx.y*512;
    float s = 0.0f, s2 = 0.0f;
    for (int r = rb + threadIdx.y; r < rb + 512; r += 8) {
        size_t idx = (size_t)r*DIM + f;
        float v = X[idx] + Y[idx];
        s += v; s2 = fmaf(v, v, s2);
    }
    __shared__ double sh[2][8][32];
    sh[0][threadIdx.y][threadIdx.x] = (double)s;
    sh[1][threadIdx.y][threadIdx.x] = (double)s2;
    __syncthreads();
    if (threadIdx.y == 0) {
        double ts = 0.0, ts2 = 0.0;
#pragma unroll
        for (int i = 0; i < 8; i++) { ts += sh[0][i][threadIdx.x]; ts2 += sh[1][i][threadIdx.x]; }
        g_psum [blockIdx.y][f] = ts;
        g_psum2[blockIdx.y][f] = ts2;
    }
}

__global__ void bn_finalize(const float* __restrict__ g, const float* __restrict__ b)
{
    int f = blockIdx.x*256 + threadIdx.x;
    if (f >= DIM) return;
    double s = 0.0, s2 = 0.0;
#pragma unroll
    for (int i = 0; i < 8; i++) { s += g_psum[i][f]; s2 += g_psum2[i][f]; }
    double mu  = s  * (1.0 / ROWS);
    double var = s2 * (1.0 / ROWS) - mu*mu;
    float rstd = (float)(1.0 / sqrt(var + 1e-5));
    float sc = g[f] * rstd;
    g_bnsc[f] = sc;
    g_bnsh[f] = b[f] - (float)mu * sc;
}

__global__ __launch_bounds__(256)
void bn_apply2(const float* __restrict__ X, const float* __restrict__ Y,
               float* __restrict__ O)
{
    int idx4 = blockIdx.x*256 + threadIdx.x;
    if (idx4 >= ROWS*DIM/4) return;
    int f = (idx4*4) % DIM;
    float4 x = *reinterpret_cast<const float4*>(&X[(size_t)idx4*4]);
    float4 y = *reinterpret_cast<const float4*>(&Y[(size_t)idx4*4]);
    float4 o;
    o.x = fmaf(x.x + y.x, g_bnsc[f+0], g_bnsh[f+0]);
    o.y = fmaf(x.y + y.y, g_bnsc[f+1], g_bnsh[f+1]);
    o.z = fmaf(x.z + y.z, g_bnsc[f+2], g_bnsh[f+2]);
    o.w = fmaf(x.w + y.w, g_bnsc[f+3], g_bnsh[f+3]);
    *reinterpret_cast<float4*>(&O[(size_t)idx4*4]) = o;
}

// ---------------- launch ----------------
static float* sym(const void* s)
{
    void* p = nullptr;
    cudaGetSymbolAddress(&p, s);
    return (float*)p;
}

extern "C" void kernel_launch(void* const* d_in, const int* in_sizes, int n_in,
                              void* d_out, int out_size)
{
    const int*   x     = (const int*)  d_in[0];
    const float* encod = (const float*)d_in[1];
    const float* embed = (const float*)d_in[2];
    const float* Wq  = (const float*)d_in[3];  const float* bq  = (const float*)d_in[4];
    const float* Wk  = (const float*)d_in[5];  const float* bk  = (const float*)d_in[6];
    const float* Wv  = (const float*)d_in[7];  const float* bv  = (const float*)d_in[8];
    const float* g1  = (const float*)d_in[9];  const float* b1  = (const float*)d_in[10];
    const float* Wq2 = (const float*)d_in[11]; const float* bq2 = (const float*)d_in[12];
    const float* Wk2 = (const float*)d_in[13]; const float* bk2 = (const float*)d_in[14];
    const float* Wv2 = (const float*)d_in[15]; const float* bv2 = (const float*)d_in[16];
    const float* Wo2 = (const float*)d_in[17]; const float* bo2 = (const float*)d_in[18];
    const float* g2  = (const float*)d_in[19]; const float* b2  = (const float*)d_in[20];
    const float* Wf  = (const float*)d_in[21]; const float* bf  = (const float*)d_in[22];
    float* out = (float*)d_out;

    float *im = sym(g_im), *sa = sym(g_sa), *t1 = sym(g_t1), *av = sym(g_av);
    float *m2 = sym(g_m2), *t2 = sym(g_t2), *ff = sym(g_ff);
    u16 *qh = (u16*)sym(g_qh), *ql = (u16*)sym(g_ql);
    u16 *kh = (u16*)sym(g_kh), *kl = (u16*)sym(g_kl);
    u16 *vh = (u16*)sym(g_vh), *vl = (u16*)sym(g_vl);
    u16 *q2h = (u16*)sym(g_q2h), *q2l = (u16*)sym(g_q2l);
    u16 *k2h = (u16*)sym(g_k2h), *k2l = (u16*)sym(g_k2l);
    u16 *v2h = (u16*)sym(g_v2h), *v2l = (u16*)sym(g_v2l);
    u16 *wh = (u16*)sym(g_Wh), *wl = (u16*)sym(g_Wl);

    cudaFuncSetAttribute(fused_attn,  cudaFuncAttributeMaxDynamicSharedMemorySize, FA_SMEM);
    cudaFuncSetAttribute(gemm_ts,     cudaFuncAttributeMaxDynamicSharedMemorySize, GEMM_SMEM);
    cudaFuncSetAttribute(qkv_gemm_ts, cudaFuncAttributeMaxDynamicSharedMemorySize, GEMM_SMEM);

    const float scale1 = 1.0f / sqrtf((float)DIM);
    const float scale2 = 1.0f / sqrtf((float)HD);

    dim3 gemmGrid(DIM/128, ROWS/64);       // (6, 64) = 384
    dim3 qkvGrid(3*DIM/128, ROWS/64);      // (18, 64) = 1152
    dim3 faGrid(SEQ/128, 1, NBH);          // (8, 1, 48)
    dim3 bnGrid(DIM/32, 8);
    dim3 bnBlk(32, 8);
    int ew4Blocks = (ROWS*DIM/4 + 255)/256;

    pe_table_kernel<<<(SEQ*DIM/2 + 255)/256, 256>>>();
    allsplit_kernel<<<(WSP_TOT + 255)/256, 256>>>(Wq, Wk, Wv, Wq2, Wk2, Wv2, Wo2, Wf);

    embed_pos_kernel<<<ew4Blocks, 256>>>(x, embed, im);

    gemm_ts<<<gemmGrid, 256, GEMM_SMEM>>>(encod, DIM, 0,   wh+OFF_Q2, wl+OFF_Q2, bq2,
                                          nullptr, q2h, q2l, DIM, DIM/2, 0, 1);
    gemm_ts<<<gemmGrid, 256, GEMM_SMEM>>>(encod, DIM, 384, wh+OFF_K2, wl+OFF_K2, bk2,
                                          nullptr, k2h, k2l, DIM, DIM/2, 0, 1);

    for (int li = 0; li < NITER; li++) {
        qkv_gemm_ts<<<qkvGrid, 256, GEMM_SMEM>>>(im, bq, bk, bv);
        fused_attn<<<faGrid, 256, FA_SMEM>>>(qh, ql, kh, kl, vh, vl, sa, scale1);

        bn_stats<<<bnGrid, bnBlk>>>(im, sa);
        bn_finalize<<<3, 256>>>(g1, b1);
        bn_apply2<<<ew4Blocks, 256>>>(im, sa, t1);

        gemm_ts<<<gemmGrid, 256, GEMM_SMEM>>>(t1, DIM, 0, wh+OFF_V2, wl+OFF_V2, bv2,
                                              nullptr, v2h, v2l, DIM, DIM, 0, 2);
        fused_attn<<<faGrid, 256, FA_SMEM>>>(q2h, q2l, k2h, k2l, v2h, v2l, av, scale2);
        gemm_ts<<<gemmGrid, 256, GEMM_SMEM>>>(av, DIM, 0, wh+OFF_O2, wl+OFF_O2, bo2,
                                              m2, nullptr, nullptr, DIM, DIM, 0, 0);

        bn_stats<<<bnGrid, bnBlk>>>(m2, t1);
        bn_finalize<<<3, 256>>>(g2, b2);
        bn_apply2<<<ew4Blocks, 256>>>(m2, t1, t2);

        gemm_ts<<<gemmGrid, 256, GEMM_SMEM>>>(t2, DIM, 0, wh+OFF_F, wl+OFF_F, bf,
                                              ff, nullptr, nullptr, DIM, DIM, 0, 0);
        bn_stats<<<bnGrid, bnBlk>>>(t2, ff);
        bn_finalize<<<3, 256>>>(g2, b2);
        bn_apply2<<<ew4Blocks, 256>>>(t2, ff, im);
    }

    cudaMemcpyAsync(out, im, (size_t)ROWS*DIM*sizeof(float),
                    cudaMemcpyDeviceToDevice);
}

// round 15
// speedup vs baseline: 1.2394x; 1.1602x over previous
#include <cuda_runtime.h>
#include <cuda_bf16.h>
#include <cuda_fp16.h>
#include <math.h>

#define BSZ   4
#define SEQ   1024
#define DIM   768
#define NH    12
#define HD    64
#define ROWS  (BSZ*SEQ)      // 4096
#define NBH   (BSZ*NH)       // 48
#define NITER 2

typedef unsigned short u16;
typedef unsigned int   u32;

// packed-weight pair offsets (u32 elements)
#define OFFP_Q   0
#define OFFP_K   98304
#define OFFP_V   196608
#define OFFP_Q2  294912
#define OFFP_K2  442368
#define OFFP_V2  589824
#define OFFP_O2  884736
#define OFFP_F   1179648
#define WSP_PAIRS 1474560

// ---------------- static scratch ----------------
__device__ float g_im [ROWS*DIM];
__device__ float g_sa [ROWS*DIM];
__device__ float g_t1 [ROWS*DIM];
__device__ float g_av [ROWS*DIM];
__device__ float g_m2 [ROWS*DIM];
__device__ float g_t2 [ROWS*DIM];
__device__ float g_ff [ROWS*DIM];
__device__ float g_pe [SEQ*DIM];
__device__ u16 g_qh [ROWS*DIM], g_ql [ROWS*DIM];
__device__ u16 g_kh [ROWS*DIM], g_kl [ROWS*DIM];
__device__ u16 g_q2h[ROWS*DIM], g_q2l[ROWS*DIM];
__device__ u16 g_k2h[ROWS*DIM], g_k2l[ROWS*DIM];
// V and V2: fp16 split, transposed-packed [bh][e][seq/2] u32
__device__ u32 g_vth [ROWS*DIM/2], g_vtl [ROWS*DIM/2];
__device__ u32 g_v2th[ROWS*DIM/2], g_v2tl[ROWS*DIM/2];
// weights: bf16 split, k-pair packed [k/2][n] u32
__device__ u32 g_Wph[WSP_PAIRS], g_Wpl[WSP_PAIRS];
__device__ double g_psum [8][DIM];
__device__ double g_psum2[8][DIM];
__device__ float  g_bnsc[DIM];
__device__ float  g_bnsh[DIM];

// ---------------- helpers ----------------
__device__ __forceinline__ void bsplit(float x, u16& h, u16& l)
{
    __nv_bfloat16 bh = __float2bfloat16(x);
    h = __bfloat16_as_ushort(bh);
    l = __bfloat16_as_ushort(__float2bfloat16(x - __bfloat162float(bh)));
}
__device__ __forceinline__ void hsplit(float x, u16& h, u16& l)
{
    __half hh = __float2half_rn(x);
    h = __half_as_ushort(hh);
    l = __half_as_ushort(__float2half_rn(x - __half2float(hh)));
}
__device__ __forceinline__ u32 pk(u16 a, u16 b) { return (u32)a | ((u32)b << 16); }

__device__ __forceinline__ void cpa16(void* dst_smem, const void* src)
{
    u32 d = (u32)__cvta_generic_to_shared(dst_smem);
    asm volatile("cp.async.cg.shared.global [%0], [%1], 16;" :: "r"(d), "l"(src));
}
#define CP_COMMIT() asm volatile("cp.async.commit_group;" ::: "memory")
#define CP_WAIT0()  asm volatile("cp.async.wait_group 0;" ::: "memory")

__device__ __forceinline__ void mma_bf16(float d[4], u32 a0, u32 a1, u32 a2, u32 a3,
                                         u32 b0, u32 b1)
{
    asm volatile(
        "mma.sync.aligned.m16n8k16.row.col.f32.bf16.bf16.f32 "
        "{%0,%1,%2,%3}, {%4,%5,%6,%7}, {%8,%9}, {%0,%1,%2,%3};\n"
        : "+f"(d[0]), "+f"(d[1]), "+f"(d[2]), "+f"(d[3])
        : "r"(a0), "r"(a1), "r"(a2), "r"(a3), "r"(b0), "r"(b1));
}
__device__ __forceinline__ void mma_f16(float d[4], u32 a0, u32 a1, u32 a2, u32 a3,
                                        u32 b0, u32 b1)
{
    asm volatile(
        "mma.sync.aligned.m16n8k16.row.col.f32.f16.f16.f32 "
        "{%0,%1,%2,%3}, {%4,%5,%6,%7}, {%8,%9}, {%0,%1,%2,%3};\n"
        : "+f"(d[0]), "+f"(d[1]), "+f"(d[2]), "+f"(d[3])
        : "r"(a0), "r"(a1), "r"(a2), "r"(a3), "r"(b0), "r"(b1));
}

// fast exp with folded factor c (= k*log2e)
__device__ __forceinline__ float fexp(float x, float c)
{
    float t = fmaxf(x * c, -120.0f);
    float r = t + 12582912.0f;
    float nf = r - 12582912.0f;
    float f = t - nf;
    float p = 1.3333558146e-3f;
    p = fmaf(p, f, 9.6181291077e-3f);
    p = fmaf(p, f, 5.5504108664e-2f);
    p = fmaf(p, f, 2.4022650695e-1f);
    p = fmaf(p, f, 6.9314718056e-1f);
    p = fmaf(p, f, 1.0f);
    int n = __float_as_int(r) - 0x4B400000;
    return __int_as_float(__float_as_int(p) + (n << 23));
}

// ---------------- one-time: PE table ----------------
__global__ void pe_table_kernel()
{
    int idx2 = blockIdx.x*256 + threadIdx.x;
    if (idx2 >= SEQ*DIM/2) return;
    int s = idx2 / (DIM/2), d2 = idx2 - s*(DIM/2);
    float inv = exp2f((float)d2 * (-13.287712379549449f * 2.0f / (float)DIM));
    float ang = (float)s * inv;
    g_pe[(size_t)s*DIM + 2*d2]     = sinf(ang);
    g_pe[(size_t)s*DIM + 2*d2 + 1] = cosf(ang);
}

// ---------------- one-time: weight split + k-pair pack ----------------
__global__ void allsplit_kernel(const float* __restrict__ p0, const float* __restrict__ p1,
                                const float* __restrict__ p2, const float* __restrict__ p3,
                                const float* __restrict__ p4, const float* __restrict__ p5,
                                const float* __restrict__ p6, const float* __restrict__ p7)
{
    int i = blockIdx.x*256 + threadIdx.x;
    if (i >= WSP_PAIRS) return;
    const float* p; int j;
    if      (i < OFFP_K)  { p = p0; j = i; }
    else if (i < OFFP_V)  { p = p1; j = i - OFFP_K; }
    else if (i < OFFP_Q2) { p = p2; j = i - OFFP_V; }
    else if (i < OFFP_K2) { p = p3; j = i - OFFP_Q2; }
    else if (i < OFFP_V2) { p = p4; j = i - OFFP_K2; }
    else if (i < OFFP_O2) { p = p5; j = i - OFFP_V2; }
    else if (i < OFFP_F)  { p = p6; j = i - OFFP_O2; }
    else                  { p = p7; j = i - OFFP_F; }
    int n = j % DIM, pr = j / DIM;
    float a = p[(size_t)(2*pr)*DIM + n];
    float b = p[(size_t)(2*pr+1)*DIM + n];
    u16 ha, la, hb, lb;
    bsplit(a, ha, la); bsplit(b, hb, lb);
    g_Wph[i] = pk(ha, hb);
    g_Wpl[i] = pk(la, lb);
}

// ---------------- embedding + PE ----------------
__global__ void embed_pos_kernel(const int* __restrict__ x,
                                 const float* __restrict__ embed,
                                 float* __restrict__ out)
{
    int idx4 = blockIdx.x * 256 + threadIdx.x;
    if (idx4 >= ROWS*DIM/4) return;
    int r = idx4 / (DIM/4), d = (idx4 - r*(DIM/4))*4;
    int s = r & (SEQ-1);
    int tok = x[r];
    float4 e = *reinterpret_cast<const float4*>(&embed[(size_t)tok*DIM + d]);
    float4 p = *reinterpret_cast<const float4*>(&g_pe[(size_t)s*DIM + d]);
    float4 o;
    o.x = fmaf(2.0f, e.x, p.x); o.y = fmaf(2.0f, e.y, p.y);
    o.z = fmaf(2.0f, e.z, p.z); o.w = fmaf(2.0f, e.w, p.w);
    *reinterpret_cast<float4*>(&out[(size_t)idx4*4]) = o;
}

// ---------------- GEMM: 64x128 tile, packed-B fragments (one LDS.32 each) ----------------
// out modes: 0 = fp32, 1 = bf16 split, 2 = fp16 split transposed-packed (V format)
#define GA_RS 40
#define GB_RS 136   // u32 row stride for packed B (16 pair-rows per k-tile)
#define GEMM_SMEM (4*64*GA_RS*2 + 4*16*GB_RS*4)   // 20480 + 34816 = 55296 bytes
__device__ __forceinline__ void gemm_body(
    const float* __restrict__ Ab, int lda,
    const u32* __restrict__ Wph, const u32* __restrict__ Wpl,
    const float* __restrict__ bias,
    float* __restrict__ Cf, void* Chv, void* Clv,
    int N, int K, int bm, int bn, int relu, int mode, u16* sm)
{
    int tid = threadIdx.x;
    int lane = tid & 31, wid = tid >> 5;
    int wm = wid & 1, wn = wid >> 1;

    u32* Bbase = (u32*)(sm + 4*64*GA_RS);
#define AHs(b) (sm + (b)*(2*64*GA_RS))
#define ALs(b) (sm + (b)*(2*64*GA_RS) + 64*GA_RS)
#define BHs(b) (Bbase + (b)*(2*16*GB_RS))
#define BLs(b) (Bbase + (b)*(2*16*GB_RS) + 16*GB_RS)

    // loader coords: A 64x32 fp32 = 512 float4 -> 2/thread
    //                B 16 pair-rows x 128 u32 = 512 x 16B chunks/array -> 2/thread
    int ar[2], ac[2], bp[2], bc[2];
#pragma unroll
    for (int it = 0; it < 2; it++) {
        int idx = it*256 + tid;
        ar[it] = idx >> 3;  ac[it] = (idx & 7) * 4;
        bp[it] = idx >> 5;  bc[it] = (idx & 31) * 4;   // u32 units
    }

    float acc[2][4][4];
#pragma unroll
    for (int i=0;i<2;i++)
#pragma unroll
        for (int j=0;j<4;j++)
#pragma unroll
            for (int q=0;q<4;q++) acc[i][j][q]=0.f;

    // prologue
    {
        float4 pa[2];
#pragma unroll
        for (int it = 0; it < 2; it++)
            pa[it] = *reinterpret_cast<const float4*>(Ab + (size_t)ar[it]*lda + ac[it]);
#pragma unroll
        for (int it = 0; it < 2; it++) {
            u16 h0,l0,h1,l1,h2,l2,h3,l3;
            bsplit(pa[it].x,h0,l0); bsplit(pa[it].y,h1,l1);
            bsplit(pa[it].z,h2,l2); bsplit(pa[it].w,h3,l3);
            *reinterpret_cast<u32*>(&AHs(0)[ar[it]*GA_RS + ac[it]])     = pk(h0,h1);
            *reinterpret_cast<u32*>(&AHs(0)[ar[it]*GA_RS + ac[it] + 2]) = pk(h2,h3);
            *reinterpret_cast<u32*>(&ALs(0)[ar[it]*GA_RS + ac[it]])     = pk(l0,l1);
            *reinterpret_cast<u32*>(&ALs(0)[ar[it]*GA_RS + ac[it] + 2]) = pk(l2,l3);
        }
#pragma unroll
        for (int it = 0; it < 2; it++) {
            cpa16(&BHs(0)[bp[it]*GB_RS + bc[it]], &Wph[(size_t)bp[it]*N + bn + bc[it]]);
            cpa16(&BLs(0)[bp[it]*GB_RS + bc[it]], &Wpl[(size_t)bp[it]*N + bn + bc[it]]);
        }
        CP_COMMIT();
        CP_WAIT0();
        __syncthreads();
    }

    int buf = 0;
    for (int kb = 0; kb < K; kb += 32) {
        bool more = (kb + 32) < K;
        int nb = buf ^ 1;
        float4 pa[2];
        if (more) {
#pragma unroll
            for (int it = 0; it < 2; it++)
                pa[it] = *reinterpret_cast<const float4*>(Ab + (size_t)ar[it]*lda + kb+32 + ac[it]);
            int prbase = (kb + 32) >> 1;
#pragma unroll
            for (int it = 0; it < 2; it++) {
                cpa16(&BHs(nb)[bp[it]*GB_RS + bc[it]], &Wph[(size_t)(prbase+bp[it])*N + bn + bc[it]]);
                cpa16(&BLs(nb)[bp[it]*GB_RS + bc[it]], &Wpl[(size_t)(prbase+bp[it])*N + bn + bc[it]]);
            }
            CP_COMMIT();
        }
        u16* cAh = AHs(buf); u16* cAl = ALs(buf);
        u32* cBh = BHs(buf); u32* cBl = BLs(buf);
#pragma unroll
        for (int ks = 0; ks < 32; ks += 16) {
            int c  = ks + (lane & 3)*2;
            int pr = (ks >> 1) + (lane & 3);        // pair row
            u32 bhf[4][2], blf[4][2];
#pragma unroll
            for (int nf = 0; nf < 4; nf++) {
                int n = wn*32 + nf*8 + (lane >> 2);
                bhf[nf][0] = cBh[pr*GB_RS + n];
                bhf[nf][1] = cBh[(pr+4)*GB_RS + n];
                blf[nf][0] = cBl[pr*GB_RS + n];
                blf[nf][1] = cBl[(pr+4)*GB_RS + n];
            }
            u32 ah[2][4], al[2][4];
#pragma unroll
            for (int mf = 0; mf < 2; mf++) {
                int r = wm*32 + mf*16 + (lane >> 2);
                ah[mf][0] = *reinterpret_cast<u32*>(&cAh[r*GA_RS + c]);
                ah[mf][1] = *reinterpret_cast<u32*>(&cAh[(r+8)*GA_RS + c]);
                ah[mf][2] = *reinterpret_cast<u32*>(&cAh[r*GA_RS + c + 8]);
                ah[mf][3] = *reinterpret_cast<u32*>(&cAh[(r+8)*GA_RS + c + 8]);
                al[mf][0] = *reinterpret_cast<u32*>(&cAl[r*GA_RS + c]);
                al[mf][1] = *reinterpret_cast<u32*>(&cAl[(r+8)*GA_RS + c]);
                al[mf][2] = *reinterpret_cast<u32*>(&cAl[r*GA_RS + c + 8]);
                al[mf][3] = *reinterpret_cast<u32*>(&cAl[(r+8)*GA_RS + c + 8]);
            }
#pragma unroll
            for (int mf = 0; mf < 2; mf++)
#pragma unroll
                for (int nf = 0; nf < 4; nf++)
                    mma_bf16(acc[mf][nf], ah[mf][0],ah[mf][1],ah[mf][2],ah[mf][3],
                             bhf[nf][0], bhf[nf][1]);
#pragma unroll
            for (int mf = 0; mf < 2; mf++)
#pragma unroll
                for (int nf = 0; nf < 4; nf++)
                    mma_bf16(acc[mf][nf], ah[mf][0],ah[mf][1],ah[mf][2],ah[mf][3],
                             blf[nf][0], blf[nf][1]);
#pragma unroll
            for (int mf = 0; mf < 2; mf++)
#pragma unroll
                for (int nf = 0; nf < 4; nf++)
                    mma_bf16(acc[mf][nf], al[mf][0],al[mf][1],al[mf][2],al[mf][3],
                             bhf[nf][0], bhf[nf][1]);
        }
        if (more) {
            u16* nAh = AHs(nb); u16* nAl = ALs(nb);
#pragma unroll
            for (int it = 0; it < 2; it++) {
                u16 h0,l0,h1,l1,h2,l2,h3,l3;
                bsplit(pa[it].x,h0,l0); bsplit(pa[it].y,h1,l1);
                bsplit(pa[it].z,h2,l2); bsplit(pa[it].w,h3,l3);
                *reinterpret_cast<u32*>(&nAh[ar[it]*GA_RS + ac[it]])     = pk(h0,h1);
                *reinterpret_cast<u32*>(&nAh[ar[it]*GA_RS + ac[it] + 2]) = pk(h2,h3);
                *reinterpret_cast<u32*>(&nAl[ar[it]*GA_RS + ac[it]])     = pk(l0,l1);
                *reinterpret_cast<u32*>(&nAl[ar[it]*GA_RS + ac[it] + 2]) = pk(l2,l3);
            }
            CP_WAIT0();
        }
        __syncthreads();
        buf = nb;
    }
#undef AHs
#undef ALs
#undef BHs
#undef BLs

#pragma unroll
    for (int mf = 0; mf < 2; mf++) {
#pragma unroll
        for (int nf = 0; nf < 4; nf++) {
            int r = bm + wm*32 + mf*16 + (lane >> 2);
            int c = bn + wn*32 + nf*8 + (lane & 3)*2;
            float b0 = bias[c], b1 = bias[c+1];
            float v0 = acc[mf][nf][0] + b0, v1 = acc[mf][nf][1] + b1;
            float v2 = acc[mf][nf][2] + b0, v3 = acc[mf][nf][3] + b1;
            if (relu) { v0=fmaxf(v0,0.f); v1=fmaxf(v1,0.f); v2=fmaxf(v2,0.f); v3=fmaxf(v3,0.f); }
            if (mode == 0) {
                *reinterpret_cast<float2*>(&Cf[(size_t)r*N + c])     = make_float2(v0, v1);
                *reinterpret_cast<float2*>(&Cf[(size_t)(r+8)*N + c]) = make_float2(v2, v3);
            } else if (mode == 1) {
                u16* Ch = (u16*)Chv; u16* Cl = (u16*)Clv;
                u16 h0,l0,h1,l1,h2,l2,h3,l3;
                bsplit(v0,h0,l0); bsplit(v1,h1,l1); bsplit(v2,h2,l2); bsplit(v3,h3,l3);
                *reinterpret_cast<u32*>(&Ch[(size_t)r*N + c])     = pk(h0,h1);
                *reinterpret_cast<u32*>(&Cl[(size_t)r*N + c])     = pk(l0,l1);
                *reinterpret_cast<u32*>(&Ch[(size_t)(r+8)*N + c]) = pk(h2,h3);
                *reinterpret_cast<u32*>(&Cl[(size_t)(r+8)*N + c]) = pk(l2,l3);
            } else {
                // fp16 split, transposed-packed V format: [bh][e][seq/2] u32
                u16 h0,l0,h1,l1,h2,l2,h3,l3;
                hsplit(v0,h0,l0); hsplit(v1,h1,l1); hsplit(v2,h2,l2); hsplit(v3,h3,l3);
                u32 m01 = pk(h0,h1), m23 = pk(h2,h3);
                u32 n01 = pk(l0,l1), n23 = pk(l2,l3);
                u32 p01 = __shfl_down_sync(0xffffffffu, m01, 4);
                u32 p23 = __shfl_down_sync(0xffffffffu, m23, 4);
                u32 q01 = __shfl_down_sync(0xffffffffu, n01, 4);
                u32 q23 = __shfl_down_sync(0xffffffffu, n23, 4);
                if ((((lane >> 2) & 1) == 0)) {
                    int bb = r >> 10, s = r & (SEQ-1);
                    int hh = c >> 6, e = c & (HD-1);
                    u32* Vh32 = (u32*)Chv; u32* Vl32 = (u32*)Clv;
                    size_t vtb = ((size_t)(bb*NH + hh)*HD);
                    size_t i0 = (vtb + e)*(SEQ/2) + (s >> 1);
                    size_t i1 = (vtb + e + 1)*(SEQ/2) + (s >> 1);
                    Vh32[i0]     = pk(h0, (u16)(p01 & 0xffffu));
                    Vh32[i1]     = pk(h1, (u16)(p01 >> 16));
                    Vl32[i0]     = pk(l0, (u16)(q01 & 0xffffu));
                    Vl32[i1]     = pk(l1, (u16)(q01 >> 16));
                    Vh32[i0 + 4] = pk(h2, (u16)(p23 & 0xffffu));
                    Vh32[i1 + 4] = pk(h3, (u16)(p23 >> 16));
                    Vl32[i0 + 4] = pk(l2, (u16)(q23 & 0xffffu));
                    Vl32[i1 + 4] = pk(l3, (u16)(q23 >> 16));
                }
            }
        }
    }
}

__global__ __launch_bounds__(256, 3)
void gemm_ts(const float* __restrict__ A, int lda, int aoff,
             const u32* __restrict__ Wph, const u32* __restrict__ Wpl,
             const float* __restrict__ bias,
             float* __restrict__ Cf, void* Chv, void* Clv,
             int N, int K, int relu, int mode)
{
    extern __shared__ u16 smg[];
    int bm = blockIdx.y*64, bn = blockIdx.x*128;
    gemm_body(A + (size_t)bm*lda + aoff, lda, Wph, Wpl, bias,
              Cf, Chv, Clv, N, K, bm, bn, relu, mode, smg);
}

__global__ __launch_bounds__(256, 3)
void qkv_gemm_ts(const float* __restrict__ A,
                 const float* __restrict__ bq, const float* __restrict__ bk,
                 const float* __restrict__ bv)
{
    extern __shared__ u16 smg[];
    int grp = blockIdx.x / 6;
    int bxl = blockIdx.x - grp*6;
    int bm = blockIdx.y*64, bn = bxl*128;
    const u32* Wph = g_Wph + grp*98304;
    const u32* Wpl = g_Wpl + grp*98304;
    const float* bias = (grp == 0) ? bq : (grp == 1) ? bk : bv;
    void* Chv = (grp == 0) ? (void*)g_qh : (grp == 1) ? (void*)g_kh : (void*)g_vth;
    void* Clv = (grp == 0) ? (void*)g_ql : (grp == 1) ? (void*)g_kl : (void*)g_vtl;
    int mode = (grp == 2) ? 2 : 1;
    int aoff = grp*256;
    gemm_body(A + (size_t)bm*DIM + aoff, DIM, Wph, Wpl, bias,
              nullptr, Chv, Clv, DIM, 256, bm, bn, 1, mode, smg);
}

// ---------------- fused flash attention: packed V^T fragments ----------------
#define FA_RS 72
#define VT_RS 36   // u32 row stride for V^T tiles
#define FA_SMEM (2*128*FA_RS*2 + 2*2*64*FA_RS*2 + 2*2*64*VT_RS*4)  // 36864*3 = 110592
__global__ __launch_bounds__(256, 2)
void fused_attn(const u16* __restrict__ Qhg, const u16* __restrict__ Qlg,
                const u16* __restrict__ Khg, const u16* __restrict__ Klg,
                const u32* __restrict__ Vth, const u32* __restrict__ Vtl,
                float* __restrict__ Of, float scale)
{
    extern __shared__ u16 sm[];
    u16* Qh = sm;
    u16* Ql = Qh + 128*FA_RS;
    u16* Kbase = sm + 2*128*FA_RS;
    u32* Vbase = (u32*)(sm + 2*128*FA_RS + 2*2*64*FA_RS);
#define KHs(b) (Kbase + (b)*(2*64*FA_RS))
#define KLs(b) (Kbase + (b)*(2*64*FA_RS) + 64*FA_RS)
#define VHs(b) (Vbase + (b)*(2*64*VT_RS))
#define VLs(b) (Vbase + (b)*(2*64*VT_RS) + 64*VT_RS)

    int bh = blockIdx.z;
    int b = bh / NH, h = bh - b*NH;
    int tid = threadIdx.x, lane = tid & 31, w = tid >> 5;
    size_t base = ((size_t)b*SEQ)*DIM + h*HD;
    size_t vtbase = (size_t)(b*NH + h)*HD*(SEQ/2);
    int q0 = blockIdx.x * 128;
    const float cfac = scale * 1.4426950408889634f;

    // loader coords: K rows (u16): kr 0..63, kc 8-u16 chunks; V rows (u32): vr, vc 4-u32 chunks
    int kr[2], kc[2], vr[2], vc[2];
#pragma unroll
    for (int it = 0; it < 2; it++) {
        int idx = it*256 + tid;
        kr[it] = idx >> 3; kc[it] = (idx & 7) * 8;
        vr[it] = idx >> 3; vc[it] = (idx & 7) * 4;
    }

#pragma unroll
    for (int it = 0; it < 2; it++) {
        size_t g = base + (size_t)kr[it]*DIM + kc[it];
        cpa16(&KHs(0)[kr[it]*FA_RS + kc[it]], Khg + g);
        cpa16(&KLs(0)[kr[it]*FA_RS + kc[it]], Klg + g);
        size_t gv = vtbase + (size_t)vr[it]*(SEQ/2) + vc[it];
        cpa16(&VHs(0)[vr[it]*VT_RS + vc[it]], Vth + gv);
        cpa16(&VLs(0)[vr[it]*VT_RS + vc[it]], Vtl + gv);
    }
    CP_COMMIT();
#pragma unroll
    for (int it = 0; it < 4; it++) {
        int idx = it*256 + tid;
        int r = idx >> 3, c8 = (idx & 7) * 8;
        *reinterpret_cast<uint4*>(&Qh[r*FA_RS + c8]) =
            *reinterpret_cast<const uint4*>(Qhg + base + (size_t)(q0+r)*DIM + c8);
        *reinterpret_cast<uint4*>(&Ql[r*FA_RS + c8]) =
            *reinterpret_cast<const uint4*>(Qlg + base + (size_t)(q0+r)*DIM + c8);
    }
    CP_WAIT0();
    __syncthreads();

    float o[8][4];
#pragma unroll
    for (int i=0;i<8;i++)
#pragma unroll
        for (int j=0;j<4;j++) o[i][j]=0.f;
    float m_lo = -1e30f, m_hi = -1e30f, l_lo = 0.f, l_hi = 0.f;

    int rq = w*16 + (lane >> 2);
    int buf = 0;

    for (int t0 = 0; t0 < SEQ; t0 += 64) {
        bool more = (t0 + 64) < SEQ;
        int nb = buf ^ 1;
        if (more) {
#pragma unroll
            for (int it = 0; it < 2; it++) {
                size_t g = base + (size_t)(t0+64+kr[it])*DIM + kc[it];
                cpa16(&KHs(nb)[kr[it]*FA_RS + kc[it]], Khg + g);
                cpa16(&KLs(nb)[kr[it]*FA_RS + kc[it]], Klg + g);
                size_t gv = vtbase + (size_t)vr[it]*(SEQ/2) + ((t0+64) >> 1) + vc[it];
                cpa16(&VHs(nb)[vr[it]*VT_RS + vc[it]], Vth + gv);
                cpa16(&VLs(nb)[vr[it]*VT_RS + vc[it]], Vtl + gv);
            }
            CP_COMMIT();
        }
        u16* cKh = KHs(buf); u16* cKl = KLs(buf);
        u32* cVh = VHs(buf); u32* cVl = VLs(buf);

        float sacc[8][4];
#pragma unroll
        for (int i=0;i<8;i++)
#pragma unroll
            for (int j=0;j<4;j++) sacc[i][j]=0.f;
#pragma unroll
        for (int ks = 0; ks < 4; ks++) {
            int c = ks*16 + (lane & 3)*2;
            u32 ah0 = *reinterpret_cast<u32*>(&Qh[rq*FA_RS + c]);
            u32 ah1 = *reinterpret_cast<u32*>(&Qh[(rq+8)*FA_RS + c]);
            u32 ah2 = *reinterpret_cast<u32*>(&Qh[rq*FA_RS + c + 8]);
            u32 ah3 = *reinterpret_cast<u32*>(&Qh[(rq+8)*FA_RS + c + 8]);
            u32 al0 = *reinterpret_cast<u32*>(&Ql[rq*FA_RS + c]);
            u32 al1 = *reinterpret_cast<u32*>(&Ql[(rq+8)*FA_RS + c]);
            u32 al2 = *reinterpret_cast<u32*>(&Ql[rq*FA_RS + c + 8]);
            u32 al3 = *reinterpret_cast<u32*>(&Ql[(rq+8)*FA_RS + c + 8]);
#pragma unroll
            for (int nf = 0; nf < 8; nf++) {
                int n = nf*8 + (lane >> 2);
                u32 bh0 = *reinterpret_cast<u32*>(&cKh[n*FA_RS + c]);
                u32 bh1 = *reinterpret_cast<u32*>(&cKh[n*FA_RS + c + 8]);
                u32 bl0 = *reinterpret_cast<u32*>(&cKl[n*FA_RS + c]);
                u32 bl1 = *reinterpret_cast<u32*>(&cKl[n*FA_RS + c + 8]);
                mma_bf16(sacc[nf], ah0,ah1,ah2,ah3, bh0,bh1);
                mma_bf16(sacc[nf], ah0,ah1,ah2,ah3, bl0,bl1);
                mma_bf16(sacc[nf], al0,al1,al2,al3, bh0,bh1);
            }
        }

        float tm_lo = -1e30f, tm_hi = -1e30f;
#pragma unroll
        for (int nf = 0; nf < 8; nf++) {
            tm_lo = fmaxf(tm_lo, fmaxf(sacc[nf][0], sacc[nf][1]));
            tm_hi = fmaxf(tm_hi, fmaxf(sacc[nf][2], sacc[nf][3]));
        }
        tm_lo = fmaxf(tm_lo, __shfl_xor_sync(0xffffffffu, tm_lo, 1));
        tm_lo = fmaxf(tm_lo, __shfl_xor_sync(0xffffffffu, tm_lo, 2));
        tm_hi = fmaxf(tm_hi, __shfl_xor_sync(0xffffffffu, tm_hi, 1));
        tm_hi = fmaxf(tm_hi, __shfl_xor_sync(0xffffffffu, tm_hi, 2));
        float mn_lo = fmaxf(m_lo, tm_lo), mn_hi = fmaxf(m_hi, tm_hi);
        float f_lo = fexp(m_lo - mn_lo, cfac), f_hi = fexp(m_hi - mn_hi, cfac);
        m_lo = mn_lo; m_hi = mn_hi;

        float ts_lo = 0.f, ts_hi = 0.f;
        u32 plo[8], phi[8];
#pragma unroll
        for (int nf = 0; nf < 8; nf++) {
            float p0 = fexp(sacc[nf][0] - mn_lo, cfac);
            float p1 = fexp(sacc[nf][1] - mn_lo, cfac);
            float p2 = fexp(sacc[nf][2] - mn_hi, cfac);
            float p3 = fexp(sacc[nf][3] - mn_hi, cfac);
            ts_lo += p0 + p1; ts_hi += p2 + p3;
            __half2 hl = __floats2half2_rn(p0, p1);
            __half2 hh = __floats2half2_rn(p2, p3);
            plo[nf] = *reinterpret_cast<u32*>(&hl);
            phi[nf] = *reinterpret_cast<u32*>(&hh);
        }
        ts_lo += __shfl_xor_sync(0xffffffffu, ts_lo, 1);
        ts_lo += __shfl_xor_sync(0xffffffffu, ts_lo, 2);
        ts_hi += __shfl_xor_sync(0xffffffffu, ts_hi, 1);
        ts_hi += __shfl_xor_sync(0xffffffffu, ts_hi, 2);
        l_lo = l_lo * f_lo + ts_lo;
        l_hi = l_hi * f_hi + ts_hi;

#pragma unroll
        for (int ef = 0; ef < 8; ef++) {
            o[ef][0] *= f_lo; o[ef][1] *= f_lo;
            o[ef][2] *= f_hi; o[ef][3] *= f_hi;
        }

#pragma unroll
        for (int ks = 0; ks < 4; ks++) {
            int pr = ks*8 + (lane & 3);
            u32 a0 = plo[2*ks], a1 = phi[2*ks], a2 = plo[2*ks+1], a3 = phi[2*ks+1];
#pragma unroll
            for (int ef = 0; ef < 8; ef++) {
                int e = ef*8 + (lane >> 2);
                u32 b0h = cVh[e*VT_RS + pr];
                u32 b1h = cVh[e*VT_RS + pr + 4];
                u32 b0l = cVl[e*VT_RS + pr];
                u32 b1l = cVl[e*VT_RS + pr + 4];
                mma_f16(o[ef], a0,a1,a2,a3, b0h,b1h);
                mma_f16(o[ef], a0,a1,a2,a3, b0l,b1l);
            }
        }
        if (more) CP_WAIT0();
        __syncthreads();
        buf = nb;
    }
#undef KHs
#undef KLs
#undef VHs
#undef VLs

    float il_lo = 1.0f / l_lo, il_hi = 1.0f / l_hi;
    size_t row = (size_t)b*SEQ + q0 + rq;
#pragma unroll
    for (int ef = 0; ef < 8; ef++) {
        int col = h*HD + ef*8 + (lane & 3)*2;
        *reinterpret_cast<float2*>(&Of[row*DIM + col]) =
            make_float2(o[ef][0]*il_lo, o[ef][1]*il_lo);
        *reinterpret_cast<float2*>(&Of[(row+8)*DIM + col]) =
            make_float2(o[ef][2]*il_hi, o[ef][3]*il_hi);
    }
}

// ---------------- batch norm ----------------
__global__ __launch_bounds__(256)
void bn_stats(const float* __restrict__ X, const float* __restrict__ Y)
{
    int f  = blockIdx.x*32 + threadIdx.x;
    int rb = blockIdx.y*512;
    float s = 0.0f, s2 = 0.0f;
    for (int r = rb + threadIdx.y; r < rb + 512; r += 8) {
        size_t idx = (size_t)r*DIM + f;
        float v = X[idx] + Y[idx];
        s += v; s2 = fmaf(v, v, s2);
    }
    __shared__ double sh[2][8][32];
    sh[0][threadIdx.y][threadIdx.x] = (double)s;
    sh[1][threadIdx.y][threadIdx.x] = (double)s2;
    __syncthreads();
    if (threadIdx.y == 0) {
        double ts = 0.0, ts2 = 0.0;
#pragma unroll
        for (int i = 0; i < 8; i++) { ts += sh[0][i][threadIdx.x]; ts2 += sh[1][i][threadIdx.x]; }
        g_psum [blockIdx.y][f] = ts;
        g_psum2[blockIdx.y][f] = ts2;
    }
}

__global__ void bn_finalize(const float* __restrict__ g, const float* __restrict__ b)
{
    int f = blockIdx.x*256 + threadIdx.x;
    if (f >= DIM) return;
    double s = 0.0, s2 = 0.0;
#pragma unroll
    for (int i = 0; i < 8; i++) { s += g_psum[i][f]; s2 += g_psum2[i][f]; }
    double mu  = s  * (1.0 / ROWS);
    double var = s2 * (1.0 / ROWS) - mu*mu;
    float rstd = (float)(1.0 / sqrt(var + 1e-5));
    float sc = g[f] * rstd;
    g_bnsc[f] = sc;
    g_bnsh[f] = b[f] - (float)mu * sc;
}

__global__ __launch_bounds__(256)
void bn_apply2(const float* __restrict__ X, const float* __restrict__ Y,
               float* __restrict__ O)
{
    int idx4 = blockIdx.x*256 + threadIdx.x;
    if (idx4 >= ROWS*DIM/4) return;
    int f = (idx4*4) % DIM;
    float4 x = *reinterpret_cast<const float4*>(&X[(size_t)idx4*4]);
    float4 y = *reinterpret_cast<const float4*>(&Y[(size_t)idx4*4]);
    float4 o;
    o.x = fmaf(x.x + y.x, g_bnsc[f+0], g_bnsh[f+0]);
    o.y = fmaf(x.y + y.y, g_bnsc[f+1], g_bnsh[f+1]);
    o.z = fmaf(x.z + y.z, g_bnsc[f+2], g_bnsh[f+2]);
    o.w = fmaf(x.w + y.w, g_bnsc[f+3], g_bnsh[f+3]);
    *reinterpret_cast<float4*>(&O[(size_t)idx4*4]) = o;
}

// ---------------- launch ----------------
static float* sym(const void* s)
{
    void* p = nullptr;
    cudaGetSymbolAddress(&p, s);
    return (float*)p;
}

extern "C" void kernel_launch(void* const* d_in, const int* in_sizes, int n_in,
                              void* d_out, int out_size)
{
    const int*   x     = (const int*)  d_in[0];
    const float* encod = (const float*)d_in[1];
    const float* embed = (const float*)d_in[2];
    const float* Wq  = (const float*)d_in[3];  const float* bq  = (const float*)d_in[4];
    const float* Wk  = (const float*)d_in[5];  const float* bk  = (const float*)d_in[6];
    const float* Wv  = (const float*)d_in[7];  const float* bv  = (const float*)d_in[8];
    const float* g1  = (const float*)d_in[9];  const float* b1  = (const float*)d_in[10];
    const float* Wq2 = (const float*)d_in[11]; const float* bq2 = (const float*)d_in[12];
    const float* Wk2 = (const float*)d_in[13]; const float* bk2 = (const float*)d_in[14];
    const float* Wv2 = (const float*)d_in[15]; const float* bv2 = (const float*)d_in[16];
    const float* Wo2 = (const float*)d_in[17]; const float* bo2 = (const float*)d_in[18];
    const float* g2  = (const float*)d_in[19]; const float* b2  = (const float*)d_in[20];
    const float* Wf  = (const float*)d_in[21]; const float* bf  = (const float*)d_in[22];
    float* out = (float*)d_out;

    float *im = sym(g_im), *sa = sym(g_sa), *t1 = sym(g_t1), *av = sym(g_av);
    float *m2 = sym(g_m2), *t2 = sym(g_t2), *ff = sym(g_ff);
    u16 *qh = (u16*)sym(g_qh), *ql = (u16*)sym(g_ql);
    u16 *kh = (u16*)sym(g_kh), *kl = (u16*)sym(g_kl);
    u16 *q2h = (u16*)sym(g_q2h), *q2l = (u16*)sym(g_q2l);
    u16 *k2h = (u16*)sym(g_k2h), *k2l = (u16*)sym(g_k2l);
    u32 *vth = (u32*)sym(g_vth),  *vtl = (u32*)sym(g_vtl);
    u32 *v2th = (u32*)sym(g_v2th), *v2tl = (u32*)sym(g_v2tl);
    u32 *wph = (u32*)sym(g_Wph), *wpl = (u32*)sym(g_Wpl);

    cudaFuncSetAttribute(fused_attn,  cudaFuncAttributeMaxDynamicSharedMemorySize, FA_SMEM);
    cudaFuncSetAttribute(gemm_ts,     cudaFuncAttributeMaxDynamicSharedMemorySize, GEMM_SMEM);
    cudaFuncSetAttribute(qkv_gemm_ts, cudaFuncAttributeMaxDynamicSharedMemorySize, GEMM_SMEM);

    const float scale1 = 1.0f / sqrtf((float)DIM);
    const float scale2 = 1.0f / sqrtf((float)HD);

    dim3 gemmGrid(DIM/128, ROWS/64);       // (6, 64) = 384
    dim3 qkvGrid(3*DIM/128, ROWS/64);      // (18, 64) = 1152
    dim3 faGrid(SEQ/128, 1, NBH);          // (8, 1, 48)
    dim3 bnGrid(DIM/32, 8);
    dim3 bnBlk(32, 8);
    int ew4Blocks = (ROWS*DIM/4 + 255)/256;

    pe_table_kernel<<<(SEQ*DIM/2 + 255)/256, 256>>>();
    allsplit_kernel<<<(WSP_PAIRS + 255)/256, 256>>>(Wq, Wk, Wv, Wq2, Wk2, Wv2, Wo2, Wf);

    embed_pos_kernel<<<ew4Blocks, 256>>>(x, embed, im);

    gemm_ts<<<gemmGrid, 256, GEMM_SMEM>>>(encod, DIM, 0,   wph+OFFP_Q2, wpl+OFFP_Q2, bq2,
                                          nullptr, q2h, q2l, DIM, DIM/2, 0, 1);
    gemm_ts<<<gemmGrid, 256, GEMM_SMEM>>>(encod, DIM, 384, wph+OFFP_K2, wpl+OFFP_K2, bk2,
                                          nullptr, k2h, k2l, DIM, DIM/2, 0, 1);

    for (int li = 0; li < NITER; li++) {
        qkv_gemm_ts<<<qkvGrid, 256, GEMM_SMEM>>>(im, bq, bk, bv);
        fused_attn<<<faGrid, 256, FA_SMEM>>>(qh, ql, kh, kl, vth, vtl, sa, scale1);

        bn_stats<<<bnGrid, bnBlk>>>(im, sa);
        bn_finalize<<<3, 256>>>(g1, b1);
        bn_apply2<<<ew4Blocks, 256>>>(im, sa, t1);

        gemm_ts<<<gemmGrid, 256, GEMM_SMEM>>>(t1, DIM, 0, wph+OFFP_V2, wpl+OFFP_V2, bv2,
                                              nullptr, v2th, v2tl, DIM, DIM, 0, 2);
        fused_attn<<<faGrid, 256, FA_SMEM>>>(q2h, q2l, k2h, k2l, v2th, v2tl, av, scale2);
        gemm_ts<<<gemmGrid, 256, GEMM_SMEM>>>(av, DIM, 0, wph+OFFP_O2, wpl+OFFP_O2, bo2,
                                              m2, nullptr, nullptr, DIM, DIM, 0, 0);

        bn_stats<<<bnGrid, bnBlk>>>(m2, t1);
        bn_finalize<<<3, 256>>>(g2, b2);
        bn_apply2<<<ew4Blocks, 256>>>(m2, t1, t2);

        gemm_ts<<<gemmGrid, 256, GEMM_SMEM>>>(t2, DIM, 0, wph+OFFP_F, wpl+OFFP_F, bf,
                                              ff, nullptr, nullptr, DIM, DIM, 0, 0);
        bn_stats<<<bnGrid, bnBlk>>>(t2, ff);
        bn_finalize<<<3, 256>>>(g2, b2);
        bn_apply2<<<ew4Blocks, 256>>>(t2, ff, im);
    }

    cudaMemcpyAsync(out, im, (size_t)ROWS*DIM*sizeof(float),
                    cudaMemcpyDeviceToDevice);
}

// round 17
// speedup vs baseline: 1.3006x; 1.0494x over previous
#include <cuda_runtime.h>
#include <cuda_bf16.h>
#include <cuda_fp16.h>
#include <math.h>

#define BSZ   4
#define SEQ   1024
#define DIM   768
#define NH    12
#define HD    64
#define ROWS  (BSZ*SEQ)      // 4096
#define NBH   (BSZ*NH)       // 48
#define NITER 2

typedef unsigned short u16;
typedef unsigned int   u32;

// weight split offsets (u16 elements), plain [k][n] layout
#define OFF_Q   0
#define OFF_K   196608
#define OFF_V   393216
#define OFF_Q2  589824
#define OFF_K2  884736
#define OFF_V2  1179648
#define OFF_O2  1769472
#define OFF_F   2359296
#define WSP_TOT 2949120

// ---------------- static scratch ----------------
__device__ float g_im [ROWS*DIM];
__device__ float g_z  [ROWS*DIM];
__device__ float g_t1 [ROWS*DIM];
__device__ float g_t2 [ROWS*DIM];
__device__ float g_av [ROWS*DIM];
__device__ float g_pe [SEQ*DIM];
__device__ u16 g_qh [ROWS*DIM], g_ql [ROWS*DIM];
__device__ u16 g_kh [ROWS*DIM], g_kl [ROWS*DIM];
__device__ u16 g_q2h[ROWS*DIM], g_q2l[ROWS*DIM];
__device__ u16 g_k2h[ROWS*DIM], g_k2l[ROWS*DIM];
__device__ u32 g_vth [ROWS*DIM/2], g_vtl [ROWS*DIM/2];
__device__ u32 g_v2th[ROWS*DIM/2], g_v2tl[ROWS*DIM/2];
__device__ u16 g_Wh[WSP_TOT], g_Wl[WSP_TOT];
__device__ double g_psum [8][DIM];
__device__ double g_psum2[8][DIM];
__device__ float  g_bnsc[DIM];
__device__ float  g_bnsh[DIM];

// ---------------- helpers ----------------
__device__ __forceinline__ void bsplit(float x, u16& h, u16& l)
{
    __nv_bfloat16 bh = __float2bfloat16(x);
    h = __bfloat16_as_ushort(bh);
    l = __bfloat16_as_ushort(__float2bfloat16(x - __bfloat162float(bh)));
}
__device__ __forceinline__ void hsplit(float x, u16& h, u16& l)
{
    __half hh = __float2half_rn(x);
    h = __half_as_ushort(hh);
    l = __half_as_ushort(__float2half_rn(x - __half2float(hh)));
}
__device__ __forceinline__ u32 pk(u16 a, u16 b) { return (u32)a | ((u32)b << 16); }

__device__ __forceinline__ u32 smem_u32(const void* p)
{
    u32 a;
    asm("{ .reg .u64 t; cvta.to.shared.u64 t, %1; cvt.u32.u64 %0, t; }" : "=r"(a) : "l"(p));
    return a;
}
__device__ __forceinline__ void cpa16(void* dst_smem, const void* src)
{
    u32 d = (u32)__cvta_generic_to_shared(dst_smem);
    asm volatile("cp.async.cg.shared.global [%0], [%1], 16;" :: "r"(d), "l"(src));
}
__device__ __forceinline__ void cpa16s(u32 dst, const void* src)
{
    asm volatile("cp.async.cg.shared.global [%0], [%1], 16;" :: "r"(dst), "l"(src));
}
#define CP_COMMIT() asm volatile("cp.async.commit_group;" ::: "memory")
#define CP_WAIT0()  asm volatile("cp.async.wait_group 0;" ::: "memory")

__device__ __forceinline__ void ldsm4(u32 r[4], u32 addr)
{
    asm volatile("ldmatrix.sync.aligned.m8n8.x4.shared.b16 {%0,%1,%2,%3}, [%4];"
        : "=r"(r[0]), "=r"(r[1]), "=r"(r[2]), "=r"(r[3]) : "r"(addr));
}
__device__ __forceinline__ void ldsm4t(u32 r[4], u32 addr)
{
    asm volatile("ldmatrix.sync.aligned.m8n8.x4.trans.shared.b16 {%0,%1,%2,%3}, [%4];"
        : "=r"(r[0]), "=r"(r[1]), "=r"(r[2]), "=r"(r[3]) : "r"(addr));
}

__device__ __forceinline__ void mma_bf16(float d[4], u32 a0, u32 a1, u32 a2, u32 a3, u32 b0, u32 b1)
{
    asm volatile(
        "mma.sync.aligned.m16n8k16.row.col.f32.bf16.bf16.f32 "
        "{%0,%1,%2,%3}, {%4,%5,%6,%7}, {%8,%9}, {%0,%1,%2,%3};\n"
        : "+f"(d[0]), "+f"(d[1]), "+f"(d[2]), "+f"(d[3])
        : "r"(a0), "r"(a1), "r"(a2), "r"(a3), "r"(b0), "r"(b1));
}
__device__ __forceinline__ void mma_f16(float d[4], u32 a0, u32 a1, u32 a2, u32 a3, u32 b0, u32 b1)
{
    asm volatile(
        "mma.sync.aligned.m16n8k16.row.col.f32.f16.f16.f32 "
        "{%0,%1,%2,%3}, {%4,%5,%6,%7}, {%8,%9}, {%0,%1,%2,%3};\n"
        : "+f"(d[0]), "+f"(d[1]), "+f"(d[2]), "+f"(d[3])
        : "r"(a0), "r"(a1), "r"(a2), "r"(a3), "r"(b0), "r"(b1));
}

// fast exp with folded factor c (= k*log2e)
__device__ __forceinline__ float fexp(float x, float c)
{
    float t = fmaxf(x * c, -120.0f);
    float r = t + 12582912.0f;
    float nf = r - 12582912.0f;
    float f = t - nf;
    float p = 1.3333558146e-3f;
    p = fmaf(p, f, 9.6181291077e-3f);
    p = fmaf(p, f, 5.5504108664e-2f);
    p = fmaf(p, f, 2.4022650695e-1f);
    p = fmaf(p, f, 6.9314718056e-1f);
    p = fmaf(p, f, 1.0f);
    int n = __float_as_int(r) - 0x4B400000;
    return __int_as_float(__float_as_int(p) + (n << 23));
}

// ---------------- one-time: PE table ----------------
__global__ void pe_table_kernel()
{
    int idx2 = blockIdx.x*256 + threadIdx.x;
    if (idx2 >= SEQ*DIM/2) return;
    int s = idx2 / (DIM/2), d2 = idx2 - s*(DIM/2);
    float inv = exp2f((float)d2 * (-13.287712379549449f * 2.0f / (float)DIM));
    float ang = (float)s * inv;
    g_pe[(size_t)s*DIM + 2*d2]     = sinf(ang);
    g_pe[(size_t)s*DIM + 2*d2 + 1] = cosf(ang);
}

// ---------------- one-time: weight splits (plain [k][n]); Wf gets +I fold ----------------
__global__ void allsplit_kernel(const float* __restrict__ p0, const float* __restrict__ p1,
                                const float* __restrict__ p2, const float* __restrict__ p3,
                                const float* __restrict__ p4, const float* __restrict__ p5,
                                const float* __restrict__ p6, const float* __restrict__ p7)
{
    int i = blockIdx.x*256 + threadIdx.x;
    if (i >= WSP_TOT) return;
    const float* p; int j;
    if      (i < OFF_K)  { p = p0; j = i; }
    else if (i < OFF_V)  { p = p1; j = i - OFF_K; }
    else if (i < OFF_Q2) { p = p2; j = i - OFF_V; }
    else if (i < OFF_K2) { p = p3; j = i - OFF_Q2; }
    else if (i < OFF_V2) { p = p4; j = i - OFF_K2; }
    else if (i < OFF_O2) { p = p5; j = i - OFF_V2; }
    else if (i < OFF_F)  { p = p6; j = i - OFF_O2; }
    else                 { p = p7; j = i - OFF_F; }
    float v = p[j];
    if (i >= OFF_F) {                       // Wf' = Wf + I (residual fold)
        int k = j / DIM, n = j - k*DIM;
        if (k == n) v += 1.0f;
    }
    u16 h, l;
    bsplit(v, h, l);
    g_Wh[i] = h;
    g_Wl[i] = l;
}

// ---------------- embedding + PE ----------------
__global__ void embed_pos_kernel(const int* __restrict__ x,
                                 const float* __restrict__ embed,
                                 float* __restrict__ out)
{
    int idx4 = blockIdx.x * 256 + threadIdx.x;
    if (idx4 >= ROWS*DIM/4) return;
    int r = idx4 / (DIM/4), d = (idx4 - r*(DIM/4))*4;
    int s = r & (SEQ-1);
    int tok = x[r];
    float4 e = *reinterpret_cast<const float4*>(&embed[(size_t)tok*DIM + d]);
    float4 p = *reinterpret_cast<const float4*>(&g_pe[(size_t)s*DIM + d]);
    float4 o;
    o.x = fmaf(2.0f, e.x, p.x); o.y = fmaf(2.0f, e.y, p.y);
    o.z = fmaf(2.0f, e.z, p.z); o.w = fmaf(2.0f, e.w, p.w);
    *reinterpret_cast<float4*>(&out[(size_t)idx4*4]) = o;
}

// ---------------- GEMM: 64x128 tile, ldmatrix fragments ----------------
// out modes: 0 = fp32 (+optional residual), 1 = bf16 split, 2 = fp16 split V-transposed
#define GA_RS 40    // u16 row stride, A tile 64x32
#define GBN_RS 136  // u16 row stride, B tile 32x128
// per buf: Ah 5120 + Al 5120 + Bh 8704 + Bl 8704 = 27648 B; x2 bufs
#define GEMM_SMEM (2*27648)
__device__ __forceinline__ void gemm_body(
    const float* __restrict__ Ab, int lda,
    const u16* __restrict__ Wh, const u16* __restrict__ Wl,
    const float* __restrict__ bias, const float* __restrict__ Rf,
    float* __restrict__ Cf, void* Chv, void* Clv,
    int N, int K, int bm, int bn, int relu, int mode, u16* sm)
{
    int tid = threadIdx.x;
    int lane = tid & 31, wid = tid >> 5;
    int wm = wid & 1, wn = wid >> 1;
    u32 uS = smem_u32(sm);

    // loader coords
    int ar[2], ac[2], bk_[2], bc_[2];
#pragma unroll
    for (int it = 0; it < 2; it++) {
        int idx = it*256 + tid;
        ar[it] = idx >> 3;  ac[it] = (idx & 7) * 4;       // A: 64 rows x 8 quads
        bk_[it] = idx >> 4; bc_[it] = (idx & 15);         // B: 32 rows x 16 chunks(16B)
    }
    // ldmatrix lane decomposition
    int g = lane >> 3, li = lane & 7;
    u32 aoff0 = (u32)((wm*32 + li + (g&1)*8) * GA_RS * 2 + ((g>>1)*8)*2);  // + mf*1280 + ks*2
    int brow0 = li + (g&1)*8;                                             // + ks
    u32 boffn = (u32)((wn*32 + (g>>1)*8) * 2);                            // + p*32 (bytes)

    float acc[2][4][4];
#pragma unroll
    for (int i=0;i<2;i++)
#pragma unroll
        for (int j=0;j<4;j++)
#pragma unroll
            for (int q=0;q<4;q++) acc[i][j][q]=0.f;

    // prologue: stage tile 0 -> buf 0
    {
        u16* Ah = sm;           u16* Al = sm + 2560;
        u32 uBh = uS + 10240,   uBl = uS + 18944;
        float4 pa[2];
#pragma unroll
        for (int it = 0; it < 2; it++)
            pa[it] = *reinterpret_cast<const float4*>(Ab + (size_t)ar[it]*lda + ac[it]);
#pragma unroll
        for (int it = 0; it < 2; it++) {
            cpa16s(uBh + bk_[it]*272 + bc_[it]*16, &Wh[(size_t)bk_[it]*N + bn + bc_[it]*8]);
            cpa16s(uBl + bk_[it]*272 + bc_[it]*16, &Wl[(size_t)bk_[it]*N + bn + bc_[it]*8]);
        }
        CP_COMMIT();
#pragma unroll
        for (int it = 0; it < 2; it++) {
            u16 h0,l0,h1,l1,h2,l2,h3,l3;
            bsplit(pa[it].x,h0,l0); bsplit(pa[it].y,h1,l1);
            bsplit(pa[it].z,h2,l2); bsplit(pa[it].w,h3,l3);
            *reinterpret_cast<u32*>(&Ah[ar[it]*GA_RS + ac[it]])     = pk(h0,h1);
            *reinterpret_cast<u32*>(&Ah[ar[it]*GA_RS + ac[it] + 2]) = pk(h2,h3);
            *reinterpret_cast<u32*>(&Al[ar[it]*GA_RS + ac[it]])     = pk(l0,l1);
            *reinterpret_cast<u32*>(&Al[ar[it]*GA_RS + ac[it] + 2]) = pk(l2,l3);
        }
        CP_WAIT0();
        __syncthreads();
    }

    int buf = 0;
    for (int kb = 0; kb < K; kb += 32) {
        bool more = (kb + 32) < K;
        int nb = buf ^ 1;
        float4 pa[2];
        if (more) {
#pragma unroll
            for (int it = 0; it < 2; it++)
                pa[it] = *reinterpret_cast<const float4*>(Ab + (size_t)ar[it]*lda + kb+32 + ac[it]);
            u32 uBhN = uS + nb*27648 + 10240, uBlN = uS + nb*27648 + 18944;
#pragma unroll
            for (int it = 0; it < 2; it++) {
                cpa16s(uBhN + bk_[it]*272 + bc_[it]*16, &Wh[(size_t)(kb+32+bk_[it])*N + bn + bc_[it]*8]);
                cpa16s(uBlN + bk_[it]*272 + bc_[it]*16, &Wl[(size_t)(kb+32+bk_[it])*N + bn + bc_[it]*8]);
            }
            CP_COMMIT();
        }
        u32 bo = buf*27648;
        u32 uAh = uS + bo, uAl = uS + bo + 5120;
        u32 uBh = uS + bo + 10240, uBl = uS + bo + 18944;
#pragma unroll
        for (int ks = 0; ks < 32; ks += 16) {
            u32 ah[2][4], al[2][4], bh[2][4], bl[2][4];
            ldsm4(ah[0], uAh + aoff0 + ks*2);
            ldsm4(ah[1], uAh + aoff0 + ks*2 + 1280);
            ldsm4(al[0], uAl + aoff0 + ks*2);
            ldsm4(al[1], uAl + aoff0 + ks*2 + 1280);
            u32 brow = (u32)((brow0 + ks) * 272);
            ldsm4t(bh[0], uBh + brow + boffn);
            ldsm4t(bh[1], uBh + brow + boffn + 32);
            ldsm4t(bl[0], uBl + brow + boffn);
            ldsm4t(bl[1], uBl + brow + boffn + 32);
            // term-major: 8 independent mmas between accumulator reuse
#pragma unroll
            for (int mf = 0; mf < 2; mf++)
#pragma unroll
                for (int nf = 0; nf < 4; nf++)
                    mma_bf16(acc[mf][nf], ah[mf][0],ah[mf][1],ah[mf][2],ah[mf][3],
                             bh[nf>>1][(nf&1)*2], bh[nf>>1][(nf&1)*2+1]);
#pragma unroll
            for (int mf = 0; mf < 2; mf++)
#pragma unroll
                for (int nf = 0; nf < 4; nf++)
                    mma_bf16(acc[mf][nf], ah[mf][0],ah[mf][1],ah[mf][2],ah[mf][3],
                             bl[nf>>1][(nf&1)*2], bl[nf>>1][(nf&1)*2+1]);
#pragma unroll
            for (int mf = 0; mf < 2; mf++)
#pragma unroll
                for (int nf = 0; nf < 4; nf++)
                    mma_bf16(acc[mf][nf], al[mf][0],al[mf][1],al[mf][2],al[mf][3],
                             bh[nf>>1][(nf&1)*2], bh[nf>>1][(nf&1)*2+1]);
        }
        if (more) {
            u16* nAh = sm + nb*13824;
            u16* nAl = nAh + 2560;
#pragma unroll
            for (int it = 0; it < 2; it++) {
                u16 h0,l0,h1,l1,h2,l2,h3,l3;
                bsplit(pa[it].x,h0,l0); bsplit(pa[it].y,h1,l1);
                bsplit(pa[it].z,h2,l2); bsplit(pa[it].w,h3,l3);
                *reinterpret_cast<u32*>(&nAh[ar[it]*GA_RS + ac[it]])     = pk(h0,h1);
                *reinterpret_cast<u32*>(&nAh[ar[it]*GA_RS + ac[it] + 2]) = pk(h2,h3);
                *reinterpret_cast<u32*>(&nAl[ar[it]*GA_RS + ac[it]])     = pk(l0,l1);
                *reinterpret_cast<u32*>(&nAl[ar[it]*GA_RS + ac[it] + 2]) = pk(l2,l3);
            }
            CP_WAIT0();
        }
        __syncthreads();
        buf = nb;
    }

#pragma unroll
    for (int mf = 0; mf < 2; mf++) {
#pragma unroll
        for (int nf = 0; nf < 4; nf++) {
            int r = bm + wm*32 + mf*16 + (lane >> 2);
            int c = bn + wn*32 + nf*8 + (lane & 3)*2;
            float b0 = bias[c], b1 = bias[c+1];
            float v0 = acc[mf][nf][0] + b0, v1 = acc[mf][nf][1] + b1;
            float v2 = acc[mf][nf][2] + b0, v3 = acc[mf][nf][3] + b1;
            if (relu) { v0=fmaxf(v0,0.f); v1=fmaxf(v1,0.f); v2=fmaxf(v2,0.f); v3=fmaxf(v3,0.f); }
            if (mode == 0) {
                if (Rf) {
                    float2 r0 = *reinterpret_cast<const float2*>(&Rf[(size_t)r*N + c]);
                    float2 r1 = *reinterpret_cast<const float2*>(&Rf[(size_t)(r+8)*N + c]);
                    v0 += r0.x; v1 += r0.y; v2 += r1.x; v3 += r1.y;
                }
                *reinterpret_cast<float2*>(&Cf[(size_t)r*N + c])     = make_float2(v0, v1);
                *reinterpret_cast<float2*>(&Cf[(size_t)(r+8)*N + c]) = make_float2(v2, v3);
            } else if (mode == 1) {
                u16* Ch = (u16*)Chv; u16* Cl = (u16*)Clv;
                u16 h0,l0,h1,l1,h2,l2,h3,l3;
                bsplit(v0,h0,l0); bsplit(v1,h1,l1); bsplit(v2,h2,l2); bsplit(v3,h3,l3);
                *reinterpret_cast<u32*>(&Ch[(size_t)r*N + c])     = pk(h0,h1);
                *reinterpret_cast<u32*>(&Cl[(size_t)r*N + c])     = pk(l0,l1);
                *reinterpret_cast<u32*>(&Ch[(size_t)(r+8)*N + c]) = pk(h2,h3);
                *reinterpret_cast<u32*>(&Cl[(size_t)(r+8)*N + c]) = pk(l2,l3);
            } else {
                u16 h0,l0,h1,l1,h2,l2,h3,l3;
                hsplit(v0,h0,l0); hsplit(v1,h1,l1); hsplit(v2,h2,l2); hsplit(v3,h3,l3);
                u32 m01 = pk(h0,h1), m23 = pk(h2,h3);
                u32 n01 = pk(l0,l1), n23 = pk(l2,l3);
                u32 p01 = __shfl_down_sync(0xffffffffu, m01, 4);
                u32 p23 = __shfl_down_sync(0xffffffffu, m23, 4);
                u32 q01 = __shfl_down_sync(0xffffffffu, n01, 4);
                u32 q23 = __shfl_down_sync(0xffffffffu, n23, 4);
                if ((((lane >> 2) & 1) == 0)) {
                    int bb = r >> 10, s = r & (SEQ-1);
                    int hh = c >> 6, e = c & (HD-1);
                    u32* Vh32 = (u32*)Chv; u32* Vl32 = (u32*)Clv;
                    size_t vtb = ((size_t)(bb*NH + hh)*HD);
                    size_t i0 = (vtb + e)*(SEQ/2) + (s >> 1);
                    size_t i1 = (vtb + e + 1)*(SEQ/2) + (s >> 1);
                    Vh32[i0]     = pk(h0, (u16)(p01 & 0xffffu));
                    Vh32[i1]     = pk(h1, (u16)(p01 >> 16));
                    Vl32[i0]     = pk(l0, (u16)(q01 & 0xffffu));
                    Vl32[i1]     = pk(l1, (u16)(q01 >> 16));
                    Vh32[i0 + 4] = pk(h2, (u16)(p23 & 0xffffu));
                    Vh32[i1 + 4] = pk(h3, (u16)(p23 >> 16));
                    Vl32[i0 + 4] = pk(l2, (u16)(q23 & 0xffffu));
                    Vl32[i1 + 4] = pk(l3, (u16)(q23 >> 16));
                }
            }
        }
    }
}

__global__ __launch_bounds__(256, 3)
void gemm_ts(const float* __restrict__ A, int lda, int aoff,
             const u16* __restrict__ Wh, const u16* __restrict__ Wl,
             const float* __restrict__ bias, const float* __restrict__ Rf,
             float* __restrict__ Cf, void* Chv, void* Clv,
             int N, int K, int relu, int mode)
{
    extern __shared__ u16 smg[];
    int bm = blockIdx.y*64, bn = blockIdx.x*128;
    gemm_body(A + (size_t)bm*lda + aoff, lda, Wh, Wl, bias, Rf,
              Cf, Chv, Clv, N, K, bm, bn, relu, mode, smg);
}

__global__ __launch_bounds__(256, 3)
void qkv_gemm_ts(const float* __restrict__ A,
                 const float* __restrict__ bq, const float* __restrict__ bk,
                 const float* __restrict__ bv)
{
    extern __shared__ u16 smg[];
    int grp = blockIdx.x / 6;
    int bxl = blockIdx.x - grp*6;
    int bm = blockIdx.y*64, bn = bxl*128;
    const u16* Wh = g_Wh + grp*196608;
    const u16* Wl = g_Wl + grp*196608;
    const float* bias = (grp == 0) ? bq : (grp == 1) ? bk : bv;
    void* Chv = (grp == 0) ? (void*)g_qh : (grp == 1) ? (void*)g_kh : (void*)g_vth;
    void* Clv = (grp == 0) ? (void*)g_ql : (grp == 1) ? (void*)g_kl : (void*)g_vtl;
    int mode = (grp == 2) ? 2 : 1;
    int aoff = grp*256;
    gemm_body(A + (size_t)bm*DIM + aoff, DIM, Wh, Wl, bias, nullptr,
              nullptr, Chv, Clv, DIM, 256, bm, bn, 1, mode, smg);
}

// ---------------- fused flash attention (R15 core + optional residual) ----------------
#define FA_RS 72
#define VT_RS 36
#define FA_SMEM (2*128*FA_RS*2 + 2*2*64*FA_RS*2 + 2*2*64*VT_RS*4)
__global__ __launch_bounds__(256, 2)
void fused_attn(const u16* __restrict__ Qhg, const u16* __restrict__ Qlg,
                const u16* __restrict__ Khg, const u16* __restrict__ Klg,
                const u32* __restrict__ Vth, const u32* __restrict__ Vtl,
                const float* __restrict__ Rf, float* __restrict__ Of, float scale)
{
    extern __shared__ u16 sm[];
    u16* Qh = sm;
    u16* Ql = Qh + 128*FA_RS;
    u16* Kbase = sm + 2*128*FA_RS;
    u32* Vbase = (u32*)(sm + 2*128*FA_RS + 2*2*64*FA_RS);
#define KHs(b) (Kbase + (b)*(2*64*FA_RS))
#define KLs(b) (Kbase + (b)*(2*64*FA_RS) + 64*FA_RS)
#define VHs(b) (Vbase + (b)*(2*64*VT_RS))
#define VLs(b) (Vbase + (b)*(2*64*VT_RS) + 64*VT_RS)

    int bh = blockIdx.z;
    int b = bh / NH, h = bh - b*NH;
    int tid = threadIdx.x, lane = tid & 31, w = tid >> 5;
    size_t base = ((size_t)b*SEQ)*DIM + h*HD;
    size_t vtbase = (size_t)(b*NH + h)*HD*(SEQ/2);
    int q0 = blockIdx.x * 128;
    const float cfac = scale * 1.4426950408889634f;

    int kr[2], kc[2], vr[2], vc[2];
#pragma unroll
    for (int it = 0; it < 2; it++) {
        int idx = it*256 + tid;
        kr[it] = idx >> 3; kc[it] = (idx & 7) * 8;
        vr[it] = idx >> 3; vc[it] = (idx & 7) * 4;
    }

#pragma unroll
    for (int it = 0; it < 2; it++) {
        size_t g = base + (size_t)kr[it]*DIM + kc[it];
        cpa16(&KHs(0)[kr[it]*FA_RS + kc[it]], Khg + g);
        cpa16(&KLs(0)[kr[it]*FA_RS + kc[it]], Klg + g);
        size_t gv = vtbase + (size_t)vr[it]*(SEQ/2) + vc[it];
        cpa16(&VHs(0)[vr[it]*VT_RS + vc[it]], Vth + gv);
        cpa16(&VLs(0)[vr[it]*VT_RS + vc[it]], Vtl + gv);
    }
    CP_COMMIT();
#pragma unroll
    for (int it = 0; it < 4; it++) {
        int idx = it*256 + tid;
        int r = idx >> 3, c8 = (idx & 7) * 8;
        *reinterpret_cast<uint4*>(&Qh[r*FA_RS + c8]) =
            *reinterpret_cast<const uint4*>(Qhg + base + (size_t)(q0+r)*DIM + c8);
        *reinterpret_cast<uint4*>(&Ql[r*FA_RS + c8]) =
            *reinterpret_cast<const uint4*>(Qlg + base + (size_t)(q0+r)*DIM + c8);
    }
    CP_WAIT0();
    __syncthreads();

    float o[8][4];
#pragma unroll
    for (int i=0;i<8;i++)
#pragma unroll
        for (int j=0;j<4;j++) o[i][j]=0.f;
    float m_lo = -1e30f, m_hi = -1e30f, l_lo = 0.f, l_hi = 0.f;

    int rq = w*16 + (lane >> 2);
    int buf = 0;

    for (int t0 = 0; t0 < SEQ; t0 += 64) {
        bool more = (t0 + 64) < SEQ;
        int nb = buf ^ 1;
        if (more) {
#pragma unroll
            for (int it = 0; it < 2; it++) {
                size_t g = base + (size_t)(t0+64+kr[it])*DIM + kc[it];
                cpa16(&KHs(nb)[kr[it]*FA_RS + kc[it]], Khg + g);
                cpa16(&KLs(nb)[kr[it]*FA_RS + kc[it]], Klg + g);
                size_t gv = vtbase + (size_t)vr[it]*(SEQ/2) + ((t0+64) >> 1) + vc[it];
                cpa16(&VHs(nb)[vr[it]*VT_RS + vc[it]], Vth + gv);
                cpa16(&VLs(nb)[vr[it]*VT_RS + vc[it]], Vtl + gv);
            }
            CP_COMMIT();
        }
        u16* cKh = KHs(buf); u16* cKl = KLs(buf);
        u32* cVh = VHs(buf); u32* cVl = VLs(buf);

        float sacc[8][4];
#pragma unroll
        for (int i=0;i<8;i++)
#pragma unroll
            for (int j=0;j<4;j++) sacc[i][j]=0.f;
#pragma unroll
        for (int ks = 0; ks < 4; ks++) {
            int c = ks*16 + (lane & 3)*2;
            u32 ah0 = *reinterpret_cast<u32*>(&Qh[rq*FA_RS + c]);
            u32 ah1 = *reinterpret_cast<u32*>(&Qh[(rq+8)*FA_RS + c]);
            u32 ah2 = *reinterpret_cast<u32*>(&Qh[rq*FA_RS + c + 8]);
            u32 ah3 = *reinterpret_cast<u32*>(&Qh[(rq+8)*FA_RS + c + 8]);
            u32 al0 = *reinterpret_cast<u32*>(&Ql[rq*FA_RS + c]);
            u32 al1 = *reinterpret_cast<u32*>(&Ql[(rq+8)*FA_RS + c]);
            u32 al2 = *reinterpret_cast<u32*>(&Ql[rq*FA_RS + c + 8]);
            u32 al3 = *reinterpret_cast<u32*>(&Ql[(rq+8)*FA_RS + c + 8]);
#pragma unroll
            for (int nf = 0; nf < 8; nf++) {
                int n = nf*8 + (lane >> 2);
                u32 bh0 = *reinterpret_cast<u32*>(&cKh[n*FA_RS + c]);
                u32 bh1 = *reinterpret_cast<u32*>(&cKh[n*FA_RS + c + 8]);
                u32 bl0 = *reinterpret_cast<u32*>(&cKl[n*FA_RS + c]);
                u32 bl1 = *reinterpret_cast<u32*>(&cKl[n*FA_RS + c + 8]);
                mma_bf16(sacc[nf], ah0,ah1,ah2,ah3, bh0,bh1);
                mma_bf16(sacc[nf], ah0,ah1,ah2,ah3, bl0,bl1);
                mma_bf16(sacc[nf], al0,al1,al2,al3, bh0,bh1);
            }
        }

        float tm_lo = -1e30f, tm_hi = -1e30f;
#pragma unroll
        for (int nf = 0; nf < 8; nf++) {
            tm_lo = fmaxf(tm_lo, fmaxf(sacc[nf][0], sacc[nf][1]));
            tm_hi = fmaxf(tm_hi, fmaxf(sacc[nf][2], sacc[nf][3]));
        }
        tm_lo = fmaxf(tm_lo, __shfl_xor_sync(0xffffffffu, tm_lo, 1));
        tm_lo = fmaxf(tm_lo, __shfl_xor_sync(0xffffffffu, tm_lo, 2));
        tm_hi = fmaxf(tm_hi, __shfl_xor_sync(0xffffffffu, tm_hi, 1));
        tm_hi = fmaxf(tm_hi, __shfl_xor_sync(0xffffffffu, tm_hi, 2));
        float mn_lo = fmaxf(m_lo, tm_lo), mn_hi = fmaxf(m_hi, tm_hi);
        float f_lo = fexp(m_lo - mn_lo, cfac), f_hi = fexp(m_hi - mn_hi, cfac);
        m_lo = mn_lo; m_hi = mn_hi;

        float ts_lo = 0.f, ts_hi = 0.f;
        u32 plo[8], phi[8];
#pragma unroll
        for (int nf = 0; nf < 8; nf++) {
            float p0 = fexp(sacc[nf][0] - mn_lo, cfac);
            float p1 = fexp(sacc[nf][1] - mn_lo, cfac);
            float p2 = fexp(sacc[nf][2] - mn_hi, cfac);
            float p3 = fexp(sacc[nf][3] - mn_hi, cfac);
            ts_lo += p0 + p1; ts_hi += p2 + p3;
            __half2 hl = __floats2half2_rn(p0, p1);
            __half2 hh = __floats2half2_rn(p2, p3);
            plo[nf] = *reinterpret_cast<u32*>(&hl);
            phi[nf] = *reinterpret_cast<u32*>(&hh);
        }
        ts_lo += __shfl_xor_sync(0xffffffffu, ts_lo, 1);
        ts_lo += __shfl_xor_sync(0xffffffffu, ts_lo, 2);
        ts_hi += __shfl_xor_sync(0xffffffffu, ts_hi, 1);
        ts_hi += __shfl_xor_sync(0xffffffffu, ts_hi, 2);
        l_lo = l_lo * f_lo + ts_lo;
        l_hi = l_hi * f_hi + ts_hi;

#pragma unroll
        for (int ef = 0; ef < 8; ef++) {
            o[ef][0] *= f_lo; o[ef][1] *= f_lo;
            o[ef][2] *= f_hi; o[ef][3] *= f_hi;
        }

#pragma unroll
        for (int ks = 0; ks < 4; ks++) {
            int pr = ks*8 + (lane & 3);
            u32 a0 = plo[2*ks], a1 = phi[2*ks], a2 = plo[2*ks+1], a3 = phi[2*ks+1];
#pragma unroll
            for (int ef = 0; ef < 8; ef++) {
                int e = ef*8 + (lane >> 2);
                u32 b0h = cVh[e*VT_RS + pr];
                u32 b1h = cVh[e*VT_RS + pr + 4];
                u32 b0l = cVl[e*VT_RS + pr];
                u32 b1l = cVl[e*VT_RS + pr + 4];
                mma_f16(o[ef], a0,a1,a2,a3, b0h,b1h);
                mma_f16(o[ef], a0,a1,a2,a3, b0l,b1l);
            }
        }
        if (more) CP_WAIT0();
        __syncthreads();
        buf = nb;
    }
#undef KHs
#undef KLs
#undef VHs
#undef VLs

    float il_lo = 1.0f / l_lo, il_hi = 1.0f / l_hi;
    size_t row = (size_t)b*SEQ + q0 + rq;
#pragma unroll
    for (int ef = 0; ef < 8; ef++) {
        int col = h*HD + ef*8 + (lane & 3)*2;
        float v0 = o[ef][0]*il_lo, v1 = o[ef][1]*il_lo;
        float v2 = o[ef][2]*il_hi, v3 = o[ef][3]*il_hi;
        if (Rf) {
            float2 r0 = *reinterpret_cast<const float2*>(&Rf[row*DIM + col]);
            float2 r1 = *reinterpret_cast<const float2*>(&Rf[(row+8)*DIM + col]);
            v0 += r0.x; v1 += r0.y; v2 += r1.x; v3 += r1.y;
        }
        *reinterpret_cast<float2*>(&Of[row*DIM + col])     = make_float2(v0, v1);
        *reinterpret_cast<float2*>(&Of[(row+8)*DIM + col]) = make_float2(v2, v3);
    }
}

// ---------------- batch norm (single input array) ----------------
__global__ __launch_bounds__(256)
void bn_stats1(const float* __restrict__ Z)
{
    int f  = blockIdx.x*32 + threadIdx.x;
    int rb = blockIdx.y*512;
    float s = 0.0f, s2 = 0.0f;
    for (int r = rb + threadIdx.y; r < rb + 512; r += 8) {
        float v = Z[(size_t)r*DIM + f];
        s += v; s2 = fmaf(v, v, s2);
    }
    __shared__ double sh[2][8][32];
    sh[0][threadIdx.y][threadIdx.x] = (double)s;
    sh[1][threadIdx.y][threadIdx.x] = (double)s2;
    __syncthreads();
    if (threadIdx.y == 0) {
        double ts = 0.0, ts2 = 0.0;
#pragma unroll
        for (int i = 0; i < 8; i++) { ts += sh[0][i][threadIdx.x]; ts2 += sh[1][i][threadIdx.x]; }
        g_psum [blockIdx.y][f] = ts;
        g_psum2[blockIdx.y][f] = ts2;
    }
}

__global__ void bn_finalize(const float* __restrict__ g, const float* __restrict__ b)
{
    int f = blockIdx.x*256 + threadIdx.x;
    if (f >= DIM) return;
    double s = 0.0, s2 = 0.0;
#pragma unroll
    for (int i = 0; i < 8; i++) { s += g_psum[i][f]; s2 += g_psum2[i][f]; }
    double mu  = s  * (1.0 / ROWS);
    double var = s2 * (1.0 / ROWS) - mu*mu;
    float rstd = (float)(1.0 / sqrt(var + 1e-5));
    float sc = g[f] * rstd;
    g_bnsc[f] = sc;
    g_bnsh[f] = b[f] - (float)mu * sc;
}

__global__ __launch_bounds__(256)
void bn_apply1(const float* __restrict__ Z, float* __restrict__ O)
{
    int idx4 = blockIdx.x*256 + threadIdx.x;
    if (idx4 >= ROWS*DIM/4) return;
    int f = (idx4*4) % DIM;
    float4 z = *reinterpret_cast<const float4*>(&Z[(size_t)idx4*4]);
    float4 o;
    o.x = fmaf(z.x, g_bnsc[f+0], g_bnsh[f+0]);
    o.y = fmaf(z.y, g_bnsc[f+1], g_bnsh[f+1]);
    o.z = fmaf(z.z, g_bnsc[f+2], g_bnsh[f+2]);
    o.w = fmaf(z.w, g_bnsc[f+3], g_bnsh[f+3]);
    *reinterpret_cast<float4*>(&O[(size_t)idx4*4]) = o;
}

// ---------------- launch ----------------
static float* sym(const void* s)
{
    void* p = nullptr;
    cudaGetSymbolAddress(&p, s);
    return (float*)p;
}

extern "C" void kernel_launch(void* const* d_in, const int* in_sizes, int n_in,
                              void* d_out, int out_size)
{
    const int*   x     = (const int*)  d_in[0];
    const float* encod = (const float*)d_in[1];
    const float* embed = (const float*)d_in[2];
    const float* Wq  = (const float*)d_in[3];  const float* bq  = (const float*)d_in[4];
    const float* Wk  = (const float*)d_in[5];  const float* bk  = (const float*)d_in[6];
    const float* Wv  = (const float*)d_in[7];  const float* bv  = (const float*)d_in[8];
    const float* g1  = (const float*)d_in[9];  const float* b1  = (const float*)d_in[10];
    const float* Wq2 = (const float*)d_in[11]; const float* bq2 = (const float*)d_in[12];
    const float* Wk2 = (const float*)d_in[13]; const float* bk2 = (const float*)d_in[14];
    const float* Wv2 = (const float*)d_in[15]; const float* bv2 = (const float*)d_in[16];
    const float* Wo2 = (const float*)d_in[17]; const float* bo2 = (const float*)d_in[18];
    const float* g2  = (const float*)d_in[19]; const float* b2  = (const float*)d_in[20];
    const float* Wf  = (const float*)d_in[21]; const float* bf  = (const float*)d_in[22];
    float* out = (float*)d_out;

    float *im = sym(g_im), *z = sym(g_z), *t1 = sym(g_t1), *t2 = sym(g_t2), *av = sym(g_av);
    u16 *qh = (u16*)sym(g_qh), *ql = (u16*)sym(g_ql);
    u16 *kh = (u16*)sym(g_kh), *kl = (u16*)sym(g_kl);
    u16 *q2h = (u16*)sym(g_q2h), *q2l = (u16*)sym(g_q2l);
    u16 *k2h = (u16*)sym(g_k2h), *k2l = (u16*)sym(g_k2l);
    u32 *vth = (u32*)sym(g_vth),  *vtl = (u32*)sym(g_vtl);
    u32 *v2th = (u32*)sym(g_v2th), *v2tl = (u32*)sym(g_v2tl);
    u16 *wh = (u16*)sym(g_Wh), *wl = (u16*)sym(g_Wl);

    cudaFuncSetAttribute(fused_attn,  cudaFuncAttributeMaxDynamicSharedMemorySize, FA_SMEM);
    cudaFuncSetAttribute(gemm_ts,     cudaFuncAttributeMaxDynamicSharedMemorySize, GEMM_SMEM);
    cudaFuncSetAttribute(qkv_gemm_ts, cudaFuncAttributeMaxDynamicSharedMemorySize, GEMM_SMEM);

    const float scale1 = 1.0f / sqrtf((float)DIM);
    const float scale2 = 1.0f / sqrtf((float)HD);

    dim3 gemmGrid(DIM/128, ROWS/64);       // (6, 64)
    dim3 qkvGrid(3*DIM/128, ROWS/64);      // (18, 64)
    dim3 faGrid(SEQ/128, 1, NBH);          // (8, 1, 48)
    dim3 bnGrid(DIM/32, 8);
    dim3 bnBlk(32, 8);
    int ew4Blocks = (ROWS*DIM/4 + 255)/256;

    pe_table_kernel<<<(SEQ*DIM/2 + 255)/256, 256>>>();
    allsplit_kernel<<<(WSP_TOT + 255)/256, 256>>>(Wq, Wk, Wv, Wq2, Wk2, Wv2, Wo2, Wf);

    embed_pos_kernel<<<ew4Blocks, 256>>>(x, embed, im);

    // loop-invariant cross-attention projections (bf16-split outputs)
    gemm_ts<<<gemmGrid, 256, GEMM_SMEM>>>(encod, DIM, 0,   wh+OFF_Q2, wl+OFF_Q2, bq2, nullptr,
                                          nullptr, q2h, q2l, DIM, DIM/2, 0, 1);
    gemm_ts<<<gemmGrid, 256, GEMM_SMEM>>>(encod, DIM, 384, wh+OFF_K2, wl+OFF_K2, bk2, nullptr,
                                          nullptr, k2h, k2l, DIM, DIM/2, 0, 1);

    for (int li = 0; li < NITER; li++) {
        // self attention (+im residual fused in epilogue)
        qkv_gemm_ts<<<qkvGrid, 256, GEMM_SMEM>>>(im, bq, bk, bv);
        fused_attn<<<faGrid, 256, FA_SMEM>>>(qh, ql, kh, kl, vth, vtl, im, z, scale1);
        bn_stats1<<<bnGrid, bnBlk>>>(z);
        bn_finalize<<<3, 256>>>(g1, b1);
        bn_apply1<<<ew4Blocks, 256>>>(z, t1);

        // cross attention; O2 gemm adds t1 residual in epilogue
        gemm_ts<<<gemmGrid, 256, GEMM_SMEM>>>(t1, DIM, 0, wh+OFF_V2, wl+OFF_V2, bv2, nullptr,
                                              nullptr, v2th, v2tl, DIM, DIM, 0, 2);
        fused_attn<<<faGrid, 256, FA_SMEM>>>(q2h, q2l, k2h, k2l, v2th, v2tl, nullptr, av, scale2);
        gemm_ts<<<gemmGrid, 256, GEMM_SMEM>>>(av, DIM, 0, wh+OFF_O2, wl+OFF_O2, bo2, t1,
                                              z, nullptr, nullptr, DIM, DIM, 0, 0);
        bn_stats1<<<bnGrid, bnBlk>>>(z);
        bn_finalize<<<3, 256>>>(g2, b2);
        bn_apply1<<<ew4Blocks, 256>>>(z, t2);

        // FFN with Wf' = Wf + I (residual folded into weight)
        gemm_ts<<<gemmGrid, 256, GEMM_SMEM>>>(t2, DIM, 0, wh+OFF_F, wl+OFF_F, bf, nullptr,
                                              z, nullptr, nullptr, DIM, DIM, 0, 0);
        bn_stats1<<<bnGrid, bnBlk>>>(z);
        bn_finalize<<<3, 256>>>(g2, b2);
        bn_apply1<<<ew4Blocks, 256>>>(z, im);
    }

    cudaMemcpyAsync(out, im, (size_t)ROWS*DIM*sizeof(float),
                    cudaMemcpyDeviceToDevice);
}